// round 2
// baseline (speedup 1.0000x reference)
#include <cuda_runtime.h>
#include <cuda_bf16.h>
#include <math.h>
#include <math_constants.h>

#define L_DIM 2048
#define S_DIM 2048
#define B_DIM 2
#define E_DIM 1024
#define H_DIM 16
#define HD    64
#define M_ROWS (L_DIM * B_DIM)   // 4096 rows for projections

typedef unsigned long long u64;

// ---------------- packed f32x2 helpers (sm_103a FFMA2 path) ----------------
__device__ __forceinline__ u64 pack2(float lo, float hi) {
    u64 r; asm("mov.b64 %0, {%1, %2};" : "=l"(r) : "f"(lo), "f"(hi)); return r;
}
__device__ __forceinline__ void unpack2(u64 v, float& lo, float& hi) {
    asm("mov.b64 {%0, %1}, %2;" : "=f"(lo), "=f"(hi) : "l"(v));
}
__device__ __forceinline__ void fma2(u64& d, u64 a, u64 b) {
    asm("fma.rn.f32x2 %0, %1, %2, %0;" : "+l"(d) : "l"(a), "l"(b));
}
__device__ __forceinline__ u64 mul2(u64 a, u64 b) {
    u64 d; asm("mul.rn.f32x2 %0, %1, %2;" : "=l"(d) : "l"(a), "l"(b)); return d;
}

// ---------------- scratch (allocation-free: __device__ globals) ----------------
__device__ float g_Q[(size_t)B_DIM * H_DIM * L_DIM * HD];   // 16 MB
__device__ float g_K[(size_t)B_DIM * H_DIM * S_DIM * HD];   // 16 MB
__device__ float g_V[(size_t)B_DIM * H_DIM * S_DIM * HD];   // 16 MB
__device__ float g_O[(size_t)L_DIM * B_DIM * E_DIM];        // 16 MB

// ============================================================================
// Projection GEMM: C[m][n] = sum_k A[m][k] * W[n][k] + bias[n]
// Accumulators packed over ROW PAIRS: acc2[ip][j] = {row 2ip, row 2ip+1} col j.
// Row-pair A operands come free as b64 halves of the float4 smem loads.
// ============================================================================
template<int LAYOUT, int ROPE>
__global__ void __launch_bounds__(256)
proj_gemm(const float* __restrict__ A,
          const float* __restrict__ W,
          const float* __restrict__ bias,
          float* __restrict__ out,
          int M, int N, int K)
{
    const int BK = 16;
    __shared__ float As[BK][132];   // transposed: As[k][m]   (132*4=528B rows, 16B-aligned)
    __shared__ float Bs[BK][132];   // transposed: Bs[k][n]

    const int tid = threadIdx.x;
    const int tx  = tid & 15;       // 8 output cols each
    const int ty  = tid >> 4;       // 8 output rows each
    const int m0  = blockIdx.y * 128;
    const int n0  = blockIdx.x * 128;

    u64 acc2[4][8];
#pragma unroll
    for (int ip = 0; ip < 4; ip++)
#pragma unroll
        for (int j = 0; j < 8; j++) acc2[ip][j] = 0ull;

    for (int k0 = 0; k0 < K; k0 += BK) {
#pragma unroll
        for (int it = 0; it < 2; it++) {
            int id  = it * 256 + tid;
            int row = id >> 2;
            int kq  = (id & 3) * 4;
            float4 va = *(const float4*)(A + (size_t)(m0 + row) * K + k0 + kq);
            As[kq + 0][row] = va.x; As[kq + 1][row] = va.y;
            As[kq + 2][row] = va.z; As[kq + 3][row] = va.w;
            float4 vb = *(const float4*)(W + (size_t)(n0 + row) * K + k0 + kq);
            Bs[kq + 0][row] = vb.x; Bs[kq + 1][row] = vb.y;
            Bs[kq + 2][row] = vb.z; Bs[kq + 3][row] = vb.w;
        }
        __syncthreads();

#pragma unroll
        for (int k = 0; k < BK; k++) {
            ulonglong2 a01 = *(const ulonglong2*)&As[k][ty * 8];
            ulonglong2 a23 = *(const ulonglong2*)&As[k][ty * 8 + 4];
            u64 ap[4] = {a01.x, a01.y, a23.x, a23.y};
            float4 b0 = *(const float4*)&Bs[k][tx * 8];
            float4 b1 = *(const float4*)&Bs[k][tx * 8 + 4];
            float bs[8] = {b0.x, b0.y, b0.z, b0.w, b1.x, b1.y, b1.z, b1.w};
            u64 bb[8];
#pragma unroll
            for (int j = 0; j < 8; j++) bb[j] = pack2(bs[j], bs[j]);
#pragma unroll
            for (int ip = 0; ip < 4; ip++)
#pragma unroll
                for (int j = 0; j < 8; j++)
                    fma2(acc2[ip][j], ap[ip], bb[j]);
        }
        __syncthreads();
    }

    // unpack to scalar accs
    float acc[8][8];
#pragma unroll
    for (int ip = 0; ip < 4; ip++)
#pragma unroll
        for (int j = 0; j < 8; j++)
            unpack2(acc2[ip][j], acc[2 * ip][j], acc[2 * ip + 1][j]);

    // bias
    {
        float bv[8];
#pragma unroll
        for (int j = 0; j < 8; j++) bv[j] = bias[n0 + tx * 8 + j];
#pragma unroll
        for (int i = 0; i < 8; i++)
#pragma unroll
            for (int j = 0; j < 8; j++) acc[i][j] += bv[j];
    }

    const int Lseq = M / B_DIM;

#pragma unroll
    for (int i = 0; i < 8; i++) {
        int m = m0 + ty * 8 + i;
        if (ROPE || LAYOUT == 1) {
            int l = m / B_DIM;
            int b = m - l * B_DIM;
            if (ROPE) {
#pragma unroll
                for (int p = 0; p < 4; p++) {
                    int n = n0 + tx * 8 + 2 * p;
                    int d = n & (HD - 1);
                    float freq = powf(10000.0f, -(float)d / (float)HD);
                    float ang  = (float)l * freq;
                    float sv, cv;
                    sincosf(ang, &sv, &cv);
                    float x1 = acc[i][2 * p];
                    float x2 = acc[i][2 * p + 1];
                    acc[i][2 * p]     = x1 * cv - x2 * sv;
                    acc[i][2 * p + 1] = x1 * sv + x2 * cv;
                }
            }
            if (LAYOUT == 1) {
                int n = n0 + tx * 8;
                int h = n / HD;
                int d = n & (HD - 1);
                float* dst = out + (((size_t)b * H_DIM + h) * Lseq + l) * HD + d;
                float4 v0 = {acc[i][0], acc[i][1], acc[i][2], acc[i][3]};
                float4 v1 = {acc[i][4], acc[i][5], acc[i][6], acc[i][7]};
                *(float4*)dst       = v0;
                *(float4*)(dst + 4) = v1;
                continue;
            }
        }
        float* dst = out + (size_t)m * N + n0 + tx * 8;
        float4 v0 = {acc[i][0], acc[i][1], acc[i][2], acc[i][3]};
        float4 v1 = {acc[i][4], acc[i][5], acc[i][6], acc[i][7]};
        *(float4*)dst       = v0;
        *(float4*)(dst + 4) = v1;
    }
}

// ============================================================================
// Flash attention (fp32 / FFMA2)
//   Qs : [d][r]  64 x 132 ; KP : [d][c] 64 x 132 (reused as P^T) ; Vs : [s][d] 64 x 68
// Accumulators packed over row pairs.
// ============================================================================
#define ATTN_SMEM_FLOATS (2 * 64 * 132 + 64 * 68)

__global__ void __launch_bounds__(256)
flash_attn(const float* __restrict__ Qg,
           const float* __restrict__ Kg,
           const float* __restrict__ Vg,
           const unsigned char* __restrict__ mask,
           float* __restrict__ Og)
{
    extern __shared__ float sm[];
    float (*Qs)[132] = (float(*)[132])sm;
    float (*KP)[132] = (float(*)[132])(sm + 64 * 132);
    float (*Vs)[68]  = (float(*)[68])(sm + 2 * 64 * 132);

    const int tid = threadIdx.x;
    const int tx  = tid & 15;
    const int ty  = tid >> 4;
    const int bh  = blockIdx.y;
    const int b   = bh / H_DIM;
    const int l0  = blockIdx.x * 128;

    const float* Qp = Qg + (size_t)bh * L_DIM * HD;
    const float* Kp = Kg + (size_t)bh * S_DIM * HD;
    const float* Vp = Vg + (size_t)bh * S_DIM * HD;

#pragma unroll
    for (int it = 0; it < 8; it++) {
        int id  = it * 256 + tid;
        int row = id >> 4;
        int dq  = (id & 15) * 4;
        float4 v = *(const float4*)(Qp + (size_t)(l0 + row) * HD + dq);
        Qs[dq + 0][row] = v.x; Qs[dq + 1][row] = v.y;
        Qs[dq + 2][row] = v.z; Qs[dq + 3][row] = v.w;
    }

    u64 o2[4][4];
    float mi[8], li[8];
#pragma unroll
    for (int i = 0; i < 8; i++) { mi[i] = -CUDART_INF_F; li[i] = 0.0f; }
#pragma unroll
    for (int ip = 0; ip < 4; ip++)
#pragma unroll
        for (int j = 0; j < 4; j++) o2[ip][j] = 0ull;

    const float scale = 0.125f;   // 1/sqrt(64)

    for (int s0 = 0; s0 < S_DIM; s0 += 64) {
#pragma unroll
        for (int it = 0; it < 4; it++) {
            int id  = it * 256 + tid;
            int row = id >> 4;
            int dq  = (id & 15) * 4;
            float4 kv = *(const float4*)(Kp + (size_t)(s0 + row) * HD + dq);
            KP[dq + 0][row] = kv.x; KP[dq + 1][row] = kv.y;
            KP[dq + 2][row] = kv.z; KP[dq + 3][row] = kv.w;
            float4 vv = *(const float4*)(Vp + (size_t)(s0 + row) * HD + dq);
            *(float4*)&Vs[row][dq] = vv;
        }
        bool msk[4];
#pragma unroll
        for (int j = 0; j < 4; j++)
            msk[j] = mask[(size_t)b * S_DIM + s0 + tx * 4 + j] != 0;

        __syncthreads();

        // ---- GEMM1: scores = Q @ K^T (FFMA2, row-pair packed) ----
        u64 sa2[4][4];
#pragma unroll
        for (int ip = 0; ip < 4; ip++)
#pragma unroll
            for (int j = 0; j < 4; j++) sa2[ip][j] = 0ull;

#pragma unroll 4
        for (int d = 0; d < HD; d++) {
            ulonglong2 q01 = *(const ulonglong2*)&Qs[d][ty * 8];
            ulonglong2 q23 = *(const ulonglong2*)&Qs[d][ty * 8 + 4];
            u64 qp[4] = {q01.x, q01.y, q23.x, q23.y};
            float4 kk = *(const float4*)&KP[d][tx * 4];
            u64 kb[4] = {pack2(kk.x, kk.x), pack2(kk.y, kk.y),
                         pack2(kk.z, kk.z), pack2(kk.w, kk.w)};
#pragma unroll
            for (int ip = 0; ip < 4; ip++)
#pragma unroll
                for (int j = 0; j < 4; j++)
                    fma2(sa2[ip][j], qp[ip], kb[j]);
        }
        __syncthreads();   // all reads of KP (K) done before P overwrites it

        // unpack scores
        float sa[8][4];
#pragma unroll
        for (int ip = 0; ip < 4; ip++)
#pragma unroll
            for (int j = 0; j < 4; j++)
                unpack2(sa2[ip][j], sa[2 * ip][j], sa[2 * ip + 1][j]);

        // ---- online softmax (per row), rescale packed O per row pair ----
        float alpha[8];
#pragma unroll
        for (int i = 0; i < 8; i++) {
            float mloc = -CUDART_INF_F;
#pragma unroll
            for (int j = 0; j < 4; j++) {
                float v = msk[j] ? -CUDART_INF_F : sa[i][j] * scale;
                sa[i][j] = v;
                mloc = fmaxf(mloc, v);
            }
#pragma unroll
            for (int off = 8; off >= 1; off >>= 1)
                mloc = fmaxf(mloc, __shfl_xor_sync(0xffffffffu, mloc, off));
            float mnew = fmaxf(mi[i], mloc);
            alpha[i]   = __expf(mi[i] - mnew);
            float psum = 0.0f;
#pragma unroll
            for (int j = 0; j < 4; j++) {
                float p = __expf(sa[i][j] - mnew);
                sa[i][j] = p;
                psum += p;
            }
#pragma unroll
            for (int off = 8; off >= 1; off >>= 1)
                psum += __shfl_xor_sync(0xffffffffu, psum, off);
            li[i] = li[i] * alpha[i] + psum;
            mi[i] = mnew;
#pragma unroll
            for (int j = 0; j < 4; j++)
                KP[tx * 4 + j][ty * 8 + i] = sa[i][j];
        }
#pragma unroll
        for (int ip = 0; ip < 4; ip++) {
            u64 a2 = pack2(alpha[2 * ip], alpha[2 * ip + 1]);
#pragma unroll
            for (int j = 0; j < 4; j++) o2[ip][j] = mul2(o2[ip][j], a2);
        }
        __syncthreads();   // P^T fully written

        // ---- GEMM2: O += P @ V (FFMA2) ----
#pragma unroll 4
        for (int s = 0; s < 64; s++) {
            ulonglong2 p01 = *(const ulonglong2*)&KP[s][ty * 8];
            ulonglong2 p23 = *(const ulonglong2*)&KP[s][ty * 8 + 4];
            u64 pp[4] = {p01.x, p01.y, p23.x, p23.y};
            float4 vv = *(const float4*)&Vs[s][tx * 4];
            u64 vb[4] = {pack2(vv.x, vv.x), pack2(vv.y, vv.y),
                         pack2(vv.z, vv.z), pack2(vv.w, vv.w)};
#pragma unroll
            for (int ip = 0; ip < 4; ip++)
#pragma unroll
                for (int j = 0; j < 4; j++)
                    fma2(o2[ip][j], pp[ip], vb[j]);
        }
        __syncthreads();
    }

    // epilogue
#pragma unroll
    for (int ip = 0; ip < 4; ip++) {
        float olo[4], ohi[4];
#pragma unroll
        for (int j = 0; j < 4; j++) unpack2(o2[ip][j], olo[j], ohi[j]);
        int i0 = 2 * ip, i1 = 2 * ip + 1;
        int l_0 = l0 + ty * 8 + i0;
        int l_1 = l0 + ty * 8 + i1;
        float inv0 = 1.0f / li[i0], inv1 = 1.0f / li[i1];
        float4 r0 = {olo[0] * inv0, olo[1] * inv0, olo[2] * inv0, olo[3] * inv0};
        float4 r1 = {ohi[0] * inv1, ohi[1] * inv1, ohi[2] * inv1, ohi[3] * inv1};
        int h = blockIdx.y - b * H_DIM;
        *(float4*)(Og + ((size_t)l_0 * B_DIM + b) * E_DIM + h * HD + tx * 4) = r0;
        *(float4*)(Og + ((size_t)l_1 * B_DIM + b) * E_DIM + h * HD + tx * 4) = r1;
    }
}

// ============================================================================
// launch
// ============================================================================
extern "C" void kernel_launch(void* const* d_in, const int* in_sizes, int n_in,
                              void* d_out, int out_size)
{
    const float* query = (const float*)d_in[0];
    const float* key   = (const float*)d_in[1];
    const float* value = (const float*)d_in[2];
    const unsigned char* mask = (const unsigned char*)d_in[3];
    const float* Wq = (const float*)d_in[4];
    const float* bq = (const float*)d_in[5];
    const float* Wk = (const float*)d_in[6];
    const float* bk = (const float*)d_in[7];
    const float* Wv = (const float*)d_in[8];
    const float* bv = (const float*)d_in[9];
    const float* Wo = (const float*)d_in[10];
    const float* bo = (const float*)d_in[11];
    float* out = (float*)d_out;

    float *Qd, *Kd, *Vd, *Od;
    cudaGetSymbolAddress((void**)&Qd, g_Q);
    cudaGetSymbolAddress((void**)&Kd, g_K);
    cudaGetSymbolAddress((void**)&Vd, g_V);
    cudaGetSymbolAddress((void**)&Od, g_O);

    const size_t attn_smem = (size_t)ATTN_SMEM_FLOATS * sizeof(float);
    cudaFuncSetAttribute(flash_attn, cudaFuncAttributeMaxDynamicSharedMemorySize,
                         (int)attn_smem);

    dim3 pgrid(E_DIM / 128, M_ROWS / 128);   // (8, 32)
    dim3 pblk(256);

    proj_gemm<1, 1><<<pgrid, pblk>>>(query, Wq, bq, Qd, M_ROWS, E_DIM, E_DIM);
    proj_gemm<1, 1><<<pgrid, pblk>>>(key,   Wk, bk, Kd, M_ROWS, E_DIM, E_DIM);
    proj_gemm<1, 0><<<pgrid, pblk>>>(value, Wv, bv, Vd, M_ROWS, E_DIM, E_DIM);

    dim3 agrid(L_DIM / 128, B_DIM * H_DIM);  // (16, 32)
    flash_attn<<<agrid, dim3(256), attn_smem>>>(Qd, Kd, Vd, mask, Od);

    proj_gemm<0, 0><<<pgrid, pblk>>>(Od, Wo, bo, out, M_ROWS, E_DIM, E_DIM);
}

// round 4
// speedup vs baseline: 1.3842x; 1.3842x over previous
#include <cuda_runtime.h>
#include <cuda_bf16.h>
#include <math.h>
#include <math_constants.h>
#include <cstdint>

#define L_DIM 2048
#define S_DIM 2048
#define B_DIM 2
#define E_DIM 1024
#define H_DIM 16
#define HD    64
#define M_ROWS (L_DIM * B_DIM)   // 4096

// ============================ helpers ============================
__device__ __forceinline__ uint32_t smem_to_u32(const void* p) {
    uint32_t a;
    asm("{ .reg .u64 t; cvta.to.shared.u64 t, %1; cvt.u32.u64 %0, t; }" : "=r"(a) : "l"(p));
    return a;
}
__device__ __forceinline__ void cp_async16(uint32_t dst, const void* src) {
    asm volatile("cp.async.cg.shared.global [%0], [%1], 16;" :: "r"(dst), "l"(src));
}
#define CP_COMMIT() asm volatile("cp.async.commit_group;" ::: "memory")
#define CP_WAIT(n)  asm volatile("cp.async.wait_group %0;" :: "n"(n) : "memory")

__device__ __forceinline__ void ldmatrix_x4(uint32_t& r0, uint32_t& r1,
                                            uint32_t& r2, uint32_t& r3, uint32_t addr) {
    asm volatile("ldmatrix.sync.aligned.m8n8.x4.shared.b16 {%0,%1,%2,%3}, [%4];"
                 : "=r"(r0), "=r"(r1), "=r"(r2), "=r"(r3) : "r"(addr));
}
__device__ __forceinline__ void mma_bf16(float* d, const uint32_t* a, const uint32_t* b) {
    asm volatile(
        "mma.sync.aligned.m16n8k16.row.col.f32.bf16.bf16.f32 "
        "{%0,%1,%2,%3}, {%4,%5,%6,%7}, {%8,%9}, {%0,%1,%2,%3};"
        : "+f"(d[0]), "+f"(d[1]), "+f"(d[2]), "+f"(d[3])
        : "r"(a[0]), "r"(a[1]), "r"(a[2]), "r"(a[3]), "r"(b[0]), "r"(b[1]));
}

// ============================ scratch ============================
__device__ float g_Q[(size_t)B_DIM * H_DIM * L_DIM * HD];
__device__ float g_K[(size_t)B_DIM * H_DIM * S_DIM * HD];
__device__ float g_V[(size_t)B_DIM * H_DIM * S_DIM * HD];
__device__ float g_O[(size_t)L_DIM * B_DIM * E_DIM];
__device__ __nv_bfloat16 g_act_hi[(size_t)M_ROWS * E_DIM];
__device__ __nv_bfloat16 g_act_lo[(size_t)M_ROWS * E_DIM];
__device__ __nv_bfloat16 g_w_hi[(size_t)E_DIM * E_DIM];
__device__ __nv_bfloat16 g_w_lo[(size_t)E_DIM * E_DIM];

// ==================== fp32 -> bf16 hi/lo split ====================
__global__ void __launch_bounds__(256)
split_bf16(const float* __restrict__ x,
           __nv_bfloat16* __restrict__ hi,
           __nv_bfloat16* __restrict__ lo, int n4)
{
    int i = blockIdx.x * blockDim.x + threadIdx.x;
    if (i >= n4) return;
    float4 v = ((const float4*)x)[i];
    float f[4] = {v.x, v.y, v.z, v.w};
    ushort h[4], l[4];
#pragma unroll
    for (int j = 0; j < 4; j++) {
        __nv_bfloat16 hb = __float2bfloat16(f[j]);
        __nv_bfloat16 lb = __float2bfloat16(f[j] - __bfloat162float(hb));
        h[j] = __bfloat16_as_ushort(hb);
        l[j] = __bfloat16_as_ushort(lb);
    }
    uint2 uh = {(uint32_t)h[0] | ((uint32_t)h[1] << 16),
                (uint32_t)h[2] | ((uint32_t)h[3] << 16)};
    uint2 ul = {(uint32_t)l[0] | ((uint32_t)l[1] << 16),
                (uint32_t)l[2] | ((uint32_t)l[3] << 16)};
    ((uint2*)hi)[i] = uh;
    ((uint2*)lo)[i] = ul;
}

// ==================== mma.sync GEMM (3-pass bf16 split) ====================
// C[m][n] = sum_k A[m][k]*W[n][k] + bias[n].  CTA: 128x128 tile, K in 64-chunks,
// cp.async double-buffered.  8 warps: 4 along M (32 rows) x 2 along N (64 cols).
// Smem rows padded to 72 bf16 (144B) -> ldmatrix conflict-free.
#define BK        64
#define ROW_PAD   72
#define TILE_B    (128 * ROW_PAD * 2)        // 18432 B per tile
#define STAGE_B   (4 * TILE_B)               // Ah, Al, Wh, Wl
#define GEMM_SMEM (2 * STAGE_B)              // 147456 B
#define NCHUNK    (E_DIM / BK)               // 16

template<int LAYOUT, int ROPE>
__global__ void __launch_bounds__(256)
mma_gemm(const __nv_bfloat16* __restrict__ Ah, const __nv_bfloat16* __restrict__ Al,
         const __nv_bfloat16* __restrict__ Wh, const __nv_bfloat16* __restrict__ Wl,
         const float* __restrict__ bias, float* __restrict__ out)
{
    extern __shared__ char smem[];
    const uint32_t sb = smem_to_u32(smem);
    const int tid  = threadIdx.x;
    const int wid  = tid >> 5;
    const int lane = tid & 31;
    const int m0 = blockIdx.y * 128;
    const int n0 = blockIdx.x * 128;
    const int wm = (wid & 3) * 32;     // warp row offset in tile
    const int wn = (wid >> 2) * 64;    // warp col offset in tile

    const __nv_bfloat16* gsrc[4] = {Ah, Al, Wh, Wl};

    // ---- prefetch lambda-ish macro: stage fill via cp.async ----
    // 4 tiles x 128 rows x 4 chunks(16B) ... per tile: 128 rows x 8 chunks = 1024
    // total 4096 16B ops / 256 thr = 16 per thread
    auto prefetch = [&](int c, int buf) {
        const int k0 = c * BK;
#pragma unroll
        for (int it = 0; it < 16; it++) {
            int idx  = it * 256 + tid;       // 0..4095
            int tile = idx >> 10;            // 0..3
            int i    = idx & 1023;
            int row  = i >> 3;               // 0..127
            int ch   = i & 7;                // 16B chunk
            int grow = (tile < 2 ? m0 : n0) + row;
            const __nv_bfloat16* gp = gsrc[tile] + (size_t)grow * E_DIM + k0 + ch * 8;
            uint32_t dst = sb + buf * STAGE_B + tile * TILE_B + row * (ROW_PAD * 2) + ch * 16;
            cp_async16(dst, gp);
        }
        CP_COMMIT();
    };

    float acc[2][8][4];
#pragma unroll
    for (int mi = 0; mi < 2; mi++)
#pragma unroll
        for (int ni = 0; ni < 8; ni++)
#pragma unroll
            for (int q = 0; q < 4; q++) acc[mi][ni][q] = 0.0f;

    prefetch(0, 0);

    for (int c = 0; c < NCHUNK; c++) {
        const int buf = c & 1;
        if (c + 1 < NCHUNK) {
            prefetch(c + 1, buf ^ 1);
            CP_WAIT(1);
        } else {
            CP_WAIT(0);
        }
        __syncthreads();

        const uint32_t st = sb + buf * STAGE_B;
        // ldmatrix base offsets for this thread
        // A: rows wm + mi*16 + (lane%16), k-col (lane/16)*8
        const int arow = lane & 15;
        const int akh  = (lane >> 4) * 8;
        // B: group g = lane/8, r = lane%8 ; row = wn + nq*16 + (g>>1)*8 + r ; k = (g&1)*8
        const int bg = lane >> 3;
        const int br = lane & 7;

#pragma unroll
        for (int ks = 0; ks < 4; ks++) {
            const int kb = ks * 16;
            uint32_t ah[2][4], al[2][4];
#pragma unroll
            for (int mi = 0; mi < 2; mi++) {
                uint32_t addr = st + 0 * TILE_B +
                    (wm + mi * 16 + arow) * (ROW_PAD * 2) + (kb + akh) * 2;
                ldmatrix_x4(ah[mi][0], ah[mi][1], ah[mi][2], ah[mi][3], addr);
                addr += TILE_B;   // Al tile
                ldmatrix_x4(al[mi][0], al[mi][1], al[mi][2], al[mi][3], addr);
            }
            uint32_t bh[8][2], bl[8][2];
#pragma unroll
            for (int nq = 0; nq < 4; nq++) {
                uint32_t addr = st + 2 * TILE_B +
                    (wn + nq * 16 + (bg >> 1) * 8 + br) * (ROW_PAD * 2) + (kb + (bg & 1) * 8) * 2;
                uint32_t r0, r1, r2, r3;
                ldmatrix_x4(r0, r1, r2, r3, addr);
                bh[2 * nq][0] = r0; bh[2 * nq][1] = r1;
                bh[2 * nq + 1][0] = r2; bh[2 * nq + 1][1] = r3;
                addr += TILE_B;   // Wl tile
                ldmatrix_x4(r0, r1, r2, r3, addr);
                bl[2 * nq][0] = r0; bl[2 * nq][1] = r1;
                bl[2 * nq + 1][0] = r2; bl[2 * nq + 1][1] = r3;
            }
#pragma unroll
            for (int mi = 0; mi < 2; mi++)
#pragma unroll
                for (int ni = 0; ni < 8; ni++) {
                    mma_bf16(acc[mi][ni], ah[mi], bh[ni]);   // hi*hi
                    mma_bf16(acc[mi][ni], ah[mi], bl[ni]);   // hi*lo
                    mma_bf16(acc[mi][ni], al[mi], bh[ni]);   // lo*hi
                }
        }
        __syncthreads();
    }

    // -------- epilogue: bias + optional RoPE + layout store --------
    const int cbase = n0 + wn + (lane & 3) * 2;
#pragma unroll
    for (int ni = 0; ni < 8; ni++) {
        const int c = cbase + ni * 8;          // even column
        const float b0 = bias[c], b1 = bias[c + 1];
        float freq = 0.0f;
        if (ROPE) {
            int d = c & (HD - 1);
            freq = powf(10000.0f, -(float)d / (float)HD);
        }
        const int h    = c >> 6;               // head (E/HD = 16 heads)
        const int dcol = c & (HD - 1);
#pragma unroll
        for (int mi = 0; mi < 2; mi++) {
#pragma unroll
            for (int rg = 0; rg < 2; rg++) {
                int m = m0 + wm + mi * 16 + (lane >> 2) + rg * 8;
                float v0 = acc[mi][ni][2 * rg] + b0;
                float v1 = acc[mi][ni][2 * rg + 1] + b1;
                int l = m >> 1;            // B_DIM = 2
                int bb = m & 1;
                if (ROPE) {
                    float sv, cv;
                    sincosf((float)l * freq, &sv, &cv);
                    float x1 = v0, x2 = v1;
                    v0 = x1 * cv - x2 * sv;
                    v1 = x1 * sv + x2 * cv;
                }
                float2 r = {v0, v1};
                if (LAYOUT == 1) {
                    *(float2*)(out + (((size_t)bb * H_DIM + h) * L_DIM + l) * HD + dcol) = r;
                } else {
                    *(float2*)(out + (size_t)m * E_DIM + c) = r;
                }
            }
        }
    }
}

// ============================================================================
// Flash attention (Round-1 scalar fp32 version)
// ============================================================================
#define ATTN_SMEM_FLOATS (2 * 64 * 132 + 64 * 68)

__global__ void __launch_bounds__(256)
flash_attn(const float* __restrict__ Qg,
           const float* __restrict__ Kg,
           const float* __restrict__ Vg,
           const unsigned char* __restrict__ mask,
           float* __restrict__ Og)
{
    extern __shared__ float sm[];
    float (*Qs)[132] = (float(*)[132])sm;
    float (*KP)[132] = (float(*)[132])(sm + 64 * 132);
    float (*Vs)[68]  = (float(*)[68])(sm + 2 * 64 * 132);

    const int tid = threadIdx.x;
    const int tx  = tid & 15;
    const int ty  = tid >> 4;
    const int bh  = blockIdx.y;
    const int b   = bh / H_DIM;
    const int h   = bh - b * H_DIM;
    const int l0  = blockIdx.x * 128;

    const float* Qp = Qg + (size_t)bh * L_DIM * HD;
    const float* Kp = Kg + (size_t)bh * S_DIM * HD;
    const float* Vp = Vg + (size_t)bh * S_DIM * HD;

#pragma unroll
    for (int it = 0; it < 8; it++) {
        int id  = it * 256 + tid;
        int row = id >> 4;
        int dq  = (id & 15) * 4;
        float4 v = *(const float4*)(Qp + (size_t)(l0 + row) * HD + dq);
        Qs[dq + 0][row] = v.x; Qs[dq + 1][row] = v.y;
        Qs[dq + 2][row] = v.z; Qs[dq + 3][row] = v.w;
    }

    float o[8][4];
    float mi[8], li[8];
#pragma unroll
    for (int i = 0; i < 8; i++) {
        mi[i] = -CUDART_INF_F;
        li[i] = 0.0f;
#pragma unroll
        for (int j = 0; j < 4; j++) o[i][j] = 0.0f;
    }

    const float scale = 0.125f;

    for (int s0 = 0; s0 < S_DIM; s0 += 64) {
#pragma unroll
        for (int it = 0; it < 4; it++) {
            int id  = it * 256 + tid;
            int row = id >> 4;
            int dq  = (id & 15) * 4;
            float4 kv = *(const float4*)(Kp + (size_t)(s0 + row) * HD + dq);
            KP[dq + 0][row] = kv.x; KP[dq + 1][row] = kv.y;
            KP[dq + 2][row] = kv.z; KP[dq + 3][row] = kv.w;
            float4 vv = *(const float4*)(Vp + (size_t)(s0 + row) * HD + dq);
            *(float4*)&Vs[row][dq] = vv;
        }
        bool msk[4];
#pragma unroll
        for (int j = 0; j < 4; j++)
            msk[j] = mask[(size_t)b * S_DIM + s0 + tx * 4 + j] != 0;

        __syncthreads();

        float sa[8][4];
#pragma unroll
        for (int i = 0; i < 8; i++)
#pragma unroll
            for (int j = 0; j < 4; j++) sa[i][j] = 0.0f;

#pragma unroll 4
        for (int d = 0; d < HD; d++) {
            float4 a0 = *(const float4*)&Qs[d][ty * 8];
            float4 a1 = *(const float4*)&Qs[d][ty * 8 + 4];
            float4 kk = *(const float4*)&KP[d][tx * 4];
            float a[8] = {a0.x, a0.y, a0.z, a0.w, a1.x, a1.y, a1.z, a1.w};
            float kb[4] = {kk.x, kk.y, kk.z, kk.w};
#pragma unroll
            for (int i = 0; i < 8; i++)
#pragma unroll
                for (int j = 0; j < 4; j++)
                    sa[i][j] = fmaf(a[i], kb[j], sa[i][j]);
        }
        __syncthreads();

#pragma unroll
        for (int i = 0; i < 8; i++) {
            float mloc = -CUDART_INF_F;
#pragma unroll
            for (int j = 0; j < 4; j++) {
                float v = msk[j] ? -CUDART_INF_F : sa[i][j] * scale;
                sa[i][j] = v;
                mloc = fmaxf(mloc, v);
            }
#pragma unroll
            for (int off = 8; off >= 1; off >>= 1)
                mloc = fmaxf(mloc, __shfl_xor_sync(0xffffffffu, mloc, off));
            float mnew  = fmaxf(mi[i], mloc);
            float alpha = __expf(mi[i] - mnew);
            float psum  = 0.0f;
#pragma unroll
            for (int j = 0; j < 4; j++) {
                float p = __expf(sa[i][j] - mnew);
                sa[i][j] = p;
                psum += p;
            }
#pragma unroll
            for (int off = 8; off >= 1; off >>= 1)
                psum += __shfl_xor_sync(0xffffffffu, psum, off);
            li[i] = li[i] * alpha + psum;
            mi[i] = mnew;
#pragma unroll
            for (int j = 0; j < 4; j++) o[i][j] *= alpha;
#pragma unroll
            for (int j = 0; j < 4; j++)
                KP[tx * 4 + j][ty * 8 + i] = sa[i][j];
        }
        __syncthreads();

#pragma unroll 4
        for (int s = 0; s < 64; s++) {
            float4 p0 = *(const float4*)&KP[s][ty * 8];
            float4 p1 = *(const float4*)&KP[s][ty * 8 + 4];
            float4 vv = *(const float4*)&Vs[s][tx * 4];
            float p[8] = {p0.x, p0.y, p0.z, p0.w, p1.x, p1.y, p1.z, p1.w};
            float vb[4] = {vv.x, vv.y, vv.z, vv.w};
#pragma unroll
            for (int i = 0; i < 8; i++)
#pragma unroll
                for (int j = 0; j < 4; j++)
                    o[i][j] = fmaf(p[i], vb[j], o[i][j]);
        }
        __syncthreads();
    }

#pragma unroll
    for (int i = 0; i < 8; i++) {
        int l = l0 + ty * 8 + i;
        float inv = 1.0f / li[i];
        float4 res = {o[i][0] * inv, o[i][1] * inv, o[i][2] * inv, o[i][3] * inv};
        *(float4*)(Og + ((size_t)l * B_DIM + b) * E_DIM + h * HD + tx * 4) = res;
    }
}

// ============================================================================
// launch
// ============================================================================
extern "C" void kernel_launch(void* const* d_in, const int* in_sizes, int n_in,
                              void* d_out, int out_size)
{
    const float* query = (const float*)d_in[0];
    const float* key   = (const float*)d_in[1];
    const float* value = (const float*)d_in[2];
    const unsigned char* mask = (const unsigned char*)d_in[3];
    const float* Wq = (const float*)d_in[4];
    const float* bq = (const float*)d_in[5];
    const float* Wk = (const float*)d_in[6];
    const float* bk = (const float*)d_in[7];
    const float* Wv = (const float*)d_in[8];
    const float* bv = (const float*)d_in[9];
    const float* Wo = (const float*)d_in[10];
    const float* bo = (const float*)d_in[11];
    float* out = (float*)d_out;

    float *Qd, *Kd, *Vd, *Od;
    cudaGetSymbolAddress((void**)&Qd, g_Q);
    cudaGetSymbolAddress((void**)&Kd, g_K);
    cudaGetSymbolAddress((void**)&Vd, g_V);
    cudaGetSymbolAddress((void**)&Od, g_O);
    __nv_bfloat16 *ah, *al, *wh, *wl;
    cudaGetSymbolAddress((void**)&ah, g_act_hi);
    cudaGetSymbolAddress((void**)&al, g_act_lo);
    cudaGetSymbolAddress((void**)&wh, g_w_hi);
    cudaGetSymbolAddress((void**)&wl, g_w_lo);

    cudaFuncSetAttribute(mma_gemm<1, 1>, cudaFuncAttributeMaxDynamicSharedMemorySize, GEMM_SMEM);
    cudaFuncSetAttribute(mma_gemm<1, 0>, cudaFuncAttributeMaxDynamicSharedMemorySize, GEMM_SMEM);
    cudaFuncSetAttribute(mma_gemm<0, 0>, cudaFuncAttributeMaxDynamicSharedMemorySize, GEMM_SMEM);
    const size_t attn_smem = (size_t)ATTN_SMEM_FLOATS * sizeof(float);
    cudaFuncSetAttribute(flash_attn, cudaFuncAttributeMaxDynamicSharedMemorySize, (int)attn_smem);

    const int ACT4 = M_ROWS * E_DIM / 4;
    const int W4   = E_DIM * E_DIM / 4;
    dim3 ggrid(E_DIM / 128, M_ROWS / 128);   // (8, 32)

    // Q projection (+RoPE)
    split_bf16<<<ACT4 / 256, 256>>>(query, ah, al, ACT4);
    split_bf16<<<W4 / 256, 256>>>(Wq, wh, wl, W4);
    mma_gemm<1, 1><<<ggrid, 256, GEMM_SMEM>>>(ah, al, wh, wl, bq, Qd);

    // K projection (+RoPE)
    split_bf16<<<ACT4 / 256, 256>>>(key, ah, al, ACT4);
    split_bf16<<<W4 / 256, 256>>>(Wk, wh, wl, W4);
    mma_gemm<1, 1><<<ggrid, 256, GEMM_SMEM>>>(ah, al, wh, wl, bk, Kd);

    // V projection
    split_bf16<<<ACT4 / 256, 256>>>(value, ah, al, ACT4);
    split_bf16<<<W4 / 256, 256>>>(Wv, wh, wl, W4);
    mma_gemm<1, 0><<<ggrid, 256, GEMM_SMEM>>>(ah, al, wh, wl, bv, Vd);

    // attention
    dim3 agrid(L_DIM / 128, B_DIM * H_DIM);
    flash_attn<<<agrid, dim3(256), attn_smem>>>(Qd, Kd, Vd, mask, Od);

    // output projection
    split_bf16<<<ACT4 / 256, 256>>>(Od, ah, al, ACT4);
    split_bf16<<<W4 / 256, 256>>>(Wo, wh, wl, W4);
    mma_gemm<0, 0><<<ggrid, 256, GEMM_SMEM>>>(ah, al, wh, wl, bo, out);
}

// round 5
// speedup vs baseline: 2.7247x; 1.9684x over previous
#include <cuda_runtime.h>
#include <cuda_bf16.h>
#include <math.h>
#include <math_constants.h>
#include <cstdint>

#define L_DIM 2048
#define S_DIM 2048
#define B_DIM 2
#define E_DIM 1024
#define H_DIM 16
#define HD    64
#define M_ROWS (L_DIM * B_DIM)   // 4096

// ============================ helpers ============================
__device__ __forceinline__ uint32_t smem_to_u32(const void* p) {
    uint32_t a;
    asm("{ .reg .u64 t; cvta.to.shared.u64 t, %1; cvt.u32.u64 %0, t; }" : "=r"(a) : "l"(p));
    return a;
}
__device__ __forceinline__ void cp_async16(uint32_t dst, const void* src) {
    asm volatile("cp.async.cg.shared.global [%0], [%1], 16;" :: "r"(dst), "l"(src));
}
#define CP_COMMIT() asm volatile("cp.async.commit_group;" ::: "memory")
#define CP_WAIT(n)  asm volatile("cp.async.wait_group %0;" :: "n"(n) : "memory")

__device__ __forceinline__ void ldmatrix_x4(uint32_t& r0, uint32_t& r1,
                                            uint32_t& r2, uint32_t& r3, uint32_t addr) {
    asm volatile("ldmatrix.sync.aligned.m8n8.x4.shared.b16 {%0,%1,%2,%3}, [%4];"
                 : "=r"(r0), "=r"(r1), "=r"(r2), "=r"(r3) : "r"(addr));
}
__device__ __forceinline__ void ldmatrix_x4_trans(uint32_t& r0, uint32_t& r1,
                                                  uint32_t& r2, uint32_t& r3, uint32_t addr) {
    asm volatile("ldmatrix.sync.aligned.m8n8.x4.trans.shared.b16 {%0,%1,%2,%3}, [%4];"
                 : "=r"(r0), "=r"(r1), "=r"(r2), "=r"(r3) : "r"(addr));
}
__device__ __forceinline__ void mma_bf16(float* d, const uint32_t* a, const uint32_t* b) {
    asm volatile(
        "mma.sync.aligned.m16n8k16.row.col.f32.bf16.bf16.f32 "
        "{%0,%1,%2,%3}, {%4,%5,%6,%7}, {%8,%9}, {%0,%1,%2,%3};"
        : "+f"(d[0]), "+f"(d[1]), "+f"(d[2]), "+f"(d[3])
        : "r"(a[0]), "r"(a[1]), "r"(a[2]), "r"(a[3]), "r"(b[0]), "r"(b[1]));
}
// pack two fp32 -> bf16x2 (lo in low half)
__device__ __forceinline__ uint32_t packbf2(float lo, float hi) {
    __nv_bfloat16 a = __float2bfloat16(lo), b = __float2bfloat16(hi);
    return ((uint32_t)__bfloat16_as_ushort(b) << 16) | (uint32_t)__bfloat16_as_ushort(a);
}
// pack residuals (v - bf16(v)) of two fp32 -> bf16x2
__device__ __forceinline__ uint32_t packres2(float lo, float hi) {
    float rl = lo - __bfloat162float(__float2bfloat16(lo));
    float rh = hi - __bfloat162float(__float2bfloat16(hi));
    return packbf2(rl, rh);
}

// ============================ scratch ============================
__device__ __nv_bfloat16 g_act_hi[(size_t)M_ROWS * E_DIM];
__device__ __nv_bfloat16 g_act_lo[(size_t)M_ROWS * E_DIM];
__device__ __nv_bfloat16 g_w_hi[(size_t)E_DIM * E_DIM];
__device__ __nv_bfloat16 g_w_lo[(size_t)E_DIM * E_DIM];
#define BHTD ((size_t)B_DIM * H_DIM * L_DIM * HD)
__device__ __nv_bfloat16 g_Qh[BHTD], g_Ql[BHTD];
__device__ __nv_bfloat16 g_Kh[BHTD], g_Kl[BHTD];
__device__ __nv_bfloat16 g_Vh[BHTD], g_Vl[BHTD];

// ==================== fp32 -> bf16 hi/lo split ====================
__global__ void __launch_bounds__(256)
split_bf16(const float* __restrict__ x,
           __nv_bfloat16* __restrict__ hi,
           __nv_bfloat16* __restrict__ lo, int n4)
{
    int i = blockIdx.x * blockDim.x + threadIdx.x;
    if (i >= n4) return;
    float4 v = ((const float4*)x)[i];
    float f[4] = {v.x, v.y, v.z, v.w};
    ushort h[4], l[4];
#pragma unroll
    for (int j = 0; j < 4; j++) {
        __nv_bfloat16 hb = __float2bfloat16(f[j]);
        __nv_bfloat16 lb = __float2bfloat16(f[j] - __bfloat162float(hb));
        h[j] = __bfloat16_as_ushort(hb);
        l[j] = __bfloat16_as_ushort(lb);
    }
    uint2 uh = {(uint32_t)h[0] | ((uint32_t)h[1] << 16),
                (uint32_t)h[2] | ((uint32_t)h[3] << 16)};
    uint2 ul = {(uint32_t)l[0] | ((uint32_t)l[1] << 16),
                (uint32_t)l[2] | ((uint32_t)l[3] << 16)};
    ((uint2*)hi)[i] = uh;
    ((uint2*)lo)[i] = ul;
}

// ==================== mma.sync GEMM (3-pass bf16 split) ====================
// LAYOUT 0: fp32 out[m*N+n].  LAYOUT 1: bf16 hi/lo out at [((b*H+h)*L+l)*HD+d].
#define BK        64
#define ROW_PAD   72
#define TILE_B    (128 * ROW_PAD * 2)        // 18432 B per tile
#define STAGE_B   (4 * TILE_B)
#define GEMM_SMEM (2 * STAGE_B)              // 147456 B
#define NCHUNK    (E_DIM / BK)               // 16

template<int LAYOUT, int ROPE>
__global__ void __launch_bounds__(256)
mma_gemm(const __nv_bfloat16* __restrict__ Ah, const __nv_bfloat16* __restrict__ Al,
         const __nv_bfloat16* __restrict__ Wh, const __nv_bfloat16* __restrict__ Wl,
         const float* __restrict__ bias, float* __restrict__ outf,
         __nv_bfloat16* __restrict__ outh, __nv_bfloat16* __restrict__ outl)
{
    extern __shared__ char smem[];
    const uint32_t sb = smem_to_u32(smem);
    const int tid  = threadIdx.x;
    const int wid  = tid >> 5;
    const int lane = tid & 31;
    const int m0 = blockIdx.y * 128;
    const int n0 = blockIdx.x * 128;
    const int wm = (wid & 3) * 32;
    const int wn = (wid >> 2) * 64;

    const __nv_bfloat16* gsrc[4] = {Ah, Al, Wh, Wl};

    auto prefetch = [&](int c, int buf) {
        const int k0 = c * BK;
#pragma unroll
        for (int it = 0; it < 16; it++) {
            int idx  = it * 256 + tid;
            int tile = idx >> 10;
            int i    = idx & 1023;
            int row  = i >> 3;
            int ch   = i & 7;
            int grow = (tile < 2 ? m0 : n0) + row;
            const __nv_bfloat16* gp = gsrc[tile] + (size_t)grow * E_DIM + k0 + ch * 8;
            uint32_t dst = sb + buf * STAGE_B + tile * TILE_B + row * (ROW_PAD * 2) + ch * 16;
            cp_async16(dst, gp);
        }
        CP_COMMIT();
    };

    float acc[2][8][4];
#pragma unroll
    for (int mi = 0; mi < 2; mi++)
#pragma unroll
        for (int ni = 0; ni < 8; ni++)
#pragma unroll
            for (int q = 0; q < 4; q++) acc[mi][ni][q] = 0.0f;

    prefetch(0, 0);

    for (int c = 0; c < NCHUNK; c++) {
        const int buf = c & 1;
        if (c + 1 < NCHUNK) {
            prefetch(c + 1, buf ^ 1);
            CP_WAIT(1);
        } else {
            CP_WAIT(0);
        }
        __syncthreads();

        const uint32_t st = sb + buf * STAGE_B;
        const int arow = lane & 15;
        const int akh  = (lane >> 4) * 8;
        const int bg = lane >> 3;
        const int br = lane & 7;

#pragma unroll
        for (int ks = 0; ks < 4; ks++) {
            const int kb = ks * 16;
            uint32_t ah[2][4], al[2][4];
#pragma unroll
            for (int mi = 0; mi < 2; mi++) {
                uint32_t addr = st + 0 * TILE_B +
                    (wm + mi * 16 + arow) * (ROW_PAD * 2) + (kb + akh) * 2;
                ldmatrix_x4(ah[mi][0], ah[mi][1], ah[mi][2], ah[mi][3], addr);
                addr += TILE_B;
                ldmatrix_x4(al[mi][0], al[mi][1], al[mi][2], al[mi][3], addr);
            }
            uint32_t bhv[8][2], blv[8][2];
#pragma unroll
            for (int nq = 0; nq < 4; nq++) {
                uint32_t addr = st + 2 * TILE_B +
                    (wn + nq * 16 + (bg >> 1) * 8 + br) * (ROW_PAD * 2) + (kb + (bg & 1) * 8) * 2;
                uint32_t r0, r1, r2, r3;
                ldmatrix_x4(r0, r1, r2, r3, addr);
                bhv[2 * nq][0] = r0; bhv[2 * nq][1] = r1;
                bhv[2 * nq + 1][0] = r2; bhv[2 * nq + 1][1] = r3;
                addr += TILE_B;
                ldmatrix_x4(r0, r1, r2, r3, addr);
                blv[2 * nq][0] = r0; blv[2 * nq][1] = r1;
                blv[2 * nq + 1][0] = r2; blv[2 * nq + 1][1] = r3;
            }
#pragma unroll
            for (int mi = 0; mi < 2; mi++)
#pragma unroll
                for (int ni = 0; ni < 8; ni++) {
                    mma_bf16(acc[mi][ni], ah[mi], bhv[ni]);
                    mma_bf16(acc[mi][ni], ah[mi], blv[ni]);
                    mma_bf16(acc[mi][ni], al[mi], bhv[ni]);
                }
        }
        __syncthreads();
    }

    // -------- epilogue --------
    const int cbase = n0 + wn + (lane & 3) * 2;
#pragma unroll
    for (int ni = 0; ni < 8; ni++) {
        const int c = cbase + ni * 8;
        const float b0 = bias[c], b1 = bias[c + 1];
        float freq = 0.0f;
        if (ROPE) {
            int d = c & (HD - 1);
            freq = powf(10000.0f, -(float)d / (float)HD);
        }
        const int h    = c >> 6;
        const int dcol = c & (HD - 1);
#pragma unroll
        for (int mi = 0; mi < 2; mi++) {
#pragma unroll
            for (int rg = 0; rg < 2; rg++) {
                int m = m0 + wm + mi * 16 + (lane >> 2) + rg * 8;
                float v0 = acc[mi][ni][2 * rg] + b0;
                float v1 = acc[mi][ni][2 * rg + 1] + b1;
                int l  = m >> 1;           // B_DIM = 2
                int bb = m & 1;
                if (ROPE) {
                    float sv, cv;
                    sincosf((float)l * freq, &sv, &cv);
                    float x1 = v0, x2 = v1;
                    v0 = x1 * cv - x2 * sv;
                    v1 = x1 * sv + x2 * cv;
                }
                if (LAYOUT == 1) {
                    size_t idx = (((size_t)bb * H_DIM + h) * L_DIM + l) * HD + dcol;
                    *(uint32_t*)(outh + idx) = packbf2(v0, v1);
                    *(uint32_t*)(outl + idx) = packres2(v0, v1);
                } else {
                    float2 r = {v0, v1};
                    *(float2*)(outf + (size_t)m * E_DIM + c) = r;
                }
            }
        }
    }
}

// ==================== flash attention on mma.sync (3-pass) ====================
// Per CTA: (b,h), 128 Q rows. 8 warps x 16 rows. S in 64-chunks, double buffered.
// smem: Qh,Ql 128x64 (pad 72); per stage Kh,Kl,Vh,Vl 64x64 (pad 72).
#define FA_ROWB   144                      // 72 bf16 pitch
#define FA_QTILE  (128 * FA_ROWB)          // 18432
#define FA_KVTILE (64 * FA_ROWB)           // 9216
#define FA_STAGE  (4 * FA_KVTILE)          // 36864
#define FA_SMEM   (2 * FA_QTILE + 2 * FA_STAGE)   // 110592
#define FA_NC     (S_DIM / 64)             // 32

__global__ void __launch_bounds__(256)
flash_attn_mma(const __nv_bfloat16* __restrict__ Qh_g, const __nv_bfloat16* __restrict__ Ql_g,
               const __nv_bfloat16* __restrict__ Kh_g, const __nv_bfloat16* __restrict__ Kl_g,
               const __nv_bfloat16* __restrict__ Vh_g, const __nv_bfloat16* __restrict__ Vl_g,
               const unsigned char* __restrict__ mask,
               __nv_bfloat16* __restrict__ Oh_g, __nv_bfloat16* __restrict__ Ol_g)
{
    extern __shared__ char smem[];
    const uint32_t sb = smem_to_u32(smem);
    const int tid = threadIdx.x, lane = tid & 31, wid = tid >> 5;
    const int bh = blockIdx.y, b = bh >> 4, h = bh & 15;
    const int l0 = blockIdx.x * 128;
    const int wm = wid * 16;

    const size_t goff = (size_t)bh * L_DIM * HD;

    // Q tiles (hi, lo): 2 x 128 rows x 8 chunks of 16B
    const __nv_bfloat16* qsrc[2] = {Qh_g + goff, Ql_g + goff};
#pragma unroll
    for (int it = 0; it < 8; it++) {
        int idx = it * 256 + tid;
        int tile = idx >> 10, i = idx & 1023, row = i >> 3, ch = i & 7;
        cp_async16(sb + tile * FA_QTILE + row * FA_ROWB + ch * 16,
                   qsrc[tile] + (size_t)(l0 + row) * HD + ch * 8);
    }

    const __nv_bfloat16* kvsrc[4] = {Kh_g + goff, Kl_g + goff, Vh_g + goff, Vl_g + goff};
    const uint32_t kvbase = sb + 2 * FA_QTILE;
    auto prefetch_kv = [&](int c, int buf) {
        int s0 = c * 64;
#pragma unroll
        for (int it = 0; it < 8; it++) {
            int idx = it * 256 + tid;
            int tile = idx >> 9, i = idx & 511, row = i >> 3, ch = i & 7;
            cp_async16(kvbase + buf * FA_STAGE + tile * FA_KVTILE + row * FA_ROWB + ch * 16,
                       kvsrc[tile] + (size_t)(s0 + row) * HD + ch * 8);
        }
        CP_COMMIT();
    };
    prefetch_kv(0, 0);   // commits Q loads too

    float o_acc[8][4];
#pragma unroll
    for (int ni = 0; ni < 8; ni++)
#pragma unroll
        for (int q = 0; q < 4; q++) o_acc[ni][q] = 0.0f;
    float mi0 = -CUDART_INF_F, mi1 = -CUDART_INF_F, li0 = 0.0f, li1 = 0.0f;

    const int arow = lane & 15, akh = (lane >> 4) * 8;
    const int bg = lane >> 3, br = lane & 7;
    const int brow_off = (bg >> 1) * 8 + br;       // K n-row offset
    const int bk_off   = (bg & 1) * 8;             // K k offset
    const int trow_off = ((lane >> 3) & 1) * 8 + (lane & 7);   // V trans row
    const int tcol_off = (lane >> 4) * 8;                      // V trans col
    const float scale = 0.125f;   // 1/sqrt(64)

    for (int c = 0; c < FA_NC; c++) {
        const int buf = c & 1;
        if (c + 1 < FA_NC) { prefetch_kv(c + 1, buf ^ 1); CP_WAIT(1); }
        else               { CP_WAIT(0); }
        __syncthreads();

        const uint32_t sK = kvbase + buf * FA_STAGE;       // Kh; Kl at +FA_KVTILE
        const uint32_t sV = sK + 2 * FA_KVTILE;             // Vh; Vl at +FA_KVTILE

        // ---- GEMM1: S = Q @ K^T (3-pass) ----
        float s[8][4];
#pragma unroll
        for (int ni = 0; ni < 8; ni++)
#pragma unroll
            for (int q = 0; q < 4; q++) s[ni][q] = 0.0f;

#pragma unroll
        for (int ks = 0; ks < 4; ks++) {
            const int kb = ks * 16;
            uint32_t qh[4], ql[4];
            uint32_t qaddr = sb + (wm + arow) * FA_ROWB + (kb + akh) * 2;
            ldmatrix_x4(qh[0], qh[1], qh[2], qh[3], qaddr);
            ldmatrix_x4(ql[0], ql[1], ql[2], ql[3], qaddr + FA_QTILE);
#pragma unroll
            for (int nq = 0; nq < 4; nq++) {
                uint32_t kaddr = sK + (nq * 16 + brow_off) * FA_ROWB + (kb + bk_off) * 2;
                uint32_t k0, k1, k2, k3, e0, e1, e2, e3;
                ldmatrix_x4(k0, k1, k2, k3, kaddr);
                ldmatrix_x4(e0, e1, e2, e3, kaddr + FA_KVTILE);
                uint32_t kh0[2] = {k0, k1}, kh1[2] = {k2, k3};
                uint32_t kl0[2] = {e0, e1}, kl1[2] = {e2, e3};
                mma_bf16(s[2 * nq],     qh, kh0);
                mma_bf16(s[2 * nq],     qh, kl0);
                mma_bf16(s[2 * nq],     ql, kh0);
                mma_bf16(s[2 * nq + 1], qh, kh1);
                mma_bf16(s[2 * nq + 1], qh, kl1);
                mma_bf16(s[2 * nq + 1], ql, kh1);
            }
        }

        // ---- online softmax (in-warp: rows r0=lane/4, r1=r0+8) ----
        const int s0c = c * 64;
        float mlo = -CUDART_INF_F, mhi = -CUDART_INF_F;
#pragma unroll
        for (int ni = 0; ni < 8; ni++) {
            uchar2 mk = *(const uchar2*)(mask + (size_t)b * S_DIM + s0c + ni * 8 + (lane & 3) * 2);
            float v0 = mk.x ? -CUDART_INF_F : s[ni][0] * scale;
            float v1 = mk.y ? -CUDART_INF_F : s[ni][1] * scale;
            float v2 = mk.x ? -CUDART_INF_F : s[ni][2] * scale;
            float v3 = mk.y ? -CUDART_INF_F : s[ni][3] * scale;
            s[ni][0] = v0; s[ni][1] = v1; s[ni][2] = v2; s[ni][3] = v3;
            mlo = fmaxf(mlo, fmaxf(v0, v1));
            mhi = fmaxf(mhi, fmaxf(v2, v3));
        }
        mlo = fmaxf(mlo, __shfl_xor_sync(0xffffffffu, mlo, 1));
        mlo = fmaxf(mlo, __shfl_xor_sync(0xffffffffu, mlo, 2));
        mhi = fmaxf(mhi, __shfl_xor_sync(0xffffffffu, mhi, 1));
        mhi = fmaxf(mhi, __shfl_xor_sync(0xffffffffu, mhi, 2));

        float mn0 = fmaxf(mi0, mlo), mn1 = fmaxf(mi1, mhi);
        float a0 = __expf(mi0 - mn0), a1 = __expf(mi1 - mn1);
        float ps0 = 0.0f, ps1 = 0.0f;
#pragma unroll
        for (int ni = 0; ni < 8; ni++) {
            float p0 = __expf(s[ni][0] - mn0);
            float p1 = __expf(s[ni][1] - mn0);
            float p2 = __expf(s[ni][2] - mn1);
            float p3 = __expf(s[ni][3] - mn1);
            s[ni][0] = p0; s[ni][1] = p1; s[ni][2] = p2; s[ni][3] = p3;
            ps0 += p0 + p1;
            ps1 += p2 + p3;
        }
        ps0 += __shfl_xor_sync(0xffffffffu, ps0, 1);
        ps0 += __shfl_xor_sync(0xffffffffu, ps0, 2);
        ps1 += __shfl_xor_sync(0xffffffffu, ps1, 1);
        ps1 += __shfl_xor_sync(0xffffffffu, ps1, 2);
        li0 = li0 * a0 + ps0;
        li1 = li1 * a1 + ps1;
        mi0 = mn0; mi1 = mn1;
#pragma unroll
        for (int ni = 0; ni < 8; ni++) {
            o_acc[ni][0] *= a0; o_acc[ni][1] *= a0;
            o_acc[ni][2] *= a1; o_acc[ni][3] *= a1;
        }

        // ---- GEMM2: O += P @ V (P from regs, split; V via ldmatrix.trans) ----
#pragma unroll
        for (int ks = 0; ks < 4; ks++) {
            uint32_t pah[4], pal[4];
            pah[0] = packbf2(s[2 * ks][0],     s[2 * ks][1]);
            pah[1] = packbf2(s[2 * ks][2],     s[2 * ks][3]);
            pah[2] = packbf2(s[2 * ks + 1][0], s[2 * ks + 1][1]);
            pah[3] = packbf2(s[2 * ks + 1][2], s[2 * ks + 1][3]);
            pal[0] = packres2(s[2 * ks][0],     s[2 * ks][1]);
            pal[1] = packres2(s[2 * ks][2],     s[2 * ks][3]);
            pal[2] = packres2(s[2 * ks + 1][0], s[2 * ks + 1][1]);
            pal[3] = packres2(s[2 * ks + 1][2], s[2 * ks + 1][3]);
#pragma unroll
            for (int nb = 0; nb < 4; nb++) {
                uint32_t vaddr = sV + (ks * 16 + trow_off) * FA_ROWB + (nb * 16 + tcol_off) * 2;
                uint32_t v0, v1, v2, v3, w0, w1, w2, w3;
                ldmatrix_x4_trans(v0, v1, v2, v3, vaddr);
                ldmatrix_x4_trans(w0, w1, w2, w3, vaddr + FA_KVTILE);
                uint32_t vh0[2] = {v0, v1}, vh1[2] = {v2, v3};
                uint32_t vl0[2] = {w0, w1}, vl1[2] = {w2, w3};
                mma_bf16(o_acc[2 * nb],     pah, vh0);
                mma_bf16(o_acc[2 * nb],     pah, vl0);
                mma_bf16(o_acc[2 * nb],     pal, vh0);
                mma_bf16(o_acc[2 * nb + 1], pah, vh1);
                mma_bf16(o_acc[2 * nb + 1], pah, vl1);
                mma_bf16(o_acc[2 * nb + 1], pal, vh1);
            }
        }
        __syncthreads();
    }

    // ---- epilogue: normalize, split to bf16 hi/lo act layout [m][E], m=l*2+b ----
    const float inv0 = 1.0f / li0, inv1 = 1.0f / li1;
    const int r0 = lane >> 2;
    const int m0g = ((l0 + wm + r0) << 1) | b;
    const int m1g = ((l0 + wm + r0 + 8) << 1) | b;
#pragma unroll
    for (int ni = 0; ni < 8; ni++) {
        int cg = h * HD + ni * 8 + (lane & 3) * 2;
        float v00 = o_acc[ni][0] * inv0, v01 = o_acc[ni][1] * inv0;
        float v10 = o_acc[ni][2] * inv1, v11 = o_acc[ni][3] * inv1;
        *(uint32_t*)(Oh_g + (size_t)m0g * E_DIM + cg) = packbf2(v00, v01);
        *(uint32_t*)(Ol_g + (size_t)m0g * E_DIM + cg) = packres2(v00, v01);
        *(uint32_t*)(Oh_g + (size_t)m1g * E_DIM + cg) = packbf2(v10, v11);
        *(uint32_t*)(Ol_g + (size_t)m1g * E_DIM + cg) = packres2(v10, v11);
    }
}

// ============================================================================
// launch
// ============================================================================
extern "C" void kernel_launch(void* const* d_in, const int* in_sizes, int n_in,
                              void* d_out, int out_size)
{
    const float* query = (const float*)d_in[0];
    const float* key   = (const float*)d_in[1];
    const float* value = (const float*)d_in[2];
    const unsigned char* mask = (const unsigned char*)d_in[3];
    const float* Wq = (const float*)d_in[4];
    const float* bq = (const float*)d_in[5];
    const float* Wk = (const float*)d_in[6];
    const float* bk = (const float*)d_in[7];
    const float* Wv = (const float*)d_in[8];
    const float* bv = (const float*)d_in[9];
    const float* Wo = (const float*)d_in[10];
    const float* bo = (const float*)d_in[11];
    float* out = (float*)d_out;

    __nv_bfloat16 *ah, *al, *wh, *wl;
    __nv_bfloat16 *qh, *ql, *kh, *kl, *vh, *vl;
    cudaGetSymbolAddress((void**)&ah, g_act_hi);
    cudaGetSymbolAddress((void**)&al, g_act_lo);
    cudaGetSymbolAddress((void**)&wh, g_w_hi);
    cudaGetSymbolAddress((void**)&wl, g_w_lo);
    cudaGetSymbolAddress((void**)&qh, g_Qh);
    cudaGetSymbolAddress((void**)&ql, g_Ql);
    cudaGetSymbolAddress((void**)&kh, g_Kh);
    cudaGetSymbolAddress((void**)&kl, g_Kl);
    cudaGetSymbolAddress((void**)&vh, g_Vh);
    cudaGetSymbolAddress((void**)&vl, g_Vl);

    cudaFuncSetAttribute(mma_gemm<1, 1>, cudaFuncAttributeMaxDynamicSharedMemorySize, GEMM_SMEM);
    cudaFuncSetAttribute(mma_gemm<1, 0>, cudaFuncAttributeMaxDynamicSharedMemorySize, GEMM_SMEM);
    cudaFuncSetAttribute(mma_gemm<0, 0>, cudaFuncAttributeMaxDynamicSharedMemorySize, GEMM_SMEM);
    cudaFuncSetAttribute(flash_attn_mma, cudaFuncAttributeMaxDynamicSharedMemorySize, FA_SMEM);

    const int ACT4 = M_ROWS * E_DIM / 4;
    const int W4   = E_DIM * E_DIM / 4;
    dim3 ggrid(E_DIM / 128, M_ROWS / 128);   // (8, 32)

    // Q projection (+RoPE) -> bf16 hi/lo [B][H][L][hd]
    split_bf16<<<ACT4 / 256, 256>>>(query, ah, al, ACT4);
    split_bf16<<<W4 / 256, 256>>>(Wq, wh, wl, W4);
    mma_gemm<1, 1><<<ggrid, 256, GEMM_SMEM>>>(ah, al, wh, wl, bq, nullptr, qh, ql);

    // K projection (+RoPE)
    split_bf16<<<ACT4 / 256, 256>>>(key, ah, al, ACT4);
    split_bf16<<<W4 / 256, 256>>>(Wk, wh, wl, W4);
    mma_gemm<1, 1><<<ggrid, 256, GEMM_SMEM>>>(ah, al, wh, wl, bk, nullptr, kh, kl);

    // V projection
    split_bf16<<<ACT4 / 256, 256>>>(value, ah, al, ACT4);
    split_bf16<<<W4 / 256, 256>>>(Wv, wh, wl, W4);
    mma_gemm<1, 0><<<ggrid, 256, GEMM_SMEM>>>(ah, al, wh, wl, bv, nullptr, vh, vl);

    // attention -> act hi/lo [m][E]
    dim3 agrid(L_DIM / 128, B_DIM * H_DIM);   // (16, 32)
    flash_attn_mma<<<agrid, 256, FA_SMEM>>>(qh, ql, kh, kl, vh, vl, mask, ah, al);

    // output projection -> d_out fp32
    split_bf16<<<W4 / 256, 256>>>(Wo, wh, wl, W4);
    mma_gemm<0, 0><<<ggrid, 256, GEMM_SMEM>>>(ah, al, wh, wl, bo, out, nullptr, nullptr);
}

// round 6
// speedup vs baseline: 2.8285x; 1.0381x over previous
#include <cuda_runtime.h>
#include <cuda_bf16.h>
#include <math.h>
#include <math_constants.h>
#include <cstdint>

#define L_DIM 2048
#define S_DIM 2048
#define B_DIM 2
#define E_DIM 1024
#define H_DIM 16
#define HD    64
#define M_ROWS (L_DIM * B_DIM)   // 4096

// ============================ helpers ============================
__device__ __forceinline__ uint32_t smem_to_u32(const void* p) {
    uint32_t a;
    asm("{ .reg .u64 t; cvta.to.shared.u64 t, %1; cvt.u32.u64 %0, t; }" : "=r"(a) : "l"(p));
    return a;
}
__device__ __forceinline__ void cp_async16(uint32_t dst, const void* src) {
    asm volatile("cp.async.cg.shared.global [%0], [%1], 16;" :: "r"(dst), "l"(src));
}
#define CP_COMMIT() asm volatile("cp.async.commit_group;" ::: "memory")
#define CP_WAIT(n)  asm volatile("cp.async.wait_group %0;" :: "n"(n) : "memory")

__device__ __forceinline__ void ldmatrix_x4(uint32_t& r0, uint32_t& r1,
                                            uint32_t& r2, uint32_t& r3, uint32_t addr) {
    asm volatile("ldmatrix.sync.aligned.m8n8.x4.shared.b16 {%0,%1,%2,%3}, [%4];"
                 : "=r"(r0), "=r"(r1), "=r"(r2), "=r"(r3) : "r"(addr));
}
__device__ __forceinline__ void ldmatrix_x4_trans(uint32_t& r0, uint32_t& r1,
                                                  uint32_t& r2, uint32_t& r3, uint32_t addr) {
    asm volatile("ldmatrix.sync.aligned.m8n8.x4.trans.shared.b16 {%0,%1,%2,%3}, [%4];"
                 : "=r"(r0), "=r"(r1), "=r"(r2), "=r"(r3) : "r"(addr));
}
__device__ __forceinline__ void mma_bf16(float* d, const uint32_t* a, const uint32_t* b) {
    asm volatile(
        "mma.sync.aligned.m16n8k16.row.col.f32.bf16.bf16.f32 "
        "{%0,%1,%2,%3}, {%4,%5,%6,%7}, {%8,%9}, {%0,%1,%2,%3};"
        : "+f"(d[0]), "+f"(d[1]), "+f"(d[2]), "+f"(d[3])
        : "r"(a[0]), "r"(a[1]), "r"(a[2]), "r"(a[3]), "r"(b[0]), "r"(b[1]));
}
__device__ __forceinline__ uint32_t packbf2(float lo, float hi) {
    __nv_bfloat16 a = __float2bfloat16(lo), b = __float2bfloat16(hi);
    return ((uint32_t)__bfloat16_as_ushort(b) << 16) | (uint32_t)__bfloat16_as_ushort(a);
}
__device__ __forceinline__ uint32_t packres2(float lo, float hi) {
    float rl = lo - __bfloat162float(__float2bfloat16(lo));
    float rh = hi - __bfloat162float(__float2bfloat16(hi));
    return packbf2(rl, rh);
}

// ============================ scratch ============================
#define ACT_SZ ((size_t)M_ROWS * E_DIM)
#define W_SZ   ((size_t)E_DIM * E_DIM)
__device__ __nv_bfloat16 g_aq_h[ACT_SZ], g_aq_l[ACT_SZ];
__device__ __nv_bfloat16 g_ak_h[ACT_SZ], g_ak_l[ACT_SZ];
__device__ __nv_bfloat16 g_av_h[ACT_SZ], g_av_l[ACT_SZ];
__device__ __nv_bfloat16 g_wq_h[W_SZ], g_wq_l[W_SZ];
__device__ __nv_bfloat16 g_wk_h[W_SZ], g_wk_l[W_SZ];
__device__ __nv_bfloat16 g_wv_h[W_SZ], g_wv_l[W_SZ];
__device__ __nv_bfloat16 g_wo_h[W_SZ], g_wo_l[W_SZ];
#define BHTD ((size_t)B_DIM * H_DIM * L_DIM * HD)
__device__ __nv_bfloat16 g_Qh[BHTD], g_Ql[BHTD];
__device__ __nv_bfloat16 g_Kh[BHTD], g_Kl[BHTD];
__device__ __nv_bfloat16 g_Vh[BHTD], g_Vl[BHTD];

// ==================== fp32 -> bf16 hi/lo split ====================
__global__ void __launch_bounds__(256)
split_bf16(const float* __restrict__ x,
           __nv_bfloat16* __restrict__ hi,
           __nv_bfloat16* __restrict__ lo, int n4)
{
    int i = blockIdx.x * blockDim.x + threadIdx.x;
    if (i >= n4) return;
    float4 v = ((const float4*)x)[i];
    float f[4] = {v.x, v.y, v.z, v.w};
    ushort h[4], l[4];
#pragma unroll
    for (int j = 0; j < 4; j++) {
        __nv_bfloat16 hb = __float2bfloat16(f[j]);
        __nv_bfloat16 lb = __float2bfloat16(f[j] - __bfloat162float(hb));
        h[j] = __bfloat16_as_ushort(hb);
        l[j] = __bfloat16_as_ushort(lb);
    }
    uint2 uh = {(uint32_t)h[0] | ((uint32_t)h[1] << 16),
                (uint32_t)h[2] | ((uint32_t)h[3] << 16)};
    uint2 ul = {(uint32_t)l[0] | ((uint32_t)l[1] << 16),
                (uint32_t)l[2] | ((uint32_t)l[3] << 16)};
    ((uint2*)hi)[i] = uh;
    ((uint2*)lo)[i] = ul;
}

// ==================== GEMM core (BK=32, 2 CTA/SM) ====================
#define BK        32
#define ROW_PADB  40                          // bf16 pitch (80 B)
#define TILE_B    (128 * ROW_PADB * 2)        // 10240 B
#define STAGE_B   (4 * TILE_B)                // 40960
#define GEMM_SMEM (2 * STAGE_B)               // 81920
#define NCHUNK    (E_DIM / BK)                // 32

__device__ __forceinline__ void gemm_core(
    const __nv_bfloat16* __restrict__ Ah, const __nv_bfloat16* __restrict__ Al,
    const __nv_bfloat16* __restrict__ Wh, const __nv_bfloat16* __restrict__ Wl,
    uint32_t sb, int m0, int n0, int tid, float acc[2][8][4])
{
    const int wid  = tid >> 5;
    const int lane = tid & 31;
    const int wm = (wid & 3) * 32;
    const int wn = (wid >> 2) * 64;

    const __nv_bfloat16* gsrc[4] = {Ah, Al, Wh, Wl};

    auto prefetch = [&](int c, int buf) {
        const int k0 = c * BK;
#pragma unroll
        for (int it = 0; it < 8; it++) {
            int idx  = it * 256 + tid;        // 0..2047
            int tile = idx >> 9;              // 0..3
            int i    = idx & 511;
            int row  = i >> 2;                // 0..127
            int ch   = i & 3;                 // 16B chunk (4 per row)
            int grow = (tile < 2 ? m0 : n0) + row;
            const __nv_bfloat16* gp = gsrc[tile] + (size_t)grow * E_DIM + k0 + ch * 8;
            uint32_t dst = sb + buf * STAGE_B + tile * TILE_B + row * (ROW_PADB * 2) + ch * 16;
            cp_async16(dst, gp);
        }
        CP_COMMIT();
    };

    prefetch(0, 0);

    const int arow = lane & 15;
    const int akh  = (lane >> 4) * 8;
    const int bg = lane >> 3;
    const int br = lane & 7;

    for (int c = 0; c < NCHUNK; c++) {
        const int buf = c & 1;
        if (c + 1 < NCHUNK) { prefetch(c + 1, buf ^ 1); CP_WAIT(1); }
        else                { CP_WAIT(0); }
        __syncthreads();

        const uint32_t st = sb + buf * STAGE_B;
#pragma unroll
        for (int ks = 0; ks < 2; ks++) {
            const int kb = ks * 16;
            uint32_t ah[2][4], al[2][4];
#pragma unroll
            for (int mi = 0; mi < 2; mi++) {
                uint32_t addr = st +
                    (wm + mi * 16 + arow) * (ROW_PADB * 2) + (kb + akh) * 2;
                ldmatrix_x4(ah[mi][0], ah[mi][1], ah[mi][2], ah[mi][3], addr);
                addr += TILE_B;
                ldmatrix_x4(al[mi][0], al[mi][1], al[mi][2], al[mi][3], addr);
            }
            uint32_t bhv[8][2], blv[8][2];
#pragma unroll
            for (int nq = 0; nq < 4; nq++) {
                uint32_t addr = st + 2 * TILE_B +
                    (wn + nq * 16 + (bg >> 1) * 8 + br) * (ROW_PADB * 2) + (kb + (bg & 1) * 8) * 2;
                uint32_t r0, r1, r2, r3;
                ldmatrix_x4(r0, r1, r2, r3, addr);
                bhv[2 * nq][0] = r0; bhv[2 * nq][1] = r1;
                bhv[2 * nq + 1][0] = r2; bhv[2 * nq + 1][1] = r3;
                addr += TILE_B;
                ldmatrix_x4(r0, r1, r2, r3, addr);
                blv[2 * nq][0] = r0; blv[2 * nq][1] = r1;
                blv[2 * nq + 1][0] = r2; blv[2 * nq + 1][1] = r3;
            }
#pragma unroll
            for (int mi = 0; mi < 2; mi++)
#pragma unroll
                for (int ni = 0; ni < 8; ni++) {
                    mma_bf16(acc[mi][ni], ah[mi], bhv[ni]);
                    mma_bf16(acc[mi][ni], ah[mi], blv[ni]);
                    mma_bf16(acc[mi][ni], al[mi], bhv[ni]);
                }
        }
        __syncthreads();
    }
}

// ---- batched QKV projection: z=0 Q(+rope), z=1 K(+rope), z=2 V ----
__global__ void __launch_bounds__(256, 2)
mma_gemm_qkv(const __nv_bfloat16* __restrict__ aqh, const __nv_bfloat16* __restrict__ aql,
             const __nv_bfloat16* __restrict__ akh, const __nv_bfloat16* __restrict__ akl,
             const __nv_bfloat16* __restrict__ avh, const __nv_bfloat16* __restrict__ avl,
             const __nv_bfloat16* __restrict__ wqh, const __nv_bfloat16* __restrict__ wql,
             const __nv_bfloat16* __restrict__ wkh, const __nv_bfloat16* __restrict__ wkl,
             const __nv_bfloat16* __restrict__ wvh, const __nv_bfloat16* __restrict__ wvl,
             const float* __restrict__ bq, const float* __restrict__ bk,
             const float* __restrict__ bv,
             __nv_bfloat16* __restrict__ qh, __nv_bfloat16* __restrict__ ql,
             __nv_bfloat16* __restrict__ kh, __nv_bfloat16* __restrict__ kl,
             __nv_bfloat16* __restrict__ vh, __nv_bfloat16* __restrict__ vl)
{
    extern __shared__ char smem[];
    const uint32_t sb = smem_to_u32(smem);
    const int tid = threadIdx.x;
    const int z = blockIdx.z;
    const int m0 = blockIdx.y * 128;
    const int n0 = blockIdx.x * 128;

    const __nv_bfloat16* Ah = (z == 0) ? aqh : (z == 1) ? akh : avh;
    const __nv_bfloat16* Al = (z == 0) ? aql : (z == 1) ? akl : avl;
    const __nv_bfloat16* Wh = (z == 0) ? wqh : (z == 1) ? wkh : wvh;
    const __nv_bfloat16* Wl = (z == 0) ? wql : (z == 1) ? wkl : wvl;
    const float* bias = (z == 0) ? bq : (z == 1) ? bk : bv;
    __nv_bfloat16* outh = (z == 0) ? qh : (z == 1) ? kh : vh;
    __nv_bfloat16* outl = (z == 0) ? ql : (z == 1) ? kl : vl;
    const bool rope = (z != 2);

    float acc[2][8][4];
#pragma unroll
    for (int mi = 0; mi < 2; mi++)
#pragma unroll
        for (int ni = 0; ni < 8; ni++)
#pragma unroll
            for (int q = 0; q < 4; q++) acc[mi][ni][q] = 0.0f;

    gemm_core(Ah, Al, Wh, Wl, sb, m0, n0, tid, acc);

    const int wid  = tid >> 5;
    const int lane = tid & 31;
    const int wm = (wid & 3) * 32;
    const int wn = (wid >> 2) * 64;
    const int cbase = n0 + wn + (lane & 3) * 2;
#pragma unroll
    for (int ni = 0; ni < 8; ni++) {
        const int c = cbase + ni * 8;
        const float b0 = bias[c], b1 = bias[c + 1];
        float freq = 0.0f;
        if (rope) {
            int d = c & (HD - 1);
            freq = powf(10000.0f, -(float)d / (float)HD);
        }
        const int h    = c >> 6;
        const int dcol = c & (HD - 1);
#pragma unroll
        for (int mi = 0; mi < 2; mi++) {
#pragma unroll
            for (int rg = 0; rg < 2; rg++) {
                int m = m0 + wm + mi * 16 + (lane >> 2) + rg * 8;
                float v0 = acc[mi][ni][2 * rg] + b0;
                float v1 = acc[mi][ni][2 * rg + 1] + b1;
                int l  = m >> 1;
                int bb = m & 1;
                if (rope) {
                    float sv, cv;
                    sincosf((float)l * freq, &sv, &cv);
                    float x1 = v0, x2 = v1;
                    v0 = x1 * cv - x2 * sv;
                    v1 = x1 * sv + x2 * cv;
                }
                size_t idx = (((size_t)bb * H_DIM + h) * L_DIM + l) * HD + dcol;
                *(uint32_t*)(outh + idx) = packbf2(v0, v1);
                *(uint32_t*)(outl + idx) = packres2(v0, v1);
            }
        }
    }
}

// ---- output projection: fp32 out[m*E+n] ----
__global__ void __launch_bounds__(256, 2)
mma_gemm_o(const __nv_bfloat16* __restrict__ Ah, const __nv_bfloat16* __restrict__ Al,
           const __nv_bfloat16* __restrict__ Wh, const __nv_bfloat16* __restrict__ Wl,
           const float* __restrict__ bias, float* __restrict__ outf)
{
    extern __shared__ char smem[];
    const uint32_t sb = smem_to_u32(smem);
    const int tid = threadIdx.x;
    const int m0 = blockIdx.y * 128;
    const int n0 = blockIdx.x * 128;

    float acc[2][8][4];
#pragma unroll
    for (int mi = 0; mi < 2; mi++)
#pragma unroll
        for (int ni = 0; ni < 8; ni++)
#pragma unroll
            for (int q = 0; q < 4; q++) acc[mi][ni][q] = 0.0f;

    gemm_core(Ah, Al, Wh, Wl, sb, m0, n0, tid, acc);

    const int wid  = tid >> 5;
    const int lane = tid & 31;
    const int wm = (wid & 3) * 32;
    const int wn = (wid >> 2) * 64;
    const int cbase = n0 + wn + (lane & 3) * 2;
#pragma unroll
    for (int ni = 0; ni < 8; ni++) {
        const int c = cbase + ni * 8;
        const float b0 = bias[c], b1 = bias[c + 1];
#pragma unroll
        for (int mi = 0; mi < 2; mi++) {
#pragma unroll
            for (int rg = 0; rg < 2; rg++) {
                int m = m0 + wm + mi * 16 + (lane >> 2) + rg * 8;
                float2 r = {acc[mi][ni][2 * rg] + b0, acc[mi][ni][2 * rg + 1] + b1};
                *(float2*)(outf + (size_t)m * E_DIM + c) = r;
            }
        }
    }
}

// ==================== flash attention on mma.sync (3-pass) ====================
#define FA_ROWB   144
#define FA_QTILE  (128 * FA_ROWB)
#define FA_KVTILE (64 * FA_ROWB)
#define FA_STAGE  (4 * FA_KVTILE)
#define FA_SMEM   (2 * FA_QTILE + 2 * FA_STAGE)   // 110592
#define FA_NC     (S_DIM / 64)

__global__ void __launch_bounds__(256, 2)
flash_attn_mma(const __nv_bfloat16* __restrict__ Qh_g, const __nv_bfloat16* __restrict__ Ql_g,
               const __nv_bfloat16* __restrict__ Kh_g, const __nv_bfloat16* __restrict__ Kl_g,
               const __nv_bfloat16* __restrict__ Vh_g, const __nv_bfloat16* __restrict__ Vl_g,
               const unsigned char* __restrict__ mask,
               __nv_bfloat16* __restrict__ Oh_g, __nv_bfloat16* __restrict__ Ol_g)
{
    extern __shared__ char smem[];
    const uint32_t sb = smem_to_u32(smem);
    const int tid = threadIdx.x, lane = tid & 31, wid = tid >> 5;
    const int bh = blockIdx.y, b = bh >> 4, h = bh & 15;
    const int l0 = blockIdx.x * 128;
    const int wm = wid * 16;

    const size_t goff = (size_t)bh * L_DIM * HD;

    const __nv_bfloat16* qsrc[2] = {Qh_g + goff, Ql_g + goff};
#pragma unroll
    for (int it = 0; it < 8; it++) {
        int idx = it * 256 + tid;
        int tile = idx >> 10, i = idx & 1023, row = i >> 3, ch = i & 7;
        cp_async16(sb + tile * FA_QTILE + row * FA_ROWB + ch * 16,
                   qsrc[tile] + (size_t)(l0 + row) * HD + ch * 8);
    }

    const __nv_bfloat16* kvsrc[4] = {Kh_g + goff, Kl_g + goff, Vh_g + goff, Vl_g + goff};
    const uint32_t kvbase = sb + 2 * FA_QTILE;
    auto prefetch_kv = [&](int c, int buf) {
        int s0 = c * 64;
#pragma unroll
        for (int it = 0; it < 8; it++) {
            int idx = it * 256 + tid;
            int tile = idx >> 9, i = idx & 511, row = i >> 3, ch = i & 7;
            cp_async16(kvbase + buf * FA_STAGE + tile * FA_KVTILE + row * FA_ROWB + ch * 16,
                       kvsrc[tile] + (size_t)(s0 + row) * HD + ch * 8);
        }
        CP_COMMIT();
    };
    prefetch_kv(0, 0);

    float o_acc[8][4];
#pragma unroll
    for (int ni = 0; ni < 8; ni++)
#pragma unroll
        for (int q = 0; q < 4; q++) o_acc[ni][q] = 0.0f;
    float mi0 = -CUDART_INF_F, mi1 = -CUDART_INF_F, li0 = 0.0f, li1 = 0.0f;

    const int arow = lane & 15, akh = (lane >> 4) * 8;
    const int bg = lane >> 3, br = lane & 7;
    const int brow_off = (bg >> 1) * 8 + br;
    const int bk_off   = (bg & 1) * 8;
    const int trow_off = ((lane >> 3) & 1) * 8 + (lane & 7);
    const int tcol_off = (lane >> 4) * 8;
    const float scale = 0.125f;

    for (int c = 0; c < FA_NC; c++) {
        const int buf = c & 1;
        if (c + 1 < FA_NC) { prefetch_kv(c + 1, buf ^ 1); CP_WAIT(1); }
        else               { CP_WAIT(0); }
        __syncthreads();

        const uint32_t sK = kvbase + buf * FA_STAGE;
        const uint32_t sV = sK + 2 * FA_KVTILE;

        float s[8][4];
#pragma unroll
        for (int ni = 0; ni < 8; ni++)
#pragma unroll
            for (int q = 0; q < 4; q++) s[ni][q] = 0.0f;

#pragma unroll
        for (int ks = 0; ks < 4; ks++) {
            const int kb = ks * 16;
            uint32_t qh[4], ql[4];
            uint32_t qaddr = sb + (wm + arow) * FA_ROWB + (kb + akh) * 2;
            ldmatrix_x4(qh[0], qh[1], qh[2], qh[3], qaddr);
            ldmatrix_x4(ql[0], ql[1], ql[2], ql[3], qaddr + FA_QTILE);
#pragma unroll
            for (int nq = 0; nq < 4; nq++) {
                uint32_t kaddr = sK + (nq * 16 + brow_off) * FA_ROWB + (kb + bk_off) * 2;
                uint32_t k0, k1, k2, k3, e0, e1, e2, e3;
                ldmatrix_x4(k0, k1, k2, k3, kaddr);
                ldmatrix_x4(e0, e1, e2, e3, kaddr + FA_KVTILE);
                uint32_t kh0[2] = {k0, k1}, kh1[2] = {k2, k3};
                uint32_t kl0[2] = {e0, e1}, kl1[2] = {e2, e3};
                mma_bf16(s[2 * nq],     qh, kh0);
                mma_bf16(s[2 * nq],     qh, kl0);
                mma_bf16(s[2 * nq],     ql, kh0);
                mma_bf16(s[2 * nq + 1], qh, kh1);
                mma_bf16(s[2 * nq + 1], qh, kl1);
                mma_bf16(s[2 * nq + 1], ql, kh1);
            }
        }

        const int s0c = c * 64;
        float mlo = -CUDART_INF_F, mhi = -CUDART_INF_F;
#pragma unroll
        for (int ni = 0; ni < 8; ni++) {
            uchar2 mk = *(const uchar2*)(mask + (size_t)b * S_DIM + s0c + ni * 8 + (lane & 3) * 2);
            float v0 = mk.x ? -CUDART_INF_F : s[ni][0] * scale;
            float v1 = mk.y ? -CUDART_INF_F : s[ni][1] * scale;
            float v2 = mk.x ? -CUDART_INF_F : s[ni][2] * scale;
            float v3 = mk.y ? -CUDART_INF_F : s[ni][3] * scale;
            s[ni][0] = v0; s[ni][1] = v1; s[ni][2] = v2; s[ni][3] = v3;
            mlo = fmaxf(mlo, fmaxf(v0, v1));
            mhi = fmaxf(mhi, fmaxf(v2, v3));
        }
        mlo = fmaxf(mlo, __shfl_xor_sync(0xffffffffu, mlo, 1));
        mlo = fmaxf(mlo, __shfl_xor_sync(0xffffffffu, mlo, 2));
        mhi = fmaxf(mhi, __shfl_xor_sync(0xffffffffu, mhi, 1));
        mhi = fmaxf(mhi, __shfl_xor_sync(0xffffffffu, mhi, 2));

        float mn0 = fmaxf(mi0, mlo), mn1 = fmaxf(mi1, mhi);
        float a0 = __expf(mi0 - mn0), a1 = __expf(mi1 - mn1);
        float ps0 = 0.0f, ps1 = 0.0f;
#pragma unroll
        for (int ni = 0; ni < 8; ni++) {
            float p0 = __expf(s[ni][0] - mn0);
            float p1 = __expf(s[ni][1] - mn0);
            float p2 = __expf(s[ni][2] - mn1);
            float p3 = __expf(s[ni][3] - mn1);
            s[ni][0] = p0; s[ni][1] = p1; s[ni][2] = p2; s[ni][3] = p3;
            ps0 += p0 + p1;
            ps1 += p2 + p3;
        }
        ps0 += __shfl_xor_sync(0xffffffffu, ps0, 1);
        ps0 += __shfl_xor_sync(0xffffffffu, ps0, 2);
        ps1 += __shfl_xor_sync(0xffffffffu, ps1, 1);
        ps1 += __shfl_xor_sync(0xffffffffu, ps1, 2);
        li0 = li0 * a0 + ps0;
        li1 = li1 * a1 + ps1;
        mi0 = mn0; mi1 = mn1;
#pragma unroll
        for (int ni = 0; ni < 8; ni++) {
            o_acc[ni][0] *= a0; o_acc[ni][1] *= a0;
            o_acc[ni][2] *= a1; o_acc[ni][3] *= a1;
        }

#pragma unroll
        for (int ks = 0; ks < 4; ks++) {
            uint32_t pah[4], pal[4];
            pah[0] = packbf2(s[2 * ks][0],     s[2 * ks][1]);
            pah[1] = packbf2(s[2 * ks][2],     s[2 * ks][3]);
            pah[2] = packbf2(s[2 * ks + 1][0], s[2 * ks + 1][1]);
            pah[3] = packbf2(s[2 * ks + 1][2], s[2 * ks + 1][3]);
            pal[0] = packres2(s[2 * ks][0],     s[2 * ks][1]);
            pal[1] = packres2(s[2 * ks][2],     s[2 * ks][3]);
            pal[2] = packres2(s[2 * ks + 1][0], s[2 * ks + 1][1]);
            pal[3] = packres2(s[2 * ks + 1][2], s[2 * ks + 1][3]);
#pragma unroll
            for (int nb = 0; nb < 4; nb++) {
                uint32_t vaddr = sV + (ks * 16 + trow_off) * FA_ROWB + (nb * 16 + tcol_off) * 2;
                uint32_t v0, v1, v2, v3, w0, w1, w2, w3;
                ldmatrix_x4_trans(v0, v1, v2, v3, vaddr);
                ldmatrix_x4_trans(w0, w1, w2, w3, vaddr + FA_KVTILE);
                uint32_t vh0[2] = {v0, v1}, vh1[2] = {v2, v3};
                uint32_t vl0[2] = {w0, w1}, vl1[2] = {w2, w3};
                mma_bf16(o_acc[2 * nb],     pah, vh0);
                mma_bf16(o_acc[2 * nb],     pah, vl0);
                mma_bf16(o_acc[2 * nb],     pal, vh0);
                mma_bf16(o_acc[2 * nb + 1], pah, vh1);
                mma_bf16(o_acc[2 * nb + 1], pah, vl1);
                mma_bf16(o_acc[2 * nb + 1], pal, vh1);
            }
        }
        __syncthreads();
    }

    const float inv0 = 1.0f / li0, inv1 = 1.0f / li1;
    const int r0 = lane >> 2;
    const int m0g = ((l0 + wm + r0) << 1) | b;
    const int m1g = ((l0 + wm + r0 + 8) << 1) | b;
#pragma unroll
    for (int ni = 0; ni < 8; ni++) {
        int cg = h * HD + ni * 8 + (lane & 3) * 2;
        float v00 = o_acc[ni][0] * inv0, v01 = o_acc[ni][1] * inv0;
        float v10 = o_acc[ni][2] * inv1, v11 = o_acc[ni][3] * inv1;
        *(uint32_t*)(Oh_g + (size_t)m0g * E_DIM + cg) = packbf2(v00, v01);
        *(uint32_t*)(Ol_g + (size_t)m0g * E_DIM + cg) = packres2(v00, v01);
        *(uint32_t*)(Oh_g + (size_t)m1g * E_DIM + cg) = packbf2(v10, v11);
        *(uint32_t*)(Ol_g + (size_t)m1g * E_DIM + cg) = packres2(v10, v11);
    }
}

// ============================================================================
// launch
// ============================================================================
extern "C" void kernel_launch(void* const* d_in, const int* in_sizes, int n_in,
                              void* d_out, int out_size)
{
    const float* query = (const float*)d_in[0];
    const float* key   = (const float*)d_in[1];
    const float* value = (const float*)d_in[2];
    const unsigned char* mask = (const unsigned char*)d_in[3];
    const float* Wq = (const float*)d_in[4];
    const float* bq = (const float*)d_in[5];
    const float* Wk = (const float*)d_in[6];
    const float* bk = (const float*)d_in[7];
    const float* Wv = (const float*)d_in[8];
    const float* bv = (const float*)d_in[9];
    const float* Wo = (const float*)d_in[10];
    const float* bo = (const float*)d_in[11];
    float* out = (float*)d_out;

    __nv_bfloat16 *aqh, *aql, *akh, *akl, *avh, *avl;
    __nv_bfloat16 *wqh, *wql, *wkh, *wkl, *wvh, *wvl, *woh, *wol;
    __nv_bfloat16 *qh, *ql, *kh, *kl, *vh, *vl;
    cudaGetSymbolAddress((void**)&aqh, g_aq_h); cudaGetSymbolAddress((void**)&aql, g_aq_l);
    cudaGetSymbolAddress((void**)&akh, g_ak_h); cudaGetSymbolAddress((void**)&akl, g_ak_l);
    cudaGetSymbolAddress((void**)&avh, g_av_h); cudaGetSymbolAddress((void**)&avl, g_av_l);
    cudaGetSymbolAddress((void**)&wqh, g_wq_h); cudaGetSymbolAddress((void**)&wql, g_wq_l);
    cudaGetSymbolAddress((void**)&wkh, g_wk_h); cudaGetSymbolAddress((void**)&wkl, g_wk_l);
    cudaGetSymbolAddress((void**)&wvh, g_wv_h); cudaGetSymbolAddress((void**)&wvl, g_wv_l);
    cudaGetSymbolAddress((void**)&woh, g_wo_h); cudaGetSymbolAddress((void**)&wol, g_wo_l);
    cudaGetSymbolAddress((void**)&qh, g_Qh); cudaGetSymbolAddress((void**)&ql, g_Ql);
    cudaGetSymbolAddress((void**)&kh, g_Kh); cudaGetSymbolAddress((void**)&kl, g_Kl);
    cudaGetSymbolAddress((void**)&vh, g_Vh); cudaGetSymbolAddress((void**)&vl, g_Vl);

    cudaFuncSetAttribute(mma_gemm_qkv, cudaFuncAttributeMaxDynamicSharedMemorySize, GEMM_SMEM);
    cudaFuncSetAttribute(mma_gemm_o,   cudaFuncAttributeMaxDynamicSharedMemorySize, GEMM_SMEM);
    cudaFuncSetAttribute(flash_attn_mma, cudaFuncAttributeMaxDynamicSharedMemorySize, FA_SMEM);

    const int ACT4 = M_ROWS * E_DIM / 4;
    const int W4   = E_DIM * E_DIM / 4;

    // splits (activations + all 4 weights)
    split_bf16<<<ACT4 / 256, 256>>>(query, aqh, aql, ACT4);
    split_bf16<<<ACT4 / 256, 256>>>(key,   akh, akl, ACT4);
    split_bf16<<<ACT4 / 256, 256>>>(value, avh, avl, ACT4);
    split_bf16<<<W4 / 256, 256>>>(Wq, wqh, wql, W4);
    split_bf16<<<W4 / 256, 256>>>(Wk, wkh, wkl, W4);
    split_bf16<<<W4 / 256, 256>>>(Wv, wvh, wvl, W4);
    split_bf16<<<W4 / 256, 256>>>(Wo, woh, wol, W4);

    // batched QKV projections (+RoPE on Q,K)
    dim3 qkv_grid(E_DIM / 128, M_ROWS / 128, 3);   // (8, 32, 3)
    mma_gemm_qkv<<<qkv_grid, 256, GEMM_SMEM>>>(
        aqh, aql, akh, akl, avh, avl,
        wqh, wql, wkh, wkl, wvh, wvl,
        bq, bk, bv, qh, ql, kh, kl, vh, vl);

    // attention -> act hi/lo [m][E] (reuse g_aq buffers)
    dim3 agrid(L_DIM / 128, B_DIM * H_DIM);        // (16, 32)
    flash_attn_mma<<<agrid, 256, FA_SMEM>>>(qh, ql, kh, kl, vh, vl, mask, aqh, aql);

    // output projection -> d_out fp32
    dim3 ogrid(E_DIM / 128, M_ROWS / 128);
    mma_gemm_o<<<ogrid, 256, GEMM_SMEM>>>(aqh, aql, woh, wol, bo, out);
}

// round 7
// speedup vs baseline: 2.8562x; 1.0098x over previous
#include <cuda_runtime.h>
#include <cuda_bf16.h>
#include <math.h>
#include <math_constants.h>
#include <cstdint>

#define L_DIM 2048
#define S_DIM 2048
#define B_DIM 2
#define E_DIM 1024
#define H_DIM 16
#define HD    64
#define M_ROWS (L_DIM * B_DIM)   // 4096

// ============================ helpers ============================
__device__ __forceinline__ uint32_t smem_to_u32(const void* p) {
    uint32_t a;
    asm("{ .reg .u64 t; cvta.to.shared.u64 t, %1; cvt.u32.u64 %0, t; }" : "=r"(a) : "l"(p));
    return a;
}
__device__ __forceinline__ void cp_async16(uint32_t dst, const void* src) {
    asm volatile("cp.async.cg.shared.global [%0], [%1], 16;" :: "r"(dst), "l"(src));
}
#define CP_COMMIT() asm volatile("cp.async.commit_group;" ::: "memory")
#define CP_WAIT(n)  asm volatile("cp.async.wait_group %0;" :: "n"(n) : "memory")

__device__ __forceinline__ void ldmatrix_x4(uint32_t& r0, uint32_t& r1,
                                            uint32_t& r2, uint32_t& r3, uint32_t addr) {
    asm volatile("ldmatrix.sync.aligned.m8n8.x4.shared.b16 {%0,%1,%2,%3}, [%4];"
                 : "=r"(r0), "=r"(r1), "=r"(r2), "=r"(r3) : "r"(addr));
}
__device__ __forceinline__ void ldmatrix_x4_trans(uint32_t& r0, uint32_t& r1,
                                                  uint32_t& r2, uint32_t& r3, uint32_t addr) {
    asm volatile("ldmatrix.sync.aligned.m8n8.x4.trans.shared.b16 {%0,%1,%2,%3}, [%4];"
                 : "=r"(r0), "=r"(r1), "=r"(r2), "=r"(r3) : "r"(addr));
}
__device__ __forceinline__ void mma_bf16(float* d, const uint32_t* a, const uint32_t* b) {
    asm volatile(
        "mma.sync.aligned.m16n8k16.row.col.f32.bf16.bf16.f32 "
        "{%0,%1,%2,%3}, {%4,%5,%6,%7}, {%8,%9}, {%0,%1,%2,%3};"
        : "+f"(d[0]), "+f"(d[1]), "+f"(d[2]), "+f"(d[3])
        : "r"(a[0]), "r"(a[1]), "r"(a[2]), "r"(a[3]), "r"(b[0]), "r"(b[1]));
}
__device__ __forceinline__ uint32_t packbf2(float lo, float hi) {
    __nv_bfloat16 a = __float2bfloat16(lo), b = __float2bfloat16(hi);
    return ((uint32_t)__bfloat16_as_ushort(b) << 16) | (uint32_t)__bfloat16_as_ushort(a);
}
__device__ __forceinline__ uint32_t packres2(float lo, float hi) {
    float rl = lo - __bfloat162float(__float2bfloat16(lo));
    float rh = hi - __bfloat162float(__float2bfloat16(hi));
    return packbf2(rl, rh);
}

// ============================ scratch ============================
#define ACT_SZ ((size_t)M_ROWS * E_DIM)
#define W_SZ   ((size_t)E_DIM * E_DIM)
__device__ __nv_bfloat16 g_aq_h[ACT_SZ], g_aq_l[ACT_SZ];
__device__ __nv_bfloat16 g_ak_h[ACT_SZ], g_ak_l[ACT_SZ];
__device__ __nv_bfloat16 g_av_h[ACT_SZ], g_av_l[ACT_SZ];
__device__ __nv_bfloat16 g_wq_h[W_SZ], g_wq_l[W_SZ];
__device__ __nv_bfloat16 g_wk_h[W_SZ], g_wk_l[W_SZ];
__device__ __nv_bfloat16 g_wv_h[W_SZ], g_wv_l[W_SZ];
__device__ __nv_bfloat16 g_wo_h[W_SZ], g_wo_l[W_SZ];
#define BHTD ((size_t)B_DIM * H_DIM * L_DIM * HD)
__device__ __nv_bfloat16 g_Qh[BHTD], g_Ql[BHTD];
__device__ __nv_bfloat16 g_Kh[BHTD], g_Kl[BHTD];
__device__ __nv_bfloat16 g_Vh[BHTD], g_Vl[BHTD];

// ==================== fused fp32 -> bf16 hi/lo split (7 jobs, 1 launch) ====
// grid = (1024, 7); jobs 0-2: activations (4 reps), 3-6: weights (1 rep)
__global__ void __launch_bounds__(256)
split_all(const float* __restrict__ q,  const float* __restrict__ k,
          const float* __restrict__ v,  const float* __restrict__ wq,
          const float* __restrict__ wk, const float* __restrict__ wv,
          const float* __restrict__ wo,
          __nv_bfloat16* aqh, __nv_bfloat16* aql,
          __nv_bfloat16* akh, __nv_bfloat16* akl,
          __nv_bfloat16* avh, __nv_bfloat16* avl,
          __nv_bfloat16* wqh, __nv_bfloat16* wql,
          __nv_bfloat16* wkh, __nv_bfloat16* wkl,
          __nv_bfloat16* wvh, __nv_bfloat16* wvl,
          __nv_bfloat16* woh, __nv_bfloat16* wol)
{
    const int j = blockIdx.y;
    const float* src = (j == 0) ? q : (j == 1) ? k : (j == 2) ? v
                     : (j == 3) ? wq : (j == 4) ? wk : (j == 5) ? wv : wo;
    __nv_bfloat16* hi = (j == 0) ? aqh : (j == 1) ? akh : (j == 2) ? avh
                      : (j == 3) ? wqh : (j == 4) ? wkh : (j == 5) ? wvh : woh;
    __nv_bfloat16* lo = (j == 0) ? aql : (j == 1) ? akl : (j == 2) ? avl
                      : (j == 3) ? wql : (j == 4) ? wkl : (j == 5) ? wvl : wol;
    const int reps = (j < 3) ? 4 : 1;

    for (int r = 0; r < reps; r++) {
        int i = (r * 1024 + blockIdx.x) * 256 + threadIdx.x;
        float4 vv = ((const float4*)src)[i];
        float f[4] = {vv.x, vv.y, vv.z, vv.w};
        ushort h[4], l[4];
#pragma unroll
        for (int t = 0; t < 4; t++) {
            __nv_bfloat16 hb = __float2bfloat16(f[t]);
            __nv_bfloat16 lb = __float2bfloat16(f[t] - __bfloat162float(hb));
            h[t] = __bfloat16_as_ushort(hb);
            l[t] = __bfloat16_as_ushort(lb);
        }
        uint2 uh = {(uint32_t)h[0] | ((uint32_t)h[1] << 16),
                    (uint32_t)h[2] | ((uint32_t)h[3] << 16)};
        uint2 ul = {(uint32_t)l[0] | ((uint32_t)l[1] << 16),
                    (uint32_t)l[2] | ((uint32_t)l[3] << 16)};
        ((uint2*)hi)[i] = uh;
        ((uint2*)lo)[i] = ul;
    }
}

// ==================== GEMM core (BK=32, 2 CTA/SM) ====================
#define BK        32
#define ROW_PADB  40
#define TILE_B    (128 * ROW_PADB * 2)
#define STAGE_B   (4 * TILE_B)
#define GEMM_SMEM (2 * STAGE_B)               // 81920
#define NCHUNK    (E_DIM / BK)                // 32

__device__ __forceinline__ void gemm_core(
    const __nv_bfloat16* __restrict__ Ah, const __nv_bfloat16* __restrict__ Al,
    const __nv_bfloat16* __restrict__ Wh, const __nv_bfloat16* __restrict__ Wl,
    uint32_t sb, int m0, int n0, int tid, float acc[2][8][4])
{
    const int wid  = tid >> 5;
    const int lane = tid & 31;
    const int wm = (wid & 3) * 32;
    const int wn = (wid >> 2) * 64;

    const __nv_bfloat16* gsrc[4] = {Ah, Al, Wh, Wl};

    auto prefetch = [&](int c, int buf) {
        const int k0 = c * BK;
#pragma unroll
        for (int it = 0; it < 8; it++) {
            int idx  = it * 256 + tid;
            int tile = idx >> 9;
            int i    = idx & 511;
            int row  = i >> 2;
            int ch   = i & 3;
            int grow = (tile < 2 ? m0 : n0) + row;
            const __nv_bfloat16* gp = gsrc[tile] + (size_t)grow * E_DIM + k0 + ch * 8;
            uint32_t dst = sb + buf * STAGE_B + tile * TILE_B + row * (ROW_PADB * 2) + ch * 16;
            cp_async16(dst, gp);
        }
        CP_COMMIT();
    };

    prefetch(0, 0);

    const int arow = lane & 15;
    const int akh  = (lane >> 4) * 8;
    const int bg = lane >> 3;
    const int br = lane & 7;

    for (int c = 0; c < NCHUNK; c++) {
        const int buf = c & 1;
        if (c + 1 < NCHUNK) { prefetch(c + 1, buf ^ 1); CP_WAIT(1); }
        else                { CP_WAIT(0); }
        __syncthreads();

        const uint32_t st = sb + buf * STAGE_B;
#pragma unroll
        for (int ks = 0; ks < 2; ks++) {
            const int kb = ks * 16;
            uint32_t ah[2][4], al[2][4];
#pragma unroll
            for (int mi = 0; mi < 2; mi++) {
                uint32_t addr = st +
                    (wm + mi * 16 + arow) * (ROW_PADB * 2) + (kb + akh) * 2;
                ldmatrix_x4(ah[mi][0], ah[mi][1], ah[mi][2], ah[mi][3], addr);
                addr += TILE_B;
                ldmatrix_x4(al[mi][0], al[mi][1], al[mi][2], al[mi][3], addr);
            }
            uint32_t bhv[8][2], blv[8][2];
#pragma unroll
            for (int nq = 0; nq < 4; nq++) {
                uint32_t addr = st + 2 * TILE_B +
                    (wn + nq * 16 + (bg >> 1) * 8 + br) * (ROW_PADB * 2) + (kb + (bg & 1) * 8) * 2;
                uint32_t r0, r1, r2, r3;
                ldmatrix_x4(r0, r1, r2, r3, addr);
                bhv[2 * nq][0] = r0; bhv[2 * nq][1] = r1;
                bhv[2 * nq + 1][0] = r2; bhv[2 * nq + 1][1] = r3;
                addr += TILE_B;
                ldmatrix_x4(r0, r1, r2, r3, addr);
                blv[2 * nq][0] = r0; blv[2 * nq][1] = r1;
                blv[2 * nq + 1][0] = r2; blv[2 * nq + 1][1] = r3;
            }
#pragma unroll
            for (int mi = 0; mi < 2; mi++)
#pragma unroll
                for (int ni = 0; ni < 8; ni++) {
                    mma_bf16(acc[mi][ni], ah[mi], bhv[ni]);
                    mma_bf16(acc[mi][ni], ah[mi], blv[ni]);
                    mma_bf16(acc[mi][ni], al[mi], bhv[ni]);
                }
        }
        __syncthreads();
    }
}

// ---- batched QKV projection: z=0 Q(+rope), z=1 K(+rope), z=2 V ----
__global__ void __launch_bounds__(256, 2)
mma_gemm_qkv(const __nv_bfloat16* __restrict__ aqh, const __nv_bfloat16* __restrict__ aql,
             const __nv_bfloat16* __restrict__ akh, const __nv_bfloat16* __restrict__ akl,
             const __nv_bfloat16* __restrict__ avh, const __nv_bfloat16* __restrict__ avl,
             const __nv_bfloat16* __restrict__ wqh, const __nv_bfloat16* __restrict__ wql,
             const __nv_bfloat16* __restrict__ wkh, const __nv_bfloat16* __restrict__ wkl,
             const __nv_bfloat16* __restrict__ wvh, const __nv_bfloat16* __restrict__ wvl,
             const float* __restrict__ bq, const float* __restrict__ bk,
             const float* __restrict__ bv,
             __nv_bfloat16* __restrict__ qh, __nv_bfloat16* __restrict__ ql,
             __nv_bfloat16* __restrict__ kh, __nv_bfloat16* __restrict__ kl,
             __nv_bfloat16* __restrict__ vh, __nv_bfloat16* __restrict__ vl)
{
    extern __shared__ char smem[];
    const uint32_t sb = smem_to_u32(smem);
    const int tid = threadIdx.x;
    const int z = blockIdx.z;
    const int m0 = blockIdx.y * 128;
    const int n0 = blockIdx.x * 128;

    const __nv_bfloat16* Ah = (z == 0) ? aqh : (z == 1) ? akh : avh;
    const __nv_bfloat16* Al = (z == 0) ? aql : (z == 1) ? akl : avl;
    const __nv_bfloat16* Wh = (z == 0) ? wqh : (z == 1) ? wkh : wvh;
    const __nv_bfloat16* Wl = (z == 0) ? wql : (z == 1) ? wkl : wvl;
    const float* bias = (z == 0) ? bq : (z == 1) ? bk : bv;
    __nv_bfloat16* outh = (z == 0) ? qh : (z == 1) ? kh : vh;
    __nv_bfloat16* outl = (z == 0) ? ql : (z == 1) ? kl : vl;
    const bool rope = (z != 2);

    float acc[2][8][4];
#pragma unroll
    for (int mi = 0; mi < 2; mi++)
#pragma unroll
        for (int ni = 0; ni < 8; ni++)
#pragma unroll
            for (int q = 0; q < 4; q++) acc[mi][ni][q] = 0.0f;

    gemm_core(Ah, Al, Wh, Wl, sb, m0, n0, tid, acc);

    const int wid  = tid >> 5;
    const int lane = tid & 31;
    const int wm = (wid & 3) * 32;
    const int wn = (wid >> 2) * 64;
    const int cbase = n0 + wn + (lane & 3) * 2;
#pragma unroll
    for (int ni = 0; ni < 8; ni++) {
        const int c = cbase + ni * 8;
        const float b0 = bias[c], b1 = bias[c + 1];
        float freq = 0.0f;
        if (rope) {
            int d = c & (HD - 1);
            freq = powf(10000.0f, -(float)d / (float)HD);
        }
        const int h    = c >> 6;
        const int dcol = c & (HD - 1);
#pragma unroll
        for (int mi = 0; mi < 2; mi++) {
#pragma unroll
            for (int rg = 0; rg < 2; rg++) {
                int m = m0 + wm + mi * 16 + (lane >> 2) + rg * 8;
                float v0 = acc[mi][ni][2 * rg] + b0;
                float v1 = acc[mi][ni][2 * rg + 1] + b1;
                int l  = m >> 1;
                int bb = m & 1;
                if (rope) {
                    float sv, cv;
                    sincosf((float)l * freq, &sv, &cv);
                    float x1 = v0, x2 = v1;
                    v0 = x1 * cv - x2 * sv;
                    v1 = x1 * sv + x2 * cv;
                }
                size_t idx = (((size_t)bb * H_DIM + h) * L_DIM + l) * HD + dcol;
                *(uint32_t*)(outh + idx) = packbf2(v0, v1);
                *(uint32_t*)(outl + idx) = packres2(v0, v1);
            }
        }
    }
}

// ---- output projection: fp32 out[m*E+n] ----
__global__ void __launch_bounds__(256, 2)
mma_gemm_o(const __nv_bfloat16* __restrict__ Ah, const __nv_bfloat16* __restrict__ Al,
           const __nv_bfloat16* __restrict__ Wh, const __nv_bfloat16* __restrict__ Wl,
           const float* __restrict__ bias, float* __restrict__ outf)
{
    extern __shared__ char smem[];
    const uint32_t sb = smem_to_u32(smem);
    const int tid = threadIdx.x;
    const int m0 = blockIdx.y * 128;
    const int n0 = blockIdx.x * 128;

    float acc[2][8][4];
#pragma unroll
    for (int mi = 0; mi < 2; mi++)
#pragma unroll
        for (int ni = 0; ni < 8; ni++)
#pragma unroll
            for (int q = 0; q < 4; q++) acc[mi][ni][q] = 0.0f;

    gemm_core(Ah, Al, Wh, Wl, sb, m0, n0, tid, acc);

    const int wid  = tid >> 5;
    const int lane = tid & 31;
    const int wm = (wid & 3) * 32;
    const int wn = (wid >> 2) * 64;
    const int cbase = n0 + wn + (lane & 3) * 2;
#pragma unroll
    for (int ni = 0; ni < 8; ni++) {
        const int c = cbase + ni * 8;
        const float b0 = bias[c], b1 = bias[c + 1];
#pragma unroll
        for (int mi = 0; mi < 2; mi++) {
#pragma unroll
            for (int rg = 0; rg < 2; rg++) {
                int m = m0 + wm + mi * 16 + (lane >> 2) + rg * 8;
                float2 r = {acc[mi][ni][2 * rg] + b0, acc[mi][ni][2 * rg + 1] + b1};
                *(float2*)(outf + (size_t)m * E_DIM + c) = r;
            }
        }
    }
}

// ==================== flash attention on mma.sync (3-pass) ====================
#define FA_ROWB   144
#define FA_QTILE  (128 * FA_ROWB)
#define FA_KVTILE (64 * FA_ROWB)
#define FA_STAGE  (4 * FA_KVTILE)
#define FA_SMEM   (2 * FA_QTILE + 2 * FA_STAGE)   // 110592
#define FA_NC     (S_DIM / 64)

__global__ void __launch_bounds__(256, 2)
flash_attn_mma(const __nv_bfloat16* __restrict__ Qh_g, const __nv_bfloat16* __restrict__ Ql_g,
               const __nv_bfloat16* __restrict__ Kh_g, const __nv_bfloat16* __restrict__ Kl_g,
               const __nv_bfloat16* __restrict__ Vh_g, const __nv_bfloat16* __restrict__ Vl_g,
               const unsigned char* __restrict__ mask,
               __nv_bfloat16* __restrict__ Oh_g, __nv_bfloat16* __restrict__ Ol_g)
{
    extern __shared__ char smem[];
    const uint32_t sb = smem_to_u32(smem);
    const int tid = threadIdx.x, lane = tid & 31, wid = tid >> 5;
    const int bh = blockIdx.y, b = bh >> 4, h = bh & 15;
    const int l0 = blockIdx.x * 128;
    const int wm = wid * 16;

    const size_t goff = (size_t)bh * L_DIM * HD;

    const __nv_bfloat16* qsrc[2] = {Qh_g + goff, Ql_g + goff};
#pragma unroll
    for (int it = 0; it < 8; it++) {
        int idx = it * 256 + tid;
        int tile = idx >> 10, i = idx & 1023, row = i >> 3, ch = i & 7;
        cp_async16(sb + tile * FA_QTILE + row * FA_ROWB + ch * 16,
                   qsrc[tile] + (size_t)(l0 + row) * HD + ch * 8);
    }

    const __nv_bfloat16* kvsrc[4] = {Kh_g + goff, Kl_g + goff, Vh_g + goff, Vl_g + goff};
    const uint32_t kvbase = sb + 2 * FA_QTILE;
    auto prefetch_kv = [&](int c, int buf) {
        int s0 = c * 64;
#pragma unroll
        for (int it = 0; it < 8; it++) {
            int idx = it * 256 + tid;
            int tile = idx >> 9, i = idx & 511, row = i >> 3, ch = i & 7;
            cp_async16(kvbase + buf * FA_STAGE + tile * FA_KVTILE + row * FA_ROWB + ch * 16,
                       kvsrc[tile] + (size_t)(s0 + row) * HD + ch * 8);
        }
        CP_COMMIT();
    };
    prefetch_kv(0, 0);

    float o_acc[8][4];
#pragma unroll
    for (int ni = 0; ni < 8; ni++)
#pragma unroll
        for (int q = 0; q < 4; q++) o_acc[ni][q] = 0.0f;
    float mi0 = -CUDART_INF_F, mi1 = -CUDART_INF_F, li0 = 0.0f, li1 = 0.0f;

    const int arow = lane & 15, akh = (lane >> 4) * 8;
    const int bg = lane >> 3, br = lane & 7;
    const int brow_off = (bg >> 1) * 8 + br;
    const int bk_off   = (bg & 1) * 8;
    const int trow_off = ((lane >> 3) & 1) * 8 + (lane & 7);
    const int tcol_off = (lane >> 4) * 8;
    // exp2-domain scale: 1/sqrt(64) * 1/ln(2)
    const float scale2 = 0.125f * 1.4426950408889634f;

    // Q fragments hoisted across the whole S loop (loaded once at c==0)
    uint32_t qfh[4][4], qfl[4][4];

    for (int c = 0; c < FA_NC; c++) {
        const int buf = c & 1;
        if (c + 1 < FA_NC) { prefetch_kv(c + 1, buf ^ 1); CP_WAIT(1); }
        else               { CP_WAIT(0); }
        __syncthreads();

        if (c == 0) {
#pragma unroll
            for (int ks = 0; ks < 4; ks++) {
                uint32_t qaddr = sb + (wm + arow) * FA_ROWB + (ks * 16 + akh) * 2;
                ldmatrix_x4(qfh[ks][0], qfh[ks][1], qfh[ks][2], qfh[ks][3], qaddr);
                ldmatrix_x4(qfl[ks][0], qfl[ks][1], qfl[ks][2], qfl[ks][3], qaddr + FA_QTILE);
            }
        }

        // prefetch mask bytes early (independent of smem)
        const int s0c = c * 64;
        uchar2 mk[8];
#pragma unroll
        for (int ni = 0; ni < 8; ni++)
            mk[ni] = *(const uchar2*)(mask + (size_t)b * S_DIM + s0c + ni * 8 + (lane & 3) * 2);

        const uint32_t sK = kvbase + buf * FA_STAGE;
        const uint32_t sV = sK + 2 * FA_KVTILE;

        float s[8][4];
#pragma unroll
        for (int ni = 0; ni < 8; ni++)
#pragma unroll
            for (int q = 0; q < 4; q++) s[ni][q] = 0.0f;

#pragma unroll
        for (int ks = 0; ks < 4; ks++) {
            const int kb = ks * 16;
#pragma unroll
            for (int nq = 0; nq < 4; nq++) {
                uint32_t kaddr = sK + (nq * 16 + brow_off) * FA_ROWB + (kb + bk_off) * 2;
                uint32_t k0, k1, k2, k3, e0, e1, e2, e3;
                ldmatrix_x4(k0, k1, k2, k3, kaddr);
                ldmatrix_x4(e0, e1, e2, e3, kaddr + FA_KVTILE);
                uint32_t kh0[2] = {k0, k1}, kh1[2] = {k2, k3};
                uint32_t kl0[2] = {e0, e1}, kl1[2] = {e2, e3};
                mma_bf16(s[2 * nq],     qfh[ks], kh0);
                mma_bf16(s[2 * nq],     qfh[ks], kl0);
                mma_bf16(s[2 * nq],     qfl[ks], kh0);
                mma_bf16(s[2 * nq + 1], qfh[ks], kh1);
                mma_bf16(s[2 * nq + 1], qfh[ks], kl1);
                mma_bf16(s[2 * nq + 1], qfl[ks], kh1);
            }
        }

        float mlo = -CUDART_INF_F, mhi = -CUDART_INF_F;
#pragma unroll
        for (int ni = 0; ni < 8; ni++) {
            float v0 = mk[ni].x ? -CUDART_INF_F : s[ni][0] * scale2;
            float v1 = mk[ni].y ? -CUDART_INF_F : s[ni][1] * scale2;
            float v2 = mk[ni].x ? -CUDART_INF_F : s[ni][2] * scale2;
            float v3 = mk[ni].y ? -CUDART_INF_F : s[ni][3] * scale2;
            s[ni][0] = v0; s[ni][1] = v1; s[ni][2] = v2; s[ni][3] = v3;
            mlo = fmaxf(mlo, fmaxf(v0, v1));
            mhi = fmaxf(mhi, fmaxf(v2, v3));
        }
        mlo = fmaxf(mlo, __shfl_xor_sync(0xffffffffu, mlo, 1));
        mlo = fmaxf(mlo, __shfl_xor_sync(0xffffffffu, mlo, 2));
        mhi = fmaxf(mhi, __shfl_xor_sync(0xffffffffu, mhi, 1));
        mhi = fmaxf(mhi, __shfl_xor_sync(0xffffffffu, mhi, 2));

        float mn0 = fmaxf(mi0, mlo), mn1 = fmaxf(mi1, mhi);
        float a0 = exp2f(mi0 - mn0), a1 = exp2f(mi1 - mn1);
        float ps0 = 0.0f, ps1 = 0.0f;
#pragma unroll
        for (int ni = 0; ni < 8; ni++) {
            float p0 = exp2f(s[ni][0] - mn0);
            float p1 = exp2f(s[ni][1] - mn0);
            float p2 = exp2f(s[ni][2] - mn1);
            float p3 = exp2f(s[ni][3] - mn1);
            s[ni][0] = p0; s[ni][1] = p1; s[ni][2] = p2; s[ni][3] = p3;
            ps0 += p0 + p1;
            ps1 += p2 + p3;
        }
        ps0 += __shfl_xor_sync(0xffffffffu, ps0, 1);
        ps0 += __shfl_xor_sync(0xffffffffu, ps0, 2);
        ps1 += __shfl_xor_sync(0xffffffffu, ps1, 1);
        ps1 += __shfl_xor_sync(0xffffffffu, ps1, 2);
        li0 = li0 * a0 + ps0;
        li1 = li1 * a1 + ps1;
        mi0 = mn0; mi1 = mn1;
#pragma unroll
        for (int ni = 0; ni < 8; ni++) {
            o_acc[ni][0] *= a0; o_acc[ni][1] *= a0;
            o_acc[ni][2] *= a1; o_acc[ni][3] *= a1;
        }

#pragma unroll
        for (int ks = 0; ks < 4; ks++) {
            uint32_t pah[4], pal[4];
            pah[0] = packbf2(s[2 * ks][0],     s[2 * ks][1]);
            pah[1] = packbf2(s[2 * ks][2],     s[2 * ks][3]);
            pah[2] = packbf2(s[2 * ks + 1][0], s[2 * ks + 1][1]);
            pah[3] = packbf2(s[2 * ks + 1][2], s[2 * ks + 1][3]);
            pal[0] = packres2(s[2 * ks][0],     s[2 * ks][1]);
            pal[1] = packres2(s[2 * ks][2],     s[2 * ks][3]);
            pal[2] = packres2(s[2 * ks + 1][0], s[2 * ks + 1][1]);
            pal[3] = packres2(s[2 * ks + 1][2], s[2 * ks + 1][3]);
#pragma unroll
            for (int nb = 0; nb < 4; nb++) {
                uint32_t vaddr = sV + (ks * 16 + trow_off) * FA_ROWB + (nb * 16 + tcol_off) * 2;
                uint32_t v0, v1, v2, v3, w0, w1, w2, w3;
                ldmatrix_x4_trans(v0, v1, v2, v3, vaddr);
                ldmatrix_x4_trans(w0, w1, w2, w3, vaddr + FA_KVTILE);
                uint32_t vh0[2] = {v0, v1}, vh1[2] = {v2, v3};
                uint32_t vl0[2] = {w0, w1}, vl1[2] = {w2, w3};
                mma_bf16(o_acc[2 * nb],     pah, vh0);
                mma_bf16(o_acc[2 * nb],     pah, vl0);
                mma_bf16(o_acc[2 * nb],     pal, vh0);
                mma_bf16(o_acc[2 * nb + 1], pah, vh1);
                mma_bf16(o_acc[2 * nb + 1], pah, vl1);
                mma_bf16(o_acc[2 * nb + 1], pal, vh1);
            }
        }
        __syncthreads();
    }

    const float inv0 = 1.0f / li0, inv1 = 1.0f / li1;
    const int r0 = lane >> 2;
    const int m0g = ((l0 + wm + r0) << 1) | b;
    const int m1g = ((l0 + wm + r0 + 8) << 1) | b;
#pragma unroll
    for (int ni = 0; ni < 8; ni++) {
        int cg = h * HD + ni * 8 + (lane & 3) * 2;
        float v00 = o_acc[ni][0] * inv0, v01 = o_acc[ni][1] * inv0;
        float v10 = o_acc[ni][2] * inv1, v11 = o_acc[ni][3] * inv1;
        *(uint32_t*)(Oh_g + (size_t)m0g * E_DIM + cg) = packbf2(v00, v01);
        *(uint32_t*)(Ol_g + (size_t)m0g * E_DIM + cg) = packres2(v00, v01);
        *(uint32_t*)(Oh_g + (size_t)m1g * E_DIM + cg) = packbf2(v10, v11);
        *(uint32_t*)(Ol_g + (size_t)m1g * E_DIM + cg) = packres2(v10, v11);
    }
}

// ============================================================================
// launch
// ============================================================================
extern "C" void kernel_launch(void* const* d_in, const int* in_sizes, int n_in,
                              void* d_out, int out_size)
{
    const float* query = (const float*)d_in[0];
    const float* key   = (const float*)d_in[1];
    const float* value = (const float*)d_in[2];
    const unsigned char* mask = (const unsigned char*)d_in[3];
    const float* Wq = (const float*)d_in[4];
    const float* bq = (const float*)d_in[5];
    const float* Wk = (const float*)d_in[6];
    const float* bk = (const float*)d_in[7];
    const float* Wv = (const float*)d_in[8];
    const float* bv = (const float*)d_in[9];
    const float* Wo = (const float*)d_in[10];
    const float* bo = (const float*)d_in[11];
    float* out = (float*)d_out;

    __nv_bfloat16 *aqh, *aql, *akh, *akl, *avh, *avl;
    __nv_bfloat16 *wqh, *wql, *wkh, *wkl, *wvh, *wvl, *woh, *wol;
    __nv_bfloat16 *qh, *ql, *kh, *kl, *vh, *vl;
    cudaGetSymbolAddress((void**)&aqh, g_aq_h); cudaGetSymbolAddress((void**)&aql, g_aq_l);
    cudaGetSymbolAddress((void**)&akh, g_ak_h); cudaGetSymbolAddress((void**)&akl, g_ak_l);
    cudaGetSymbolAddress((void**)&avh, g_av_h); cudaGetSymbolAddress((void**)&avl, g_av_l);
    cudaGetSymbolAddress((void**)&wqh, g_wq_h); cudaGetSymbolAddress((void**)&wql, g_wq_l);
    cudaGetSymbolAddress((void**)&wkh, g_wk_h); cudaGetSymbolAddress((void**)&wkl, g_wk_l);
    cudaGetSymbolAddress((void**)&wvh, g_wv_h); cudaGetSymbolAddress((void**)&wvl, g_wv_l);
    cudaGetSymbolAddress((void**)&woh, g_wo_h); cudaGetSymbolAddress((void**)&wol, g_wo_l);
    cudaGetSymbolAddress((void**)&qh, g_Qh); cudaGetSymbolAddress((void**)&ql, g_Ql);
    cudaGetSymbolAddress((void**)&kh, g_Kh); cudaGetSymbolAddress((void**)&kl, g_Kl);
    cudaGetSymbolAddress((void**)&vh, g_Vh); cudaGetSymbolAddress((void**)&vl, g_Vl);

    cudaFuncSetAttribute(mma_gemm_qkv, cudaFuncAttributeMaxDynamicSharedMemorySize, GEMM_SMEM);
    cudaFuncSetAttribute(mma_gemm_o,   cudaFuncAttributeMaxDynamicSharedMemorySize, GEMM_SMEM);
    cudaFuncSetAttribute(flash_attn_mma, cudaFuncAttributeMaxDynamicSharedMemorySize, FA_SMEM);

    // one fused split launch for all 3 activations + 4 weights
    dim3 sgrid(1024, 7);
    split_all<<<sgrid, 256>>>(query, key, value, Wq, Wk, Wv, Wo,
                              aqh, aql, akh, akl, avh, avl,
                              wqh, wql, wkh, wkl, wvh, wvl, woh, wol);

    // batched QKV projections (+RoPE on Q,K)
    dim3 qkv_grid(E_DIM / 128, M_ROWS / 128, 3);   // (8, 32, 3)
    mma_gemm_qkv<<<qkv_grid, 256, GEMM_SMEM>>>(
        aqh, aql, akh, akl, avh, avl,
        wqh, wql, wkh, wkl, wvh, wvl,
        bq, bk, bv, qh, ql, kh, kl, vh, vl);

    // attention -> act hi/lo [m][E] (reuse g_aq buffers)
    dim3 agrid(L_DIM / 128, B_DIM * H_DIM);        // (16, 32)
    flash_attn_mma<<<agrid, 256, FA_SMEM>>>(qh, ql, kh, kl, vh, vl, mask, aqh, aql);

    // output projection -> d_out fp32
    dim3 ogrid(E_DIM / 128, M_ROWS / 128);
    mma_gemm_o<<<ogrid, 256, GEMM_SMEM>>>(aqh, aql, woh, wol, bo, out);
}

// round 8
// speedup vs baseline: 2.8697x; 1.0047x over previous
#include <cuda_runtime.h>
#include <cuda_bf16.h>
#include <math.h>
#include <math_constants.h>
#include <cstdint>

#define L_DIM 2048
#define S_DIM 2048
#define B_DIM 2
#define E_DIM 1024
#define H_DIM 16
#define HD    64
#define M_ROWS (L_DIM * B_DIM)   // 4096

// ============================ helpers ============================
__device__ __forceinline__ uint32_t smem_to_u32(const void* p) {
    uint32_t a;
    asm("{ .reg .u64 t; cvta.to.shared.u64 t, %1; cvt.u32.u64 %0, t; }" : "=r"(a) : "l"(p));
    return a;
}
__device__ __forceinline__ void cp_async16(uint32_t dst, const void* src) {
    asm volatile("cp.async.cg.shared.global [%0], [%1], 16;" :: "r"(dst), "l"(src));
}
#define CP_COMMIT() asm volatile("cp.async.commit_group;" ::: "memory")
#define CP_WAIT(n)  asm volatile("cp.async.wait_group %0;" :: "n"(n) : "memory")

__device__ __forceinline__ void ldmatrix_x4(uint32_t& r0, uint32_t& r1,
                                            uint32_t& r2, uint32_t& r3, uint32_t addr) {
    asm volatile("ldmatrix.sync.aligned.m8n8.x4.shared.b16 {%0,%1,%2,%3}, [%4];"
                 : "=r"(r0), "=r"(r1), "=r"(r2), "=r"(r3) : "r"(addr));
}
__device__ __forceinline__ void ldmatrix_x4_trans(uint32_t& r0, uint32_t& r1,
                                                  uint32_t& r2, uint32_t& r3, uint32_t addr) {
    asm volatile("ldmatrix.sync.aligned.m8n8.x4.trans.shared.b16 {%0,%1,%2,%3}, [%4];"
                 : "=r"(r0), "=r"(r1), "=r"(r2), "=r"(r3) : "r"(addr));
}
__device__ __forceinline__ void mma_bf16(float* d, const uint32_t* a, const uint32_t* b) {
    asm volatile(
        "mma.sync.aligned.m16n8k16.row.col.f32.bf16.bf16.f32 "
        "{%0,%1,%2,%3}, {%4,%5,%6,%7}, {%8,%9}, {%0,%1,%2,%3};"
        : "+f"(d[0]), "+f"(d[1]), "+f"(d[2]), "+f"(d[3])
        : "r"(a[0]), "r"(a[1]), "r"(a[2]), "r"(a[3]), "r"(b[0]), "r"(b[1]));
}
__device__ __forceinline__ uint32_t packbf2(float lo, float hi) {
    __nv_bfloat16 a = __float2bfloat16(lo), b = __float2bfloat16(hi);
    return ((uint32_t)__bfloat16_as_ushort(b) << 16) | (uint32_t)__bfloat16_as_ushort(a);
}
__device__ __forceinline__ uint32_t packres2(float lo, float hi) {
    float rl = lo - __bfloat162float(__float2bfloat16(lo));
    float rh = hi - __bfloat162float(__float2bfloat16(hi));
    return packbf2(rl, rh);
}

// ============================ scratch ============================
#define ACT_SZ ((size_t)M_ROWS * E_DIM)
#define W_SZ   ((size_t)E_DIM * E_DIM)
__device__ __nv_bfloat16 g_aq_h[ACT_SZ], g_aq_l[ACT_SZ];
__device__ __nv_bfloat16 g_ak_h[ACT_SZ], g_ak_l[ACT_SZ];
__device__ __nv_bfloat16 g_av_h[ACT_SZ], g_av_l[ACT_SZ];
__device__ __nv_bfloat16 g_wq_h[W_SZ], g_wq_l[W_SZ];
__device__ __nv_bfloat16 g_wk_h[W_SZ], g_wk_l[W_SZ];
__device__ __nv_bfloat16 g_wv_h[W_SZ], g_wv_l[W_SZ];
__device__ __nv_bfloat16 g_wo_h[W_SZ], g_wo_l[W_SZ];
#define BHTD ((size_t)B_DIM * H_DIM * L_DIM * HD)
__device__ __nv_bfloat16 g_Qh[BHTD], g_Ql[BHTD];
__device__ __nv_bfloat16 g_Kh[BHTD], g_Kl[BHTD];
__device__ __nv_bfloat16 g_Vh[BHTD], g_Vl[BHTD];

// ==================== fused fp32 -> bf16 hi/lo split (7 jobs, 1 launch) ====
__global__ void __launch_bounds__(256)
split_all(const float* __restrict__ q,  const float* __restrict__ k,
          const float* __restrict__ v,  const float* __restrict__ wq,
          const float* __restrict__ wk, const float* __restrict__ wv,
          const float* __restrict__ wo,
          __nv_bfloat16* aqh, __nv_bfloat16* aql,
          __nv_bfloat16* akh, __nv_bfloat16* akl,
          __nv_bfloat16* avh, __nv_bfloat16* avl,
          __nv_bfloat16* wqh, __nv_bfloat16* wql,
          __nv_bfloat16* wkh, __nv_bfloat16* wkl,
          __nv_bfloat16* wvh, __nv_bfloat16* wvl,
          __nv_bfloat16* woh, __nv_bfloat16* wol)
{
    const int j = blockIdx.y;
    const float* src = (j == 0) ? q : (j == 1) ? k : (j == 2) ? v
                     : (j == 3) ? wq : (j == 4) ? wk : (j == 5) ? wv : wo;
    __nv_bfloat16* hi = (j == 0) ? aqh : (j == 1) ? akh : (j == 2) ? avh
                      : (j == 3) ? wqh : (j == 4) ? wkh : (j == 5) ? wvh : woh;
    __nv_bfloat16* lo = (j == 0) ? aql : (j == 1) ? akl : (j == 2) ? avl
                      : (j == 3) ? wql : (j == 4) ? wkl : (j == 5) ? wvl : wol;
    const int reps = (j < 3) ? 4 : 1;

    for (int r = 0; r < reps; r++) {
        int i = (r * 1024 + blockIdx.x) * 256 + threadIdx.x;
        float4 vv = ((const float4*)src)[i];
        float f[4] = {vv.x, vv.y, vv.z, vv.w};
        ushort h[4], l[4];
#pragma unroll
        for (int t = 0; t < 4; t++) {
            __nv_bfloat16 hb = __float2bfloat16(f[t]);
            __nv_bfloat16 lb = __float2bfloat16(f[t] - __bfloat162float(hb));
            h[t] = __bfloat16_as_ushort(hb);
            l[t] = __bfloat16_as_ushort(lb);
        }
        uint2 uh = {(uint32_t)h[0] | ((uint32_t)h[1] << 16),
                    (uint32_t)h[2] | ((uint32_t)h[3] << 16)};
        uint2 ul = {(uint32_t)l[0] | ((uint32_t)l[1] << 16),
                    (uint32_t)l[2] | ((uint32_t)l[3] << 16)};
        ((uint2*)hi)[i] = uh;
        ((uint2*)lo)[i] = ul;
    }
}

// ==================== GEMM core (BK=32, 2 CTA/SM) ====================
#define BK        32
#define ROW_PADB  40
#define TILE_B    (128 * ROW_PADB * 2)
#define STAGE_B   (4 * TILE_B)
#define GEMM_SMEM (2 * STAGE_B)               // 81920
#define NCHUNK    (E_DIM / BK)                // 32

__device__ __forceinline__ void gemm_core(
    const __nv_bfloat16* __restrict__ Ah, const __nv_bfloat16* __restrict__ Al,
    const __nv_bfloat16* __restrict__ Wh, const __nv_bfloat16* __restrict__ Wl,
    uint32_t sb, int m0, int n0, int tid, float acc[2][8][4])
{
    const int wid  = tid >> 5;
    const int lane = tid & 31;
    const int wm = (wid & 3) * 32;
    const int wn = (wid >> 2) * 64;

    const __nv_bfloat16* gsrc[4] = {Ah, Al, Wh, Wl};

    auto prefetch = [&](int c, int buf) {
        const int k0 = c * BK;
#pragma unroll
        for (int it = 0; it < 8; it++) {
            int idx  = it * 256 + tid;
            int tile = idx >> 9;
            int i    = idx & 511;
            int row  = i >> 2;
            int ch   = i & 3;
            int grow = (tile < 2 ? m0 : n0) + row;
            const __nv_bfloat16* gp = gsrc[tile] + (size_t)grow * E_DIM + k0 + ch * 8;
            uint32_t dst = sb + buf * STAGE_B + tile * TILE_B + row * (ROW_PADB * 2) + ch * 16;
            cp_async16(dst, gp);
        }
        CP_COMMIT();
    };

    prefetch(0, 0);

    const int arow = lane & 15;
    const int akh  = (lane >> 4) * 8;
    const int bg = lane >> 3;
    const int br = lane & 7;

    for (int c = 0; c < NCHUNK; c++) {
        const int buf = c & 1;
        if (c + 1 < NCHUNK) { prefetch(c + 1, buf ^ 1); CP_WAIT(1); }
        else                { CP_WAIT(0); }
        __syncthreads();

        const uint32_t st = sb + buf * STAGE_B;
#pragma unroll
        for (int ks = 0; ks < 2; ks++) {
            const int kb = ks * 16;
            uint32_t ah[2][4], al[2][4];
#pragma unroll
            for (int mi = 0; mi < 2; mi++) {
                uint32_t addr = st +
                    (wm + mi * 16 + arow) * (ROW_PADB * 2) + (kb + akh) * 2;
                ldmatrix_x4(ah[mi][0], ah[mi][1], ah[mi][2], ah[mi][3], addr);
                addr += TILE_B;
                ldmatrix_x4(al[mi][0], al[mi][1], al[mi][2], al[mi][3], addr);
            }
            uint32_t bhv[8][2], blv[8][2];
#pragma unroll
            for (int nq = 0; nq < 4; nq++) {
                uint32_t addr = st + 2 * TILE_B +
                    (wn + nq * 16 + (bg >> 1) * 8 + br) * (ROW_PADB * 2) + (kb + (bg & 1) * 8) * 2;
                uint32_t r0, r1, r2, r3;
                ldmatrix_x4(r0, r1, r2, r3, addr);
                bhv[2 * nq][0] = r0; bhv[2 * nq][1] = r1;
                bhv[2 * nq + 1][0] = r2; bhv[2 * nq + 1][1] = r3;
                addr += TILE_B;
                ldmatrix_x4(r0, r1, r2, r3, addr);
                blv[2 * nq][0] = r0; blv[2 * nq][1] = r1;
                blv[2 * nq + 1][0] = r2; blv[2 * nq + 1][1] = r3;
            }
            // pass-major emission: 16 independent accumulators between
            // successive writes to the same accumulator (was a 3-deep RAW chain)
#pragma unroll
            for (int mi = 0; mi < 2; mi++)
#pragma unroll
                for (int ni = 0; ni < 8; ni++)
                    mma_bf16(acc[mi][ni], ah[mi], bhv[ni]);   // pass 1: hi*hi
#pragma unroll
            for (int mi = 0; mi < 2; mi++)
#pragma unroll
                for (int ni = 0; ni < 8; ni++)
                    mma_bf16(acc[mi][ni], ah[mi], blv[ni]);   // pass 2: hi*lo
#pragma unroll
            for (int mi = 0; mi < 2; mi++)
#pragma unroll
                for (int ni = 0; ni < 8; ni++)
                    mma_bf16(acc[mi][ni], al[mi], bhv[ni]);   // pass 3: lo*hi
        }
        __syncthreads();
    }
}

// ---- batched QKV projection: z=0 Q(+rope), z=1 K(+rope), z=2 V ----
__global__ void __launch_bounds__(256, 2)
mma_gemm_qkv(const __nv_bfloat16* __restrict__ aqh, const __nv_bfloat16* __restrict__ aql,
             const __nv_bfloat16* __restrict__ akh, const __nv_bfloat16* __restrict__ akl,
             const __nv_bfloat16* __restrict__ avh, const __nv_bfloat16* __restrict__ avl,
             const __nv_bfloat16* __restrict__ wqh, const __nv_bfloat16* __restrict__ wql,
             const __nv_bfloat16* __restrict__ wkh, const __nv_bfloat16* __restrict__ wkl,
             const __nv_bfloat16* __restrict__ wvh, const __nv_bfloat16* __restrict__ wvl,
             const float* __restrict__ bq, const float* __restrict__ bk,
             const float* __restrict__ bv,
             __nv_bfloat16* __restrict__ qh, __nv_bfloat16* __restrict__ ql,
             __nv_bfloat16* __restrict__ kh, __nv_bfloat16* __restrict__ kl,
             __nv_bfloat16* __restrict__ vh, __nv_bfloat16* __restrict__ vl)
{
    extern __shared__ char smem[];
    const uint32_t sb = smem_to_u32(smem);
    const int tid = threadIdx.x;
    const int z = blockIdx.z;
    const int m0 = blockIdx.y * 128;
    const int n0 = blockIdx.x * 128;

    const __nv_bfloat16* Ah = (z == 0) ? aqh : (z == 1) ? akh : avh;
    const __nv_bfloat16* Al = (z == 0) ? aql : (z == 1) ? akl : avl;
    const __nv_bfloat16* Wh = (z == 0) ? wqh : (z == 1) ? wkh : wvh;
    const __nv_bfloat16* Wl = (z == 0) ? wql : (z == 1) ? wkl : wvl;
    const float* bias = (z == 0) ? bq : (z == 1) ? bk : bv;
    __nv_bfloat16* outh = (z == 0) ? qh : (z == 1) ? kh : vh;
    __nv_bfloat16* outl = (z == 0) ? ql : (z == 1) ? kl : vl;
    const bool rope = (z != 2);

    float acc[2][8][4];
#pragma unroll
    for (int mi = 0; mi < 2; mi++)
#pragma unroll
        for (int ni = 0; ni < 8; ni++)
#pragma unroll
            for (int q = 0; q < 4; q++) acc[mi][ni][q] = 0.0f;

    gemm_core(Ah, Al, Wh, Wl, sb, m0, n0, tid, acc);

    const int wid  = tid >> 5;
    const int lane = tid & 31;
    const int wm = (wid & 3) * 32;
    const int wn = (wid >> 2) * 64;
    const int cbase = n0 + wn + (lane & 3) * 2;
#pragma unroll
    for (int ni = 0; ni < 8; ni++) {
        const int c = cbase + ni * 8;
        const float b0 = bias[c], b1 = bias[c + 1];
        float freq = 0.0f;
        if (rope) {
            int d = c & (HD - 1);
            freq = powf(10000.0f, -(float)d / (float)HD);
        }
        const int h    = c >> 6;
        const int dcol = c & (HD - 1);
#pragma unroll
        for (int mi = 0; mi < 2; mi++) {
#pragma unroll
            for (int rg = 0; rg < 2; rg++) {
                int m = m0 + wm + mi * 16 + (lane >> 2) + rg * 8;
                float v0 = acc[mi][ni][2 * rg] + b0;
                float v1 = acc[mi][ni][2 * rg + 1] + b1;
                int l  = m >> 1;
                int bb = m & 1;
                if (rope) {
                    float sv, cv;
                    sincosf((float)l * freq, &sv, &cv);
                    float x1 = v0, x2 = v1;
                    v0 = x1 * cv - x2 * sv;
                    v1 = x1 * sv + x2 * cv;
                }
                size_t idx = (((size_t)bb * H_DIM + h) * L_DIM + l) * HD + dcol;
                *(uint32_t*)(outh + idx) = packbf2(v0, v1);
                *(uint32_t*)(outl + idx) = packres2(v0, v1);
            }
        }
    }
}

// ---- output projection: fp32 out[m*E+n] ----
__global__ void __launch_bounds__(256, 2)
mma_gemm_o(const __nv_bfloat16* __restrict__ Ah, const __nv_bfloat16* __restrict__ Al,
           const __nv_bfloat16* __restrict__ Wh, const __nv_bfloat16* __restrict__ Wl,
           const float* __restrict__ bias, float* __restrict__ outf)
{
    extern __shared__ char smem[];
    const uint32_t sb = smem_to_u32(smem);
    const int tid = threadIdx.x;
    const int m0 = blockIdx.y * 128;
    const int n0 = blockIdx.x * 128;

    float acc[2][8][4];
#pragma unroll
    for (int mi = 0; mi < 2; mi++)
#pragma unroll
        for (int ni = 0; ni < 8; ni++)
#pragma unroll
            for (int q = 0; q < 4; q++) acc[mi][ni][q] = 0.0f;

    gemm_core(Ah, Al, Wh, Wl, sb, m0, n0, tid, acc);

    const int wid  = tid >> 5;
    const int lane = tid & 31;
    const int wm = (wid & 3) * 32;
    const int wn = (wid >> 2) * 64;
    const int cbase = n0 + wn + (lane & 3) * 2;
#pragma unroll
    for (int ni = 0; ni < 8; ni++) {
        const int c = cbase + ni * 8;
        const float b0 = bias[c], b1 = bias[c + 1];
#pragma unroll
        for (int mi = 0; mi < 2; mi++) {
#pragma unroll
            for (int rg = 0; rg < 2; rg++) {
                int m = m0 + wm + mi * 16 + (lane >> 2) + rg * 8;
                float2 r = {acc[mi][ni][2 * rg] + b0, acc[mi][ni][2 * rg + 1] + b1};
                *(float2*)(outf + (size_t)m * E_DIM + c) = r;
            }
        }
    }
}

// ==================== flash attention on mma.sync (3-pass) ====================
#define FA_ROWB   144
#define FA_QTILE  (128 * FA_ROWB)
#define FA_KVTILE (64 * FA_ROWB)
#define FA_STAGE  (4 * FA_KVTILE)
#define FA_SMEM   (2 * FA_QTILE + 2 * FA_STAGE)   // 110592
#define FA_NC     (S_DIM / 64)

__global__ void __launch_bounds__(256, 2)
flash_attn_mma(const __nv_bfloat16* __restrict__ Qh_g, const __nv_bfloat16* __restrict__ Ql_g,
               const __nv_bfloat16* __restrict__ Kh_g, const __nv_bfloat16* __restrict__ Kl_g,
               const __nv_bfloat16* __restrict__ Vh_g, const __nv_bfloat16* __restrict__ Vl_g,
               const unsigned char* __restrict__ mask,
               __nv_bfloat16* __restrict__ Oh_g, __nv_bfloat16* __restrict__ Ol_g)
{
    extern __shared__ char smem[];
    const uint32_t sb = smem_to_u32(smem);
    const int tid = threadIdx.x, lane = tid & 31, wid = tid >> 5;
    const int bh = blockIdx.y, b = bh >> 4, h = bh & 15;
    const int l0 = blockIdx.x * 128;
    const int wm = wid * 16;

    const size_t goff = (size_t)bh * L_DIM * HD;

    const __nv_bfloat16* qsrc[2] = {Qh_g + goff, Ql_g + goff};
#pragma unroll
    for (int it = 0; it < 8; it++) {
        int idx = it * 256 + tid;
        int tile = idx >> 10, i = idx & 1023, row = i >> 3, ch = i & 7;
        cp_async16(sb + tile * FA_QTILE + row * FA_ROWB + ch * 16,
                   qsrc[tile] + (size_t)(l0 + row) * HD + ch * 8);
    }

    const __nv_bfloat16* kvsrc[4] = {Kh_g + goff, Kl_g + goff, Vh_g + goff, Vl_g + goff};
    const uint32_t kvbase = sb + 2 * FA_QTILE;
    auto prefetch_kv = [&](int c, int buf) {
        int s0 = c * 64;
#pragma unroll
        for (int it = 0; it < 8; it++) {
            int idx = it * 256 + tid;
            int tile = idx >> 9, i = idx & 511, row = i >> 3, ch = i & 7;
            cp_async16(kvbase + buf * FA_STAGE + tile * FA_KVTILE + row * FA_ROWB + ch * 16,
                       kvsrc[tile] + (size_t)(s0 + row) * HD + ch * 8);
        }
        CP_COMMIT();
    };
    prefetch_kv(0, 0);

    float o_acc[8][4];
#pragma unroll
    for (int ni = 0; ni < 8; ni++)
#pragma unroll
        for (int q = 0; q < 4; q++) o_acc[ni][q] = 0.0f;
    float mi0 = -CUDART_INF_F, mi1 = -CUDART_INF_F, li0 = 0.0f, li1 = 0.0f;

    const int arow = lane & 15, akh = (lane >> 4) * 8;
    const int bg = lane >> 3, br = lane & 7;
    const int brow_off = (bg >> 1) * 8 + br;
    const int bk_off   = (bg & 1) * 8;
    const int trow_off = ((lane >> 3) & 1) * 8 + (lane & 7);
    const int tcol_off = (lane >> 4) * 8;
    const float scale2 = 0.125f * 1.4426950408889634f;   // 1/sqrt(64) / ln2

    uint32_t qfh[4][4], qfl[4][4];

    for (int c = 0; c < FA_NC; c++) {
        const int buf = c & 1;

        // mask bytes: independent global load, issue before the async wait
        const int s0c = c * 64;
        uchar2 mk[8];
#pragma unroll
        for (int ni = 0; ni < 8; ni++)
            mk[ni] = *(const uchar2*)(mask + (size_t)b * S_DIM + s0c + ni * 8 + (lane & 3) * 2);

        if (c + 1 < FA_NC) { prefetch_kv(c + 1, buf ^ 1); CP_WAIT(1); }
        else               { CP_WAIT(0); }
        __syncthreads();

        if (c == 0) {
#pragma unroll
            for (int ks = 0; ks < 4; ks++) {
                uint32_t qaddr = sb + (wm + arow) * FA_ROWB + (ks * 16 + akh) * 2;
                ldmatrix_x4(qfh[ks][0], qfh[ks][1], qfh[ks][2], qfh[ks][3], qaddr);
                ldmatrix_x4(qfl[ks][0], qfl[ks][1], qfl[ks][2], qfl[ks][3], qaddr + FA_QTILE);
            }
        }

        const uint32_t sK = kvbase + buf * FA_STAGE;
        const uint32_t sV = sK + 2 * FA_KVTILE;

        float s[8][4];
#pragma unroll
        for (int ni = 0; ni < 8; ni++)
#pragma unroll
            for (int q = 0; q < 4; q++) s[ni][q] = 0.0f;

        // GEMM1: per (ks,nq) interleave the two accumulators across passes —
        // chain separation 2x, and per-acc pass order (hh,hl,lh) preserved.
#pragma unroll
        for (int ks = 0; ks < 4; ks++) {
            const int kb = ks * 16;
#pragma unroll
            for (int nq = 0; nq < 4; nq++) {
                uint32_t kaddr = sK + (nq * 16 + brow_off) * FA_ROWB + (kb + bk_off) * 2;
                uint32_t k0, k1, k2, k3, e0, e1, e2, e3;
                ldmatrix_x4(k0, k1, k2, k3, kaddr);
                ldmatrix_x4(e0, e1, e2, e3, kaddr + FA_KVTILE);
                uint32_t kh0[2] = {k0, k1}, kh1[2] = {k2, k3};
                uint32_t kl0[2] = {e0, e1}, kl1[2] = {e2, e3};
                mma_bf16(s[2 * nq],     qfh[ks], kh0);
                mma_bf16(s[2 * nq + 1], qfh[ks], kh1);
                mma_bf16(s[2 * nq],     qfh[ks], kl0);
                mma_bf16(s[2 * nq + 1], qfh[ks], kl1);
                mma_bf16(s[2 * nq],     qfl[ks], kh0);
                mma_bf16(s[2 * nq + 1], qfl[ks], kh1);
            }
        }

        float mlo = -CUDART_INF_F, mhi = -CUDART_INF_F;
#pragma unroll
        for (int ni = 0; ni < 8; ni++) {
            float v0 = mk[ni].x ? -CUDART_INF_F : s[ni][0] * scale2;
            float v1 = mk[ni].y ? -CUDART_INF_F : s[ni][1] * scale2;
            float v2 = mk[ni].x ? -CUDART_INF_F : s[ni][2] * scale2;
            float v3 = mk[ni].y ? -CUDART_INF_F : s[ni][3] * scale2;
            s[ni][0] = v0; s[ni][1] = v1; s[ni][2] = v2; s[ni][3] = v3;
            mlo = fmaxf(mlo, fmaxf(v0, v1));
            mhi = fmaxf(mhi, fmaxf(v2, v3));
        }
        mlo = fmaxf(mlo, __shfl_xor_sync(0xffffffffu, mlo, 1));
        mlo = fmaxf(mlo, __shfl_xor_sync(0xffffffffu, mlo, 2));
        mhi = fmaxf(mhi, __shfl_xor_sync(0xffffffffu, mhi, 1));
        mhi = fmaxf(mhi, __shfl_xor_sync(0xffffffffu, mhi, 2));

        float mn0 = fmaxf(mi0, mlo), mn1 = fmaxf(mi1, mhi);
        float a0 = exp2f(mi0 - mn0), a1 = exp2f(mi1 - mn1);
        float ps0 = 0.0f, ps1 = 0.0f;
#pragma unroll
        for (int ni = 0; ni < 8; ni++) {
            float p0 = exp2f(s[ni][0] - mn0);
            float p1 = exp2f(s[ni][1] - mn0);
            float p2 = exp2f(s[ni][2] - mn1);
            float p3 = exp2f(s[ni][3] - mn1);
            s[ni][0] = p0; s[ni][1] = p1; s[ni][2] = p2; s[ni][3] = p3;
            ps0 += p0 + p1;
            ps1 += p2 + p3;
        }
        ps0 += __shfl_xor_sync(0xffffffffu, ps0, 1);
        ps0 += __shfl_xor_sync(0xffffffffu, ps0, 2);
        ps1 += __shfl_xor_sync(0xffffffffu, ps1, 1);
        ps1 += __shfl_xor_sync(0xffffffffu, ps1, 2);
        li0 = li0 * a0 + ps0;
        li1 = li1 * a1 + ps1;
        mi0 = mn0; mi1 = mn1;
#pragma unroll
        for (int ni = 0; ni < 8; ni++) {
            o_acc[ni][0] *= a0; o_acc[ni][1] *= a0;
            o_acc[ni][2] *= a1; o_acc[ni][3] *= a1;
        }

        // GEMM2: interleave the two o accumulators across passes
#pragma unroll
        for (int ks = 0; ks < 4; ks++) {
            uint32_t pah[4], pal[4];
            pah[0] = packbf2(s[2 * ks][0],     s[2 * ks][1]);
            pah[1] = packbf2(s[2 * ks][2],     s[2 * ks][3]);
            pah[2] = packbf2(s[2 * ks + 1][0], s[2 * ks + 1][1]);
            pah[3] = packbf2(s[2 * ks + 1][2], s[2 * ks + 1][3]);
            pal[0] = packres2(s[2 * ks][0],     s[2 * ks][1]);
            pal[1] = packres2(s[2 * ks][2],     s[2 * ks][3]);
            pal[2] = packres2(s[2 * ks + 1][0], s[2 * ks + 1][1]);
            pal[3] = packres2(s[2 * ks + 1][2], s[2 * ks + 1][3]);
#pragma unroll
            for (int nb = 0; nb < 4; nb++) {
                uint32_t vaddr = sV + (ks * 16 + trow_off) * FA_ROWB + (nb * 16 + tcol_off) * 2;
                uint32_t v0, v1, v2, v3, w0, w1, w2, w3;
                ldmatrix_x4_trans(v0, v1, v2, v3, vaddr);
                ldmatrix_x4_trans(w0, w1, w2, w3, vaddr + FA_KVTILE);
                uint32_t vh0[2] = {v0, v1}, vh1[2] = {v2, v3};
                uint32_t vl0[2] = {w0, w1}, vl1[2] = {w2, w3};
                mma_bf16(o_acc[2 * nb],     pah, vh0);
                mma_bf16(o_acc[2 * nb + 1], pah, vh1);
                mma_bf16(o_acc[2 * nb],     pah, vl0);
                mma_bf16(o_acc[2 * nb + 1], pah, vl1);
                mma_bf16(o_acc[2 * nb],     pal, vh0);
                mma_bf16(o_acc[2 * nb + 1], pal, vh1);
            }
        }
        __syncthreads();
    }

    const float inv0 = 1.0f / li0, inv1 = 1.0f / li1;
    const int r0 = lane >> 2;
    const int m0g = ((l0 + wm + r0) << 1) | b;
    const int m1g = ((l0 + wm + r0 + 8) << 1) | b;
#pragma unroll
    for (int ni = 0; ni < 8; ni++) {
        int cg = h * HD + ni * 8 + (lane & 3) * 2;
        float v00 = o_acc[ni][0] * inv0, v01 = o_acc[ni][1] * inv0;
        float v10 = o_acc[ni][2] * inv1, v11 = o_acc[ni][3] * inv1;
        *(uint32_t*)(Oh_g + (size_t)m0g * E_DIM + cg) = packbf2(v00, v01);
        *(uint32_t*)(Ol_g + (size_t)m0g * E_DIM + cg) = packres2(v00, v01);
        *(uint32_t*)(Oh_g + (size_t)m1g * E_DIM + cg) = packbf2(v10, v11);
        *(uint32_t*)(Ol_g + (size_t)m1g * E_DIM + cg) = packres2(v10, v11);
    }
}

// ============================================================================
// launch
// ============================================================================
extern "C" void kernel_launch(void* const* d_in, const int* in_sizes, int n_in,
                              void* d_out, int out_size)
{
    const float* query = (const float*)d_in[0];
    const float* key   = (const float*)d_in[1];
    const float* value = (const float*)d_in[2];
    const unsigned char* mask = (const unsigned char*)d_in[3];
    const float* Wq = (const float*)d_in[4];
    const float* bq = (const float*)d_in[5];
    const float* Wk = (const float*)d_in[6];
    const float* bk = (const float*)d_in[7];
    const float* Wv = (const float*)d_in[8];
    const float* bv = (const float*)d_in[9];
    const float* Wo = (const float*)d_in[10];
    const float* bo = (const float*)d_in[11];
    float* out = (float*)d_out;

    __nv_bfloat16 *aqh, *aql, *akh, *akl, *avh, *avl;
    __nv_bfloat16 *wqh, *wql, *wkh, *wkl, *wvh, *wvl, *woh, *wol;
    __nv_bfloat16 *qh, *ql, *kh, *kl, *vh, *vl;
    cudaGetSymbolAddress((void**)&aqh, g_aq_h); cudaGetSymbolAddress((void**)&aql, g_aq_l);
    cudaGetSymbolAddress((void**)&akh, g_ak_h); cudaGetSymbolAddress((void**)&akl, g_ak_l);
    cudaGetSymbolAddress((void**)&avh, g_av_h); cudaGetSymbolAddress((void**)&avl, g_av_l);
    cudaGetSymbolAddress((void**)&wqh, g_wq_h); cudaGetSymbolAddress((void**)&wql, g_wq_l);
    cudaGetSymbolAddress((void**)&wkh, g_wk_h); cudaGetSymbolAddress((void**)&wkl, g_wk_l);
    cudaGetSymbolAddress((void**)&wvh, g_wv_h); cudaGetSymbolAddress((void**)&wvl, g_wv_l);
    cudaGetSymbolAddress((void**)&woh, g_wo_h); cudaGetSymbolAddress((void**)&wol, g_wo_l);
    cudaGetSymbolAddress((void**)&qh, g_Qh); cudaGetSymbolAddress((void**)&ql, g_Ql);
    cudaGetSymbolAddress((void**)&kh, g_Kh); cudaGetSymbolAddress((void**)&kl, g_Kl);
    cudaGetSymbolAddress((void**)&vh, g_Vh); cudaGetSymbolAddress((void**)&vl, g_Vl);

    cudaFuncSetAttribute(mma_gemm_qkv, cudaFuncAttributeMaxDynamicSharedMemorySize, GEMM_SMEM);
    cudaFuncSetAttribute(mma_gemm_o,   cudaFuncAttributeMaxDynamicSharedMemorySize, GEMM_SMEM);
    cudaFuncSetAttribute(flash_attn_mma, cudaFuncAttributeMaxDynamicSharedMemorySize, FA_SMEM);

    // one fused split launch for all 3 activations + 4 weights
    dim3 sgrid(1024, 7);
    split_all<<<sgrid, 256>>>(query, key, value, Wq, Wk, Wv, Wo,
                              aqh, aql, akh, akl, avh, avl,
                              wqh, wql, wkh, wkl, wvh, wvl, woh, wol);

    // batched QKV projections (+RoPE on Q,K)
    dim3 qkv_grid(E_DIM / 128, M_ROWS / 128, 3);   // (8, 32, 3)
    mma_gemm_qkv<<<qkv_grid, 256, GEMM_SMEM>>>(
        aqh, aql, akh, akl, avh, avl,
        wqh, wql, wkh, wkl, wvh, wvl,
        bq, bk, bv, qh, ql, kh, kl, vh, vl);

    // attention -> act hi/lo [m][E] (reuse g_aq buffers)
    dim3 agrid(L_DIM / 128, B_DIM * H_DIM);        // (16, 32)
    flash_attn_mma<<<agrid, 256, FA_SMEM>>>(qh, ql, kh, kl, vh, vl, mask, aqh, aql);

    // output projection -> d_out fp32
    dim3 ogrid(E_DIM / 128, M_ROWS / 128);
    mma_gemm_o<<<ogrid, 256, GEMM_SMEM>>>(aqh, aql, woh, wol, bo, out);
}

// round 9
// speedup vs baseline: 2.9192x; 1.0172x over previous
#include <cuda_runtime.h>
#include <cuda_bf16.h>
#include <math.h>
#include <math_constants.h>
#include <cstdint>

#define L_DIM 2048
#define S_DIM 2048
#define B_DIM 2
#define E_DIM 1024
#define H_DIM 16
#define HD    64
#define M_ROWS (L_DIM * B_DIM)   // 4096

// ============================ helpers ============================
__device__ __forceinline__ uint32_t smem_to_u32(const void* p) {
    uint32_t a;
    asm("{ .reg .u64 t; cvta.to.shared.u64 t, %1; cvt.u32.u64 %0, t; }" : "=r"(a) : "l"(p));
    return a;
}
__device__ __forceinline__ void cp_async16(uint32_t dst, const void* src) {
    asm volatile("cp.async.cg.shared.global [%0], [%1], 16;" :: "r"(dst), "l"(src));
}
#define CP_COMMIT() asm volatile("cp.async.commit_group;" ::: "memory")
#define CP_WAIT(n)  asm volatile("cp.async.wait_group %0;" :: "n"(n) : "memory")

__device__ __forceinline__ void ldmatrix_x4(uint32_t& r0, uint32_t& r1,
                                            uint32_t& r2, uint32_t& r3, uint32_t addr) {
    asm volatile("ldmatrix.sync.aligned.m8n8.x4.shared.b16 {%0,%1,%2,%3}, [%4];"
                 : "=r"(r0), "=r"(r1), "=r"(r2), "=r"(r3) : "r"(addr));
}
__device__ __forceinline__ void ldmatrix_x4_trans(uint32_t& r0, uint32_t& r1,
                                                  uint32_t& r2, uint32_t& r3, uint32_t addr) {
    asm volatile("ldmatrix.sync.aligned.m8n8.x4.trans.shared.b16 {%0,%1,%2,%3}, [%4];"
                 : "=r"(r0), "=r"(r1), "=r"(r2), "=r"(r3) : "r"(addr));
}
__device__ __forceinline__ void mma_bf16(float* d, const uint32_t* a, const uint32_t* b) {
    asm volatile(
        "mma.sync.aligned.m16n8k16.row.col.f32.bf16.bf16.f32 "
        "{%0,%1,%2,%3}, {%4,%5,%6,%7}, {%8,%9}, {%0,%1,%2,%3};"
        : "+f"(d[0]), "+f"(d[1]), "+f"(d[2]), "+f"(d[3])
        : "r"(a[0]), "r"(a[1]), "r"(a[2]), "r"(a[3]), "r"(b[0]), "r"(b[1]));
}
__device__ __forceinline__ uint32_t packbf2(float lo, float hi) {
    __nv_bfloat16 a = __float2bfloat16(lo), b = __float2bfloat16(hi);
    return ((uint32_t)__bfloat16_as_ushort(b) << 16) | (uint32_t)__bfloat16_as_ushort(a);
}
__device__ __forceinline__ uint32_t packres2(float lo, float hi) {
    float rl = lo - __bfloat162float(__float2bfloat16(lo));
    float rh = hi - __bfloat162float(__float2bfloat16(hi));
    return packbf2(rl, rh);
}

// ============================ scratch ============================
#define ACT_SZ ((size_t)M_ROWS * E_DIM)
#define W_SZ   ((size_t)E_DIM * E_DIM)
__device__ __nv_bfloat16 g_aq_h[ACT_SZ], g_aq_l[ACT_SZ];
__device__ __nv_bfloat16 g_ak_h[ACT_SZ], g_ak_l[ACT_SZ];
__device__ __nv_bfloat16 g_av_h[ACT_SZ], g_av_l[ACT_SZ];
__device__ __nv_bfloat16 g_wq_h[W_SZ], g_wq_l[W_SZ];
__device__ __nv_bfloat16 g_wk_h[W_SZ], g_wk_l[W_SZ];
__device__ __nv_bfloat16 g_wv_h[W_SZ], g_wv_l[W_SZ];
__device__ __nv_bfloat16 g_wo_h[W_SZ], g_wo_l[W_SZ];
#define BHTD ((size_t)B_DIM * H_DIM * L_DIM * HD)
__device__ __nv_bfloat16 g_Qh[BHTD], g_Ql[BHTD];
__device__ __nv_bfloat16 g_Kh[BHTD], g_Kl[BHTD];
__device__ __nv_bfloat16 g_Vh[BHTD], g_Vl[BHTD];

// ==================== fused fp32 -> bf16 hi/lo split (7 jobs, 1 launch) ====
__global__ void __launch_bounds__(256)
split_all(const float* __restrict__ q,  const float* __restrict__ k,
          const float* __restrict__ v,  const float* __restrict__ wq,
          const float* __restrict__ wk, const float* __restrict__ wv,
          const float* __restrict__ wo,
          __nv_bfloat16* aqh, __nv_bfloat16* aql,
          __nv_bfloat16* akh, __nv_bfloat16* akl,
          __nv_bfloat16* avh, __nv_bfloat16* avl,
          __nv_bfloat16* wqh, __nv_bfloat16* wql,
          __nv_bfloat16* wkh, __nv_bfloat16* wkl,
          __nv_bfloat16* wvh, __nv_bfloat16* wvl,
          __nv_bfloat16* woh, __nv_bfloat16* wol)
{
    const int j = blockIdx.y;
    const float* src = (j == 0) ? q : (j == 1) ? k : (j == 2) ? v
                     : (j == 3) ? wq : (j == 4) ? wk : (j == 5) ? wv : wo;
    __nv_bfloat16* hi = (j == 0) ? aqh : (j == 1) ? akh : (j == 2) ? avh
                      : (j == 3) ? wqh : (j == 4) ? wkh : (j == 5) ? wvh : woh;
    __nv_bfloat16* lo = (j == 0) ? aql : (j == 1) ? akl : (j == 2) ? avl
                      : (j == 3) ? wql : (j == 4) ? wkl : (j == 5) ? wvl : wol;
    const int reps = (j < 3) ? 4 : 1;

    for (int r = 0; r < reps; r++) {
        int i = (r * 1024 + blockIdx.x) * 256 + threadIdx.x;
        float4 vv = ((const float4*)src)[i];
        float f[4] = {vv.x, vv.y, vv.z, vv.w};
        ushort h[4], l[4];
#pragma unroll
        for (int t = 0; t < 4; t++) {
            __nv_bfloat16 hb = __float2bfloat16(f[t]);
            __nv_bfloat16 lb = __float2bfloat16(f[t] - __bfloat162float(hb));
            h[t] = __bfloat16_as_ushort(hb);
            l[t] = __bfloat16_as_ushort(lb);
        }
        uint2 uh = {(uint32_t)h[0] | ((uint32_t)h[1] << 16),
                    (uint32_t)h[2] | ((uint32_t)h[3] << 16)};
        uint2 ul = {(uint32_t)l[0] | ((uint32_t)l[1] << 16),
                    (uint32_t)l[2] | ((uint32_t)l[3] << 16)};
        ((uint2*)hi)[i] = uh;
        ((uint2*)lo)[i] = ul;
    }
}

// ==================== GEMM core (BK=32, 2 CTA/SM, 1 sync/chunk) ====================
#define BK        32
#define ROW_PADB  40
#define TILE_B    (128 * ROW_PADB * 2)
#define STAGE_B   (4 * TILE_B)
#define GEMM_SMEM (2 * STAGE_B)               // 81920
#define NCHUNK    (E_DIM / BK)                // 32

__device__ __forceinline__ void gemm_core(
    const __nv_bfloat16* __restrict__ Ah, const __nv_bfloat16* __restrict__ Al,
    const __nv_bfloat16* __restrict__ Wh, const __nv_bfloat16* __restrict__ Wl,
    uint32_t sb, int m0, int n0, int tid, float acc[2][8][4])
{
    const int wid  = tid >> 5;
    const int lane = tid & 31;
    const int wm = (wid & 3) * 32;
    const int wn = (wid >> 2) * 64;

    const __nv_bfloat16* gsrc[4] = {Ah, Al, Wh, Wl};

    auto prefetch = [&](int c, int buf) {
        const int k0 = c * BK;
#pragma unroll
        for (int it = 0; it < 8; it++) {
            int idx  = it * 256 + tid;
            int tile = idx >> 9;
            int i    = idx & 511;
            int row  = i >> 2;
            int ch   = i & 3;
            int grow = (tile < 2 ? m0 : n0) + row;
            const __nv_bfloat16* gp = gsrc[tile] + (size_t)grow * E_DIM + k0 + ch * 8;
            uint32_t dst = sb + buf * STAGE_B + tile * TILE_B + row * (ROW_PADB * 2) + ch * 16;
            cp_async16(dst, gp);
        }
        CP_COMMIT();
    };

    prefetch(0, 0);

    const int arow = lane & 15;
    const int akh  = (lane >> 4) * 8;
    const int bg = lane >> 3;
    const int br = lane & 7;

    for (int c = 0; c < NCHUNK; c++) {
        const int buf = c & 1;
        // single barrier per chunk: wait own async group, then barrier.
        // After this barrier every warp has finished reading buffer (c-1),
        // so prefetching chunk c+1 into buf^1 is safe.
        CP_WAIT(0);
        __syncthreads();
        if (c + 1 < NCHUNK) prefetch(c + 1, buf ^ 1);

        const uint32_t st = sb + buf * STAGE_B;
#pragma unroll
        for (int ks = 0; ks < 2; ks++) {
            const int kb = ks * 16;
            uint32_t ah[2][4], al[2][4];
#pragma unroll
            for (int mi = 0; mi < 2; mi++) {
                uint32_t addr = st +
                    (wm + mi * 16 + arow) * (ROW_PADB * 2) + (kb + akh) * 2;
                ldmatrix_x4(ah[mi][0], ah[mi][1], ah[mi][2], ah[mi][3], addr);
                addr += TILE_B;
                ldmatrix_x4(al[mi][0], al[mi][1], al[mi][2], al[mi][3], addr);
            }
            uint32_t bhv[8][2], blv[8][2];
#pragma unroll
            for (int nq = 0; nq < 4; nq++) {
                uint32_t addr = st + 2 * TILE_B +
                    (wn + nq * 16 + (bg >> 1) * 8 + br) * (ROW_PADB * 2) + (kb + (bg & 1) * 8) * 2;
                uint32_t r0, r1, r2, r3;
                ldmatrix_x4(r0, r1, r2, r3, addr);
                bhv[2 * nq][0] = r0; bhv[2 * nq][1] = r1;
                bhv[2 * nq + 1][0] = r2; bhv[2 * nq + 1][1] = r3;
                addr += TILE_B;
                ldmatrix_x4(r0, r1, r2, r3, addr);
                blv[2 * nq][0] = r0; blv[2 * nq][1] = r1;
                blv[2 * nq + 1][0] = r2; blv[2 * nq + 1][1] = r3;
            }
#pragma unroll
            for (int mi = 0; mi < 2; mi++)
#pragma unroll
                for (int ni = 0; ni < 8; ni++)
                    mma_bf16(acc[mi][ni], ah[mi], bhv[ni]);
#pragma unroll
            for (int mi = 0; mi < 2; mi++)
#pragma unroll
                for (int ni = 0; ni < 8; ni++)
                    mma_bf16(acc[mi][ni], ah[mi], blv[ni]);
#pragma unroll
            for (int mi = 0; mi < 2; mi++)
#pragma unroll
                for (int ni = 0; ni < 8; ni++)
                    mma_bf16(acc[mi][ni], al[mi], bhv[ni]);
        }
    }
}

// ---- batched QKV projection: z=0 Q(+rope), z=1 K(+rope), z=2 V ----
__global__ void __launch_bounds__(256, 2)
mma_gemm_qkv(const __nv_bfloat16* __restrict__ aqh, const __nv_bfloat16* __restrict__ aql,
             const __nv_bfloat16* __restrict__ akh, const __nv_bfloat16* __restrict__ akl,
             const __nv_bfloat16* __restrict__ avh, const __nv_bfloat16* __restrict__ avl,
             const __nv_bfloat16* __restrict__ wqh, const __nv_bfloat16* __restrict__ wql,
             const __nv_bfloat16* __restrict__ wkh, const __nv_bfloat16* __restrict__ wkl,
             const __nv_bfloat16* __restrict__ wvh, const __nv_bfloat16* __restrict__ wvl,
             const float* __restrict__ bq, const float* __restrict__ bk,
             const float* __restrict__ bv,
             __nv_bfloat16* __restrict__ qh, __nv_bfloat16* __restrict__ ql,
             __nv_bfloat16* __restrict__ kh, __nv_bfloat16* __restrict__ kl,
             __nv_bfloat16* __restrict__ vh, __nv_bfloat16* __restrict__ vl)
{
    extern __shared__ char smem[];
    const uint32_t sb = smem_to_u32(smem);
    const int tid = threadIdx.x;
    const int z = blockIdx.z;
    const int m0 = blockIdx.y * 128;
    const int n0 = blockIdx.x * 128;

    const __nv_bfloat16* Ah = (z == 0) ? aqh : (z == 1) ? akh : avh;
    const __nv_bfloat16* Al = (z == 0) ? aql : (z == 1) ? akl : avl;
    const __nv_bfloat16* Wh = (z == 0) ? wqh : (z == 1) ? wkh : wvh;
    const __nv_bfloat16* Wl = (z == 0) ? wql : (z == 1) ? wkl : wvl;
    const float* bias = (z == 0) ? bq : (z == 1) ? bk : bv;
    __nv_bfloat16* outh = (z == 0) ? qh : (z == 1) ? kh : vh;
    __nv_bfloat16* outl = (z == 0) ? ql : (z == 1) ? kl : vl;
    const bool rope = (z != 2);

    float acc[2][8][4];
#pragma unroll
    for (int mi = 0; mi < 2; mi++)
#pragma unroll
        for (int ni = 0; ni < 8; ni++)
#pragma unroll
            for (int q = 0; q < 4; q++) acc[mi][ni][q] = 0.0f;

    gemm_core(Ah, Al, Wh, Wl, sb, m0, n0, tid, acc);

    const int wid  = tid >> 5;
    const int lane = tid & 31;
    const int wm = (wid & 3) * 32;
    const int wn = (wid >> 2) * 64;
    const int cbase = n0 + wn + (lane & 3) * 2;
#pragma unroll
    for (int ni = 0; ni < 8; ni++) {
        const int c = cbase + ni * 8;
        const float b0 = bias[c], b1 = bias[c + 1];
        float freq = 0.0f;
        if (rope) {
            int d = c & (HD - 1);
            freq = powf(10000.0f, -(float)d / (float)HD);
        }
        const int h    = c >> 6;
        const int dcol = c & (HD - 1);
#pragma unroll
        for (int mi = 0; mi < 2; mi++) {
#pragma unroll
            for (int rg = 0; rg < 2; rg++) {
                int m = m0 + wm + mi * 16 + (lane >> 2) + rg * 8;
                float v0 = acc[mi][ni][2 * rg] + b0;
                float v1 = acc[mi][ni][2 * rg + 1] + b1;
                int l  = m >> 1;
                int bb = m & 1;
                if (rope) {
                    float sv, cv;
                    sincosf((float)l * freq, &sv, &cv);
                    float x1 = v0, x2 = v1;
                    v0 = x1 * cv - x2 * sv;
                    v1 = x1 * sv + x2 * cv;
                }
                size_t idx = (((size_t)bb * H_DIM + h) * L_DIM + l) * HD + dcol;
                *(uint32_t*)(outh + idx) = packbf2(v0, v1);
                *(uint32_t*)(outl + idx) = packres2(v0, v1);
            }
        }
    }
}

// ---- output projection: fp32 out[m*E+n] ----
__global__ void __launch_bounds__(256, 2)
mma_gemm_o(const __nv_bfloat16* __restrict__ Ah, const __nv_bfloat16* __restrict__ Al,
           const __nv_bfloat16* __restrict__ Wh, const __nv_bfloat16* __restrict__ Wl,
           const float* __restrict__ bias, float* __restrict__ outf)
{
    extern __shared__ char smem[];
    const uint32_t sb = smem_to_u32(smem);
    const int tid = threadIdx.x;
    const int m0 = blockIdx.y * 128;
    const int n0 = blockIdx.x * 128;

    float acc[2][8][4];
#pragma unroll
    for (int mi = 0; mi < 2; mi++)
#pragma unroll
        for (int ni = 0; ni < 8; ni++)
#pragma unroll
            for (int q = 0; q < 4; q++) acc[mi][ni][q] = 0.0f;

    gemm_core(Ah, Al, Wh, Wl, sb, m0, n0, tid, acc);

    const int wid  = tid >> 5;
    const int lane = tid & 31;
    const int wm = (wid & 3) * 32;
    const int wn = (wid >> 2) * 64;
    const int cbase = n0 + wn + (lane & 3) * 2;
#pragma unroll
    for (int ni = 0; ni < 8; ni++) {
        const int c = cbase + ni * 8;
        const float b0 = bias[c], b1 = bias[c + 1];
#pragma unroll
        for (int mi = 0; mi < 2; mi++) {
#pragma unroll
            for (int rg = 0; rg < 2; rg++) {
                int m = m0 + wm + mi * 16 + (lane >> 2) + rg * 8;
                float2 r = {acc[mi][ni][2 * rg] + b0, acc[mi][ni][2 * rg + 1] + b1};
                *(float2*)(outf + (size_t)m * E_DIM + c) = r;
            }
        }
    }
}

// ==================== flash attention on mma.sync (1 sync/chunk) ====================
#define FA_ROWB   144
#define FA_QTILE  (128 * FA_ROWB)
#define FA_KVTILE (64 * FA_ROWB)
#define FA_STAGE  (4 * FA_KVTILE)
#define FA_SMEM   (2 * FA_QTILE + 2 * FA_STAGE)   // 110592
#define FA_NC     (S_DIM / 64)

__global__ void __launch_bounds__(256, 2)
flash_attn_mma(const __nv_bfloat16* __restrict__ Qh_g, const __nv_bfloat16* __restrict__ Ql_g,
               const __nv_bfloat16* __restrict__ Kh_g, const __nv_bfloat16* __restrict__ Kl_g,
               const __nv_bfloat16* __restrict__ Vh_g, const __nv_bfloat16* __restrict__ Vl_g,
               const unsigned char* __restrict__ mask,
               __nv_bfloat16* __restrict__ Oh_g, __nv_bfloat16* __restrict__ Ol_g)
{
    extern __shared__ char smem[];
    const uint32_t sb = smem_to_u32(smem);
    const int tid = threadIdx.x, lane = tid & 31, wid = tid >> 5;
    const int bh = blockIdx.y, b = bh >> 4, h = bh & 15;
    const int l0 = blockIdx.x * 128;
    const int wm = wid * 16;

    const size_t goff = (size_t)bh * L_DIM * HD;

    const __nv_bfloat16* qsrc[2] = {Qh_g + goff, Ql_g + goff};
#pragma unroll
    for (int it = 0; it < 8; it++) {
        int idx = it * 256 + tid;
        int tile = idx >> 10, i = idx & 1023, row = i >> 3, ch = i & 7;
        cp_async16(sb + tile * FA_QTILE + row * FA_ROWB + ch * 16,
                   qsrc[tile] + (size_t)(l0 + row) * HD + ch * 8);
    }

    const __nv_bfloat16* kvsrc[4] = {Kh_g + goff, Kl_g + goff, Vh_g + goff, Vl_g + goff};
    const uint32_t kvbase = sb + 2 * FA_QTILE;
    auto prefetch_kv = [&](int c, int buf) {
        int s0 = c * 64;
#pragma unroll
        for (int it = 0; it < 8; it++) {
            int idx = it * 256 + tid;
            int tile = idx >> 9, i = idx & 511, row = i >> 3, ch = i & 7;
            cp_async16(kvbase + buf * FA_STAGE + tile * FA_KVTILE + row * FA_ROWB + ch * 16,
                       kvsrc[tile] + (size_t)(s0 + row) * HD + ch * 8);
        }
        CP_COMMIT();
    };
    prefetch_kv(0, 0);   // also commits the Q loads above

    float o_acc[8][4];
#pragma unroll
    for (int ni = 0; ni < 8; ni++)
#pragma unroll
        for (int q = 0; q < 4; q++) o_acc[ni][q] = 0.0f;
    float mi0 = -CUDART_INF_F, mi1 = -CUDART_INF_F, li0 = 0.0f, li1 = 0.0f;

    const int arow = lane & 15, akh = (lane >> 4) * 8;
    const int bg = lane >> 3, br = lane & 7;
    const int brow_off = (bg >> 1) * 8 + br;
    const int bk_off   = (bg & 1) * 8;
    const int trow_off = ((lane >> 3) & 1) * 8 + (lane & 7);
    const int tcol_off = (lane >> 4) * 8;
    const float scale2 = 0.125f * 1.4426950408889634f;   // 1/sqrt(64) / ln2

    uint32_t qfh[4][4], qfl[4][4];

    for (int c = 0; c < FA_NC; c++) {
        const int buf = c & 1;

        // mask bytes: independent global load, issue before the async wait
        const int s0c = c * 64;
        uchar2 mk[8];
#pragma unroll
        for (int ni = 0; ni < 8; ni++)
            mk[ni] = *(const uchar2*)(mask + (size_t)b * S_DIM + s0c + ni * 8 + (lane & 3) * 2);

        // single barrier per chunk; after it, all warps finished reading
        // buffer (c-1), so prefetching chunk c+1 into buf^1 is safe.
        CP_WAIT(0);
        __syncthreads();
        if (c + 1 < FA_NC) prefetch_kv(c + 1, buf ^ 1);

        if (c == 0) {
#pragma unroll
            for (int ks = 0; ks < 4; ks++) {
                uint32_t qaddr = sb + (wm + arow) * FA_ROWB + (ks * 16 + akh) * 2;
                ldmatrix_x4(qfh[ks][0], qfh[ks][1], qfh[ks][2], qfh[ks][3], qaddr);
                ldmatrix_x4(qfl[ks][0], qfl[ks][1], qfl[ks][2], qfl[ks][3], qaddr + FA_QTILE);
            }
        }

        const uint32_t sK = kvbase + buf * FA_STAGE;
        const uint32_t sV = sK + 2 * FA_KVTILE;

        float s[8][4];
#pragma unroll
        for (int ni = 0; ni < 8; ni++)
#pragma unroll
            for (int q = 0; q < 4; q++) s[ni][q] = 0.0f;

#pragma unroll
        for (int ks = 0; ks < 4; ks++) {
            const int kb = ks * 16;
#pragma unroll
            for (int nq = 0; nq < 4; nq++) {
                uint32_t kaddr = sK + (nq * 16 + brow_off) * FA_ROWB + (kb + bk_off) * 2;
                uint32_t k0, k1, k2, k3, e0, e1, e2, e3;
                ldmatrix_x4(k0, k1, k2, k3, kaddr);
                ldmatrix_x4(e0, e1, e2, e3, kaddr + FA_KVTILE);
                uint32_t kh0[2] = {k0, k1}, kh1[2] = {k2, k3};
                uint32_t kl0[2] = {e0, e1}, kl1[2] = {e2, e3};
                mma_bf16(s[2 * nq],     qfh[ks], kh0);
                mma_bf16(s[2 * nq + 1], qfh[ks], kh1);
                mma_bf16(s[2 * nq],     qfh[ks], kl0);
                mma_bf16(s[2 * nq + 1], qfh[ks], kl1);
                mma_bf16(s[2 * nq],     qfl[ks], kh0);
                mma_bf16(s[2 * nq + 1], qfl[ks], kh1);
            }
        }

        float mlo = -CUDART_INF_F, mhi = -CUDART_INF_F;
#pragma unroll
        for (int ni = 0; ni < 8; ni++) {
            float v0 = mk[ni].x ? -CUDART_INF_F : s[ni][0] * scale2;
            float v1 = mk[ni].y ? -CUDART_INF_F : s[ni][1] * scale2;
            float v2 = mk[ni].x ? -CUDART_INF_F : s[ni][2] * scale2;
            float v3 = mk[ni].y ? -CUDART_INF_F : s[ni][3] * scale2;
            s[ni][0] = v0; s[ni][1] = v1; s[ni][2] = v2; s[ni][3] = v3;
            mlo = fmaxf(mlo, fmaxf(v0, v1));
            mhi = fmaxf(mhi, fmaxf(v2, v3));
        }
        mlo = fmaxf(mlo, __shfl_xor_sync(0xffffffffu, mlo, 1));
        mlo = fmaxf(mlo, __shfl_xor_sync(0xffffffffu, mlo, 2));
        mhi = fmaxf(mhi, __shfl_xor_sync(0xffffffffu, mhi, 1));
        mhi = fmaxf(mhi, __shfl_xor_sync(0xffffffffu, mhi, 2));

        float mn0 = fmaxf(mi0, mlo), mn1 = fmaxf(mi1, mhi);
        float a0 = exp2f(mi0 - mn0), a1 = exp2f(mi1 - mn1);
        float ps0 = 0.0f, ps1 = 0.0f;
#pragma unroll
        for (int ni = 0; ni < 8; ni++) {
            float p0 = exp2f(s[ni][0] - mn0);
            float p1 = exp2f(s[ni][1] - mn0);
            float p2 = exp2f(s[ni][2] - mn1);
            float p3 = exp2f(s[ni][3] - mn1);
            s[ni][0] = p0; s[ni][1] = p1; s[ni][2] = p2; s[ni][3] = p3;
            ps0 += p0 + p1;
            ps1 += p2 + p3;
        }
        ps0 += __shfl_xor_sync(0xffffffffu, ps0, 1);
        ps0 += __shfl_xor_sync(0xffffffffu, ps0, 2);
        ps1 += __shfl_xor_sync(0xffffffffu, ps1, 1);
        ps1 += __shfl_xor_sync(0xffffffffu, ps1, 2);
        li0 = li0 * a0 + ps0;
        li1 = li1 * a1 + ps1;
        mi0 = mn0; mi1 = mn1;
#pragma unroll
        for (int ni = 0; ni < 8; ni++) {
            o_acc[ni][0] *= a0; o_acc[ni][1] *= a0;
            o_acc[ni][2] *= a1; o_acc[ni][3] *= a1;
        }

#pragma unroll
        for (int ks = 0; ks < 4; ks++) {
            uint32_t pah[4], pal[4];
            pah[0] = packbf2(s[2 * ks][0],     s[2 * ks][1]);
            pah[1] = packbf2(s[2 * ks][2],     s[2 * ks][3]);
            pah[2] = packbf2(s[2 * ks + 1][0], s[2 * ks + 1][1]);
            pah[3] = packbf2(s[2 * ks + 1][2], s[2 * ks + 1][3]);
            pal[0] = packres2(s[2 * ks][0],     s[2 * ks][1]);
            pal[1] = packres2(s[2 * ks][2],     s[2 * ks][3]);
            pal[2] = packres2(s[2 * ks + 1][0], s[2 * ks + 1][1]);
            pal[3] = packres2(s[2 * ks + 1][2], s[2 * ks + 1][3]);
#pragma unroll
            for (int nb = 0; nb < 4; nb++) {
                uint32_t vaddr = sV + (ks * 16 + trow_off) * FA_ROWB + (nb * 16 + tcol_off) * 2;
                uint32_t v0, v1, v2, v3, w0, w1, w2, w3;
                ldmatrix_x4_trans(v0, v1, v2, v3, vaddr);
                ldmatrix_x4_trans(w0, w1, w2, w3, vaddr + FA_KVTILE);
                uint32_t vh0[2] = {v0, v1}, vh1[2] = {v2, v3};
                uint32_t vl0[2] = {w0, w1}, vl1[2] = {w2, w3};
                mma_bf16(o_acc[2 * nb],     pah, vh0);
                mma_bf16(o_acc[2 * nb + 1], pah, vh1);
                mma_bf16(o_acc[2 * nb],     pah, vl0);
                mma_bf16(o_acc[2 * nb + 1], pah, vl1);
                mma_bf16(o_acc[2 * nb],     pal, vh0);
                mma_bf16(o_acc[2 * nb + 1], pal, vh1);
            }
        }
    }

    const float inv0 = 1.0f / li0, inv1 = 1.0f / li1;
    const int r0 = lane >> 2;
    const int m0g = ((l0 + wm + r0) << 1) | b;
    const int m1g = ((l0 + wm + r0 + 8) << 1) | b;
#pragma unroll
    for (int ni = 0; ni < 8; ni++) {
        int cg = h * HD + ni * 8 + (lane & 3) * 2;
        float v00 = o_acc[ni][0] * inv0, v01 = o_acc[ni][1] * inv0;
        float v10 = o_acc[ni][2] * inv1, v11 = o_acc[ni][3] * inv1;
        *(uint32_t*)(Oh_g + (size_t)m0g * E_DIM + cg) = packbf2(v00, v01);
        *(uint32_t*)(Ol_g + (size_t)m0g * E_DIM + cg) = packres2(v00, v01);
        *(uint32_t*)(Oh_g + (size_t)m1g * E_DIM + cg) = packbf2(v10, v11);
        *(uint32_t*)(Ol_g + (size_t)m1g * E_DIM + cg) = packres2(v10, v11);
    }
}

// ============================================================================
// launch
// ============================================================================
extern "C" void kernel_launch(void* const* d_in, const int* in_sizes, int n_in,
                              void* d_out, int out_size)
{
    const float* query = (const float*)d_in[0];
    const float* key   = (const float*)d_in[1];
    const float* value = (const float*)d_in[2];
    const unsigned char* mask = (const unsigned char*)d_in[3];
    const float* Wq = (const float*)d_in[4];
    const float* bq = (const float*)d_in[5];
    const float* Wk = (const float*)d_in[6];
    const float* bk = (const float*)d_in[7];
    const float* Wv = (const float*)d_in[8];
    const float* bv = (const float*)d_in[9];
    const float* Wo = (const float*)d_in[10];
    const float* bo = (const float*)d_in[11];
    float* out = (float*)d_out;

    __nv_bfloat16 *aqh, *aql, *akh, *akl, *avh, *avl;
    __nv_bfloat16 *wqh, *wql, *wkh, *wkl, *wvh, *wvl, *woh, *wol;
    __nv_bfloat16 *qh, *ql, *kh, *kl, *vh, *vl;
    cudaGetSymbolAddress((void**)&aqh, g_aq_h); cudaGetSymbolAddress((void**)&aql, g_aq_l);
    cudaGetSymbolAddress((void**)&akh, g_ak_h); cudaGetSymbolAddress((void**)&akl, g_ak_l);
    cudaGetSymbolAddress((void**)&avh, g_av_h); cudaGetSymbolAddress((void**)&avl, g_av_l);
    cudaGetSymbolAddress((void**)&wqh, g_wq_h); cudaGetSymbolAddress((void**)&wql, g_wq_l);
    cudaGetSymbolAddress((void**)&wkh, g_wk_h); cudaGetSymbolAddress((void**)&wkl, g_wk_l);
    cudaGetSymbolAddress((void**)&wvh, g_wv_h); cudaGetSymbolAddress((void**)&wvl, g_wv_l);
    cudaGetSymbolAddress((void**)&woh, g_wo_h); cudaGetSymbolAddress((void**)&wol, g_wo_l);
    cudaGetSymbolAddress((void**)&qh, g_Qh); cudaGetSymbolAddress((void**)&ql, g_Ql);
    cudaGetSymbolAddress((void**)&kh, g_Kh); cudaGetSymbolAddress((void**)&kl, g_Kl);
    cudaGetSymbolAddress((void**)&vh, g_Vh); cudaGetSymbolAddress((void**)&vl, g_Vl);

    cudaFuncSetAttribute(mma_gemm_qkv, cudaFuncAttributeMaxDynamicSharedMemorySize, GEMM_SMEM);
    cudaFuncSetAttribute(mma_gemm_o,   cudaFuncAttributeMaxDynamicSharedMemorySize, GEMM_SMEM);
    cudaFuncSetAttribute(flash_attn_mma, cudaFuncAttributeMaxDynamicSharedMemorySize, FA_SMEM);

    // one fused split launch for all 3 activations + 4 weights
    dim3 sgrid(1024, 7);
    split_all<<<sgrid, 256>>>(query, key, value, Wq, Wk, Wv, Wo,
                              aqh, aql, akh, akl, avh, avl,
                              wqh, wql, wkh, wkl, wvh, wvl, woh, wol);

    // batched QKV projections (+RoPE on Q,K)
    dim3 qkv_grid(E_DIM / 128, M_ROWS / 128, 3);   // (8, 32, 3)
    mma_gemm_qkv<<<qkv_grid, 256, GEMM_SMEM>>>(
        aqh, aql, akh, akl, avh, avl,
        wqh, wql, wkh, wkl, wvh, wvl,
        bq, bk, bv, qh, ql, kh, kl, vh, vl);

    // attention -> act hi/lo [m][E] (reuse g_aq buffers)
    dim3 agrid(L_DIM / 128, B_DIM * H_DIM);        // (16, 32)
    flash_attn_mma<<<agrid, 256, FA_SMEM>>>(qh, ql, kh, kl, vh, vl, mask, aqh, aql);

    // output projection -> d_out fp32
    dim3 ogrid(E_DIM / 128, M_ROWS / 128);
    mma_gemm_o<<<ogrid, 256, GEMM_SMEM>>>(aqh, aql, woh, wol, bo, out);
}

// round 10
// speedup vs baseline: 4.0368x; 1.3829x over previous
#include <cuda_runtime.h>
#include <cuda_fp16.h>
#include <math.h>
#include <math_constants.h>
#include <cstdint>

#define L_DIM 2048
#define S_DIM 2048
#define B_DIM 2
#define E_DIM 1024
#define H_DIM 16
#define HD    64
#define M_ROWS (L_DIM * B_DIM)   // 4096

// ============================ helpers ============================
__device__ __forceinline__ uint32_t smem_to_u32(const void* p) {
    uint32_t a;
    asm("{ .reg .u64 t; cvta.to.shared.u64 t, %1; cvt.u32.u64 %0, t; }" : "=r"(a) : "l"(p));
    return a;
}
__device__ __forceinline__ void cp_async16(uint32_t dst, const void* src) {
    asm volatile("cp.async.cg.shared.global [%0], [%1], 16;" :: "r"(dst), "l"(src));
}
#define CP_COMMIT() asm volatile("cp.async.commit_group;" ::: "memory")
#define CP_WAIT(n)  asm volatile("cp.async.wait_group %0;" :: "n"(n) : "memory")

__device__ __forceinline__ void ldmatrix_x4(uint32_t& r0, uint32_t& r1,
                                            uint32_t& r2, uint32_t& r3, uint32_t addr) {
    asm volatile("ldmatrix.sync.aligned.m8n8.x4.shared.b16 {%0,%1,%2,%3}, [%4];"
                 : "=r"(r0), "=r"(r1), "=r"(r2), "=r"(r3) : "r"(addr));
}
__device__ __forceinline__ void ldmatrix_x4_trans(uint32_t& r0, uint32_t& r1,
                                                  uint32_t& r2, uint32_t& r3, uint32_t addr) {
    asm volatile("ldmatrix.sync.aligned.m8n8.x4.trans.shared.b16 {%0,%1,%2,%3}, [%4];"
                 : "=r"(r0), "=r"(r1), "=r"(r2), "=r"(r3) : "r"(addr));
}
// fp16 inputs, fp32 accumulate
__device__ __forceinline__ void mma_f16(float* d, const uint32_t* a, const uint32_t* b) {
    asm volatile(
        "mma.sync.aligned.m16n8k16.row.col.f32.f16.f16.f32 "
        "{%0,%1,%2,%3}, {%4,%5,%6,%7}, {%8,%9}, {%0,%1,%2,%3};"
        : "+f"(d[0]), "+f"(d[1]), "+f"(d[2]), "+f"(d[3])
        : "r"(a[0]), "r"(a[1]), "r"(a[2]), "r"(a[3]), "r"(b[0]), "r"(b[1]));
}
// pack two fp32 -> half2 (lo in low half)
__device__ __forceinline__ uint32_t packh2(float lo, float hi) {
    __half2 h = __floats2half2_rn(lo, hi);
    return *(uint32_t*)&h;
}
// residuals (v - fp16(v)) of two fp32 -> half2
__device__ __forceinline__ uint32_t packresh2(float lo, float hi) {
    float rl = lo - __half2float(__float2half_rn(lo));
    float rh = hi - __half2float(__float2half_rn(hi));
    return packh2(rl, rh);
}

// ============================ scratch ============================
#define ACT_SZ ((size_t)M_ROWS * E_DIM)
#define W_SZ   ((size_t)E_DIM * E_DIM)
__device__ __half g_aq_h[ACT_SZ], g_aq_l[ACT_SZ];
__device__ __half g_ak_h[ACT_SZ], g_ak_l[ACT_SZ];
__device__ __half g_av_h[ACT_SZ], g_av_l[ACT_SZ];
__device__ __half g_wq_h[W_SZ], g_wk_h[W_SZ], g_wv_h[W_SZ], g_wo_h[W_SZ];
#define BHTD ((size_t)B_DIM * H_DIM * L_DIM * HD)
__device__ __half g_Qh[BHTD], g_Ql[BHTD];
__device__ __half g_Kh[BHTD];
__device__ __half g_Vh[BHTD];

// ==================== fused fp32 -> fp16 hi(/lo) split ====================
// jobs 0-2: activations (hi+lo, 4 reps); 3-6: weights (hi only, 1 rep)
__global__ void __launch_bounds__(256)
split_all(const float* __restrict__ q,  const float* __restrict__ k,
          const float* __restrict__ v,  const float* __restrict__ wq,
          const float* __restrict__ wk, const float* __restrict__ wv,
          const float* __restrict__ wo,
          __half* aqh, __half* aql, __half* akh, __half* akl,
          __half* avh, __half* avl,
          __half* wqh, __half* wkh, __half* wvh, __half* woh)
{
    const int j = blockIdx.y;
    const float* src = (j == 0) ? q : (j == 1) ? k : (j == 2) ? v
                     : (j == 3) ? wq : (j == 4) ? wk : (j == 5) ? wv : wo;
    __half* hi = (j == 0) ? aqh : (j == 1) ? akh : (j == 2) ? avh
               : (j == 3) ? wqh : (j == 4) ? wkh : (j == 5) ? wvh : woh;
    __half* lo = (j == 0) ? aql : (j == 1) ? akl : avl;
    const int reps = (j < 3) ? 4 : 1;

    for (int r = 0; r < reps; r++) {
        int i = (r * 1024 + blockIdx.x) * 256 + threadIdx.x;
        float4 vv = ((const float4*)src)[i];
        uint2 uh = {packh2(vv.x, vv.y), packh2(vv.z, vv.w)};
        ((uint2*)hi)[i] = uh;
        if (j < 3) {
            uint2 ul = {packresh2(vv.x, vv.y), packresh2(vv.z, vv.w)};
            ((uint2*)lo)[i] = ul;
        }
    }
}

// ==================== GEMM core (BK=32, fp16 2-pass, 3-stage) ====================
#define BK        32
#define ROW_PADB  40                          // fp16 pitch 80 B (64B data + 16 pad)
#define TILE_B    (128 * ROW_PADB * 2)        // 10240
#define STAGE_B   (3 * TILE_B)                // 30720 (Ah, Al, Wh)
#define GEMM_SMEM (3 * STAGE_B)               // 92160, 2 CTA/SM
#define NCHUNK    (E_DIM / BK)                // 32

__device__ __forceinline__ void gemm_core(
    const __half* __restrict__ Ah, const __half* __restrict__ Al,
    const __half* __restrict__ Wh,
    uint32_t sb, int m0, int n0, int tid, float acc[2][8][4])
{
    const int wid  = tid >> 5;
    const int lane = tid & 31;
    const int wm = (wid & 3) * 32;
    const int wn = (wid >> 2) * 64;

    const __half* gsrc[3] = {Ah, Al, Wh};

    auto prefetch = [&](int c, int buf) {
        const int k0 = c * BK;
#pragma unroll
        for (int it = 0; it < 6; it++) {
            int idx  = it * 256 + tid;        // 0..1535
            int tile = idx >> 9;              // 0..2
            int i    = idx & 511;
            int row  = i >> 2;                // 0..127
            int ch   = i & 3;                 // 16B chunk
            int grow = (tile < 2 ? m0 : n0) + row;
            const __half* gp = gsrc[tile] + (size_t)grow * E_DIM + k0 + ch * 8;
            uint32_t dst = sb + buf * STAGE_B + tile * TILE_B + row * (ROW_PADB * 2) + ch * 16;
            cp_async16(dst, gp);
        }
        CP_COMMIT();
    };

    prefetch(0, 0);
    prefetch(1, 1);

    const int arow = lane & 15;
    const int akh  = (lane >> 4) * 8;
    const int bg = lane >> 3;
    const int br = lane & 7;

    for (int c = 0; c < NCHUNK; c++) {
        const int buf = c % 3;
        if (c + 1 < NCHUNK) CP_WAIT(1); else CP_WAIT(0);
        __syncthreads();
        if (c + 2 < NCHUNK) prefetch(c + 2, (c + 2) % 3);

        const uint32_t st = sb + buf * STAGE_B;
#pragma unroll
        for (int ks = 0; ks < 2; ks++) {
            const int kb = ks * 16;
            uint32_t ah[2][4], al[2][4];
#pragma unroll
            for (int mi = 0; mi < 2; mi++) {
                uint32_t addr = st +
                    (wm + mi * 16 + arow) * (ROW_PADB * 2) + (kb + akh) * 2;
                ldmatrix_x4(ah[mi][0], ah[mi][1], ah[mi][2], ah[mi][3], addr);
                addr += TILE_B;
                ldmatrix_x4(al[mi][0], al[mi][1], al[mi][2], al[mi][3], addr);
            }
            uint32_t bhv[8][2];
#pragma unroll
            for (int nq = 0; nq < 4; nq++) {
                uint32_t addr = st + 2 * TILE_B +
                    (wn + nq * 16 + (bg >> 1) * 8 + br) * (ROW_PADB * 2) + (kb + (bg & 1) * 8) * 2;
                uint32_t r0, r1, r2, r3;
                ldmatrix_x4(r0, r1, r2, r3, addr);
                bhv[2 * nq][0] = r0; bhv[2 * nq][1] = r1;
                bhv[2 * nq + 1][0] = r2; bhv[2 * nq + 1][1] = r3;
            }
#pragma unroll
            for (int mi = 0; mi < 2; mi++)
#pragma unroll
                for (int ni = 0; ni < 8; ni++)
                    mma_f16(acc[mi][ni], ah[mi], bhv[ni]);   // hi pass
#pragma unroll
            for (int mi = 0; mi < 2; mi++)
#pragma unroll
                for (int ni = 0; ni < 8; ni++)
                    mma_f16(acc[mi][ni], al[mi], bhv[ni]);   // lo pass
        }
    }
}

// ---- batched QKV projection: z=0 Q(+rope, hi+lo out), z=1 K(+rope, hi), z=2 V(hi) ----
__global__ void __launch_bounds__(256, 2)
mma_gemm_qkv(const __half* __restrict__ aqh, const __half* __restrict__ aql,
             const __half* __restrict__ akh, const __half* __restrict__ akl,
             const __half* __restrict__ avh, const __half* __restrict__ avl,
             const __half* __restrict__ wqh, const __half* __restrict__ wkh,
             const __half* __restrict__ wvh,
             const float* __restrict__ bq, const float* __restrict__ bk,
             const float* __restrict__ bv,
             __half* __restrict__ qh, __half* __restrict__ ql,
             __half* __restrict__ kh, __half* __restrict__ vh)
{
    extern __shared__ char smem[];
    const uint32_t sb = smem_to_u32(smem);
    const int tid = threadIdx.x;
    const int z = blockIdx.z;
    const int m0 = blockIdx.y * 128;
    const int n0 = blockIdx.x * 128;

    const __half* Ah = (z == 0) ? aqh : (z == 1) ? akh : avh;
    const __half* Al = (z == 0) ? aql : (z == 1) ? akl : avl;
    const __half* Wh = (z == 0) ? wqh : (z == 1) ? wkh : wvh;
    const float* bias = (z == 0) ? bq : (z == 1) ? bk : bv;
    __half* outh = (z == 0) ? qh : (z == 1) ? kh : vh;
    const bool rope = (z != 2);

    float acc[2][8][4];
#pragma unroll
    for (int mi = 0; mi < 2; mi++)
#pragma unroll
        for (int ni = 0; ni < 8; ni++)
#pragma unroll
            for (int q = 0; q < 4; q++) acc[mi][ni][q] = 0.0f;

    gemm_core(Ah, Al, Wh, sb, m0, n0, tid, acc);

    const int wid  = tid >> 5;
    const int lane = tid & 31;
    const int wm = (wid & 3) * 32;
    const int wn = (wid >> 2) * 64;
    const int cbase = n0 + wn + (lane & 3) * 2;
#pragma unroll
    for (int ni = 0; ni < 8; ni++) {
        const int c = cbase + ni * 8;
        const float b0 = bias[c], b1 = bias[c + 1];
        float freq = 0.0f;
        if (rope) {
            int d = c & (HD - 1);
            freq = powf(10000.0f, -(float)d / (float)HD);
        }
        const int h    = c >> 6;
        const int dcol = c & (HD - 1);
#pragma unroll
        for (int mi = 0; mi < 2; mi++) {
#pragma unroll
            for (int rg = 0; rg < 2; rg++) {
                int m = m0 + wm + mi * 16 + (lane >> 2) + rg * 8;
                float v0 = acc[mi][ni][2 * rg] + b0;
                float v1 = acc[mi][ni][2 * rg + 1] + b1;
                int l  = m >> 1;
                int bb = m & 1;
                if (rope) {
                    float sv, cv;
                    sincosf((float)l * freq, &sv, &cv);
                    float x1 = v0, x2 = v1;
                    v0 = x1 * cv - x2 * sv;
                    v1 = x1 * sv + x2 * cv;
                }
                size_t idx = (((size_t)bb * H_DIM + h) * L_DIM + l) * HD + dcol;
                *(uint32_t*)(outh + idx) = packh2(v0, v1);
                if (z == 0)
                    *(uint32_t*)(ql + idx) = packresh2(v0, v1);
            }
        }
    }
}

// ---- output projection: fp32 out[m*E+n] ----
__global__ void __launch_bounds__(256, 2)
mma_gemm_o(const __half* __restrict__ Ah, const __half* __restrict__ Al,
           const __half* __restrict__ Wh,
           const float* __restrict__ bias, float* __restrict__ outf)
{
    extern __shared__ char smem[];
    const uint32_t sb = smem_to_u32(smem);
    const int tid = threadIdx.x;
    const int m0 = blockIdx.y * 128;
    const int n0 = blockIdx.x * 128;

    float acc[2][8][4];
#pragma unroll
    for (int mi = 0; mi < 2; mi++)
#pragma unroll
        for (int ni = 0; ni < 8; ni++)
#pragma unroll
            for (int q = 0; q < 4; q++) acc[mi][ni][q] = 0.0f;

    gemm_core(Ah, Al, Wh, sb, m0, n0, tid, acc);

    const int wid  = tid >> 5;
    const int lane = tid & 31;
    const int wm = (wid & 3) * 32;
    const int wn = (wid >> 2) * 64;
    const int cbase = n0 + wn + (lane & 3) * 2;
#pragma unroll
    for (int ni = 0; ni < 8; ni++) {
        const int c = cbase + ni * 8;
        const float b0 = bias[c], b1 = bias[c + 1];
#pragma unroll
        for (int mi = 0; mi < 2; mi++) {
#pragma unroll
            for (int rg = 0; rg < 2; rg++) {
                int m = m0 + wm + mi * 16 + (lane >> 2) + rg * 8;
                float2 r = {acc[mi][ni][2 * rg] + b0, acc[mi][ni][2 * rg + 1] + b1};
                *(float2*)(outf + (size_t)m * E_DIM + c) = r;
            }
        }
    }
}

// ==================== flash attention (fp16 2-pass, 3-stage KV ring) ====================
#define FA_ROWB   144
#define FA_QTILE  (128 * FA_ROWB)              // 18432
#define FA_KVTILE (64 * FA_ROWB)               // 9216
#define FA_STAGE  (2 * FA_KVTILE)              // Kh, Vh = 18432
#define FA_SMEM   (2 * FA_QTILE + 3 * FA_STAGE)  // 36864 + 55296 = 92160
#define FA_NC     (S_DIM / 64)

__global__ void __launch_bounds__(256, 2)
flash_attn_mma(const __half* __restrict__ Qh_g, const __half* __restrict__ Ql_g,
               const __half* __restrict__ Kh_g, const __half* __restrict__ Vh_g,
               const unsigned char* __restrict__ mask,
               __half* __restrict__ Oh_g, __half* __restrict__ Ol_g)
{
    extern __shared__ char smem[];
    const uint32_t sb = smem_to_u32(smem);
    const int tid = threadIdx.x, lane = tid & 31, wid = tid >> 5;
    const int bh = blockIdx.y, b = bh >> 4, h = bh & 15;
    const int l0 = blockIdx.x * 128;
    const int wm = wid * 16;

    const size_t goff = (size_t)bh * L_DIM * HD;

    // Q hi+lo tiles (committed with KV group 0)
    const __half* qsrc[2] = {Qh_g + goff, Ql_g + goff};
#pragma unroll
    for (int it = 0; it < 8; it++) {
        int idx = it * 256 + tid;
        int tile = idx >> 10, i = idx & 1023, row = i >> 3, ch = i & 7;
        cp_async16(sb + tile * FA_QTILE + row * FA_ROWB + ch * 16,
                   qsrc[tile] + (size_t)(l0 + row) * HD + ch * 8);
    }

    const __half* kvsrc[2] = {Kh_g + goff, Vh_g + goff};
    const uint32_t kvbase = sb + 2 * FA_QTILE;
    auto prefetch_kv = [&](int c, int buf) {
        int s0 = c * 64;
#pragma unroll
        for (int it = 0; it < 4; it++) {
            int idx = it * 256 + tid;           // 0..1023
            int tile = idx >> 9, i = idx & 511, row = i >> 3, ch = i & 7;
            cp_async16(kvbase + buf * FA_STAGE + tile * FA_KVTILE + row * FA_ROWB + ch * 16,
                       kvsrc[tile] + (size_t)(s0 + row) * HD + ch * 8);
        }
        CP_COMMIT();
    };
    prefetch_kv(0, 0);
    prefetch_kv(1, 1);

    float o_acc[8][4];
#pragma unroll
    for (int ni = 0; ni < 8; ni++)
#pragma unroll
        for (int q = 0; q < 4; q++) o_acc[ni][q] = 0.0f;
    float mi0 = -CUDART_INF_F, mi1 = -CUDART_INF_F, li0 = 0.0f, li1 = 0.0f;

    const int arow = lane & 15, akh = (lane >> 4) * 8;
    const int bg = lane >> 3, br = lane & 7;
    const int brow_off = (bg >> 1) * 8 + br;
    const int bk_off   = (bg & 1) * 8;
    const int trow_off = ((lane >> 3) & 1) * 8 + (lane & 7);
    const int tcol_off = (lane >> 4) * 8;
    const float scale2 = 0.125f * 1.4426950408889634f;   // 1/sqrt(64) / ln2

    uint32_t qfh[4][4], qfl[4][4];

    for (int c = 0; c < FA_NC; c++) {
        const int buf = c % 3;

        const int s0c = c * 64;
        uchar2 mk[8];
#pragma unroll
        for (int ni = 0; ni < 8; ni++)
            mk[ni] = *(const uchar2*)(mask + (size_t)b * S_DIM + s0c + ni * 8 + (lane & 3) * 2);

        if (c + 1 < FA_NC) CP_WAIT(1); else CP_WAIT(0);
        __syncthreads();
        if (c + 2 < FA_NC) prefetch_kv(c + 2, (c + 2) % 3);

        if (c == 0) {
#pragma unroll
            for (int ks = 0; ks < 4; ks++) {
                uint32_t qaddr = sb + (wm + arow) * FA_ROWB + (ks * 16 + akh) * 2;
                ldmatrix_x4(qfh[ks][0], qfh[ks][1], qfh[ks][2], qfh[ks][3], qaddr);
                ldmatrix_x4(qfl[ks][0], qfl[ks][1], qfl[ks][2], qfl[ks][3], qaddr + FA_QTILE);
            }
        }

        const uint32_t sK = kvbase + buf * FA_STAGE;
        const uint32_t sV = sK + FA_KVTILE;

        float s[8][4];
#pragma unroll
        for (int ni = 0; ni < 8; ni++)
#pragma unroll
            for (int q = 0; q < 4; q++) s[ni][q] = 0.0f;

        // GEMM1: S = (Qh + Ql) * Kh^T
#pragma unroll
        for (int ks = 0; ks < 4; ks++) {
            const int kb = ks * 16;
#pragma unroll
            for (int nq = 0; nq < 4; nq++) {
                uint32_t kaddr = sK + (nq * 16 + brow_off) * FA_ROWB + (kb + bk_off) * 2;
                uint32_t k0, k1, k2, k3;
                ldmatrix_x4(k0, k1, k2, k3, kaddr);
                uint32_t kh0[2] = {k0, k1}, kh1[2] = {k2, k3};
                mma_f16(s[2 * nq],     qfh[ks], kh0);
                mma_f16(s[2 * nq + 1], qfh[ks], kh1);
                mma_f16(s[2 * nq],     qfl[ks], kh0);
                mma_f16(s[2 * nq + 1], qfl[ks], kh1);
            }
        }

        float mlo = -CUDART_INF_F, mhi = -CUDART_INF_F;
#pragma unroll
        for (int ni = 0; ni < 8; ni++) {
            float v0 = mk[ni].x ? -CUDART_INF_F : s[ni][0] * scale2;
            float v1 = mk[ni].y ? -CUDART_INF_F : s[ni][1] * scale2;
            float v2 = mk[ni].x ? -CUDART_INF_F : s[ni][2] * scale2;
            float v3 = mk[ni].y ? -CUDART_INF_F : s[ni][3] * scale2;
            s[ni][0] = v0; s[ni][1] = v1; s[ni][2] = v2; s[ni][3] = v3;
            mlo = fmaxf(mlo, fmaxf(v0, v1));
            mhi = fmaxf(mhi, fmaxf(v2, v3));
        }
        mlo = fmaxf(mlo, __shfl_xor_sync(0xffffffffu, mlo, 1));
        mlo = fmaxf(mlo, __shfl_xor_sync(0xffffffffu, mlo, 2));
        mhi = fmaxf(mhi, __shfl_xor_sync(0xffffffffu, mhi, 1));
        mhi = fmaxf(mhi, __shfl_xor_sync(0xffffffffu, mhi, 2));

        float mn0 = fmaxf(mi0, mlo), mn1 = fmaxf(mi1, mhi);
        float a0 = exp2f(mi0 - mn0), a1 = exp2f(mi1 - mn1);
        float ps0 = 0.0f, ps1 = 0.0f;
#pragma unroll
        for (int ni = 0; ni < 8; ni++) {
            float p0 = exp2f(s[ni][0] - mn0);
            float p1 = exp2f(s[ni][1] - mn0);
            float p2 = exp2f(s[ni][2] - mn1);
            float p3 = exp2f(s[ni][3] - mn1);
            s[ni][0] = p0; s[ni][1] = p1; s[ni][2] = p2; s[ni][3] = p3;
            ps0 += p0 + p1;
            ps1 += p2 + p3;
        }
        ps0 += __shfl_xor_sync(0xffffffffu, ps0, 1);
        ps0 += __shfl_xor_sync(0xffffffffu, ps0, 2);
        ps1 += __shfl_xor_sync(0xffffffffu, ps1, 1);
        ps1 += __shfl_xor_sync(0xffffffffu, ps1, 2);
        li0 = li0 * a0 + ps0;
        li1 = li1 * a1 + ps1;
        mi0 = mn0; mi1 = mn1;
#pragma unroll
        for (int ni = 0; ni < 8; ni++) {
            o_acc[ni][0] *= a0; o_acc[ni][1] *= a0;
            o_acc[ni][2] *= a1; o_acc[ni][3] *= a1;
        }

        // GEMM2: O += (Ph + Pl) * Vh
#pragma unroll
        for (int ks = 0; ks < 4; ks++) {
            uint32_t pah[4], pal[4];
            pah[0] = packh2(s[2 * ks][0],     s[2 * ks][1]);
            pah[1] = packh2(s[2 * ks][2],     s[2 * ks][3]);
            pah[2] = packh2(s[2 * ks + 1][0], s[2 * ks + 1][1]);
            pah[3] = packh2(s[2 * ks + 1][2], s[2 * ks + 1][3]);
            pal[0] = packresh2(s[2 * ks][0],     s[2 * ks][1]);
            pal[1] = packresh2(s[2 * ks][2],     s[2 * ks][3]);
            pal[2] = packresh2(s[2 * ks + 1][0], s[2 * ks + 1][1]);
            pal[3] = packresh2(s[2 * ks + 1][2], s[2 * ks + 1][3]);
#pragma unroll
            for (int nb = 0; nb < 4; nb++) {
                uint32_t vaddr = sV + (ks * 16 + trow_off) * FA_ROWB + (nb * 16 + tcol_off) * 2;
                uint32_t v0, v1, v2, v3;
                ldmatrix_x4_trans(v0, v1, v2, v3, vaddr);
                uint32_t vh0[2] = {v0, v1}, vh1[2] = {v2, v3};
                mma_f16(o_acc[2 * nb],     pah, vh0);
                mma_f16(o_acc[2 * nb + 1], pah, vh1);
                mma_f16(o_acc[2 * nb],     pal, vh0);
                mma_f16(o_acc[2 * nb + 1], pal, vh1);
            }
        }
    }

    const float inv0 = 1.0f / li0, inv1 = 1.0f / li1;
    const int r0 = lane >> 2;
    const int m0g = ((l0 + wm + r0) << 1) | b;
    const int m1g = ((l0 + wm + r0 + 8) << 1) | b;
#pragma unroll
    for (int ni = 0; ni < 8; ni++) {
        int cg = h * HD + ni * 8 + (lane & 3) * 2;
        float v00 = o_acc[ni][0] * inv0, v01 = o_acc[ni][1] * inv0;
        float v10 = o_acc[ni][2] * inv1, v11 = o_acc[ni][3] * inv1;
        *(uint32_t*)(Oh_g + (size_t)m0g * E_DIM + cg) = packh2(v00, v01);
        *(uint32_t*)(Ol_g + (size_t)m0g * E_DIM + cg) = packresh2(v00, v01);
        *(uint32_t*)(Oh_g + (size_t)m1g * E_DIM + cg) = packh2(v10, v11);
        *(uint32_t*)(Ol_g + (size_t)m1g * E_DIM + cg) = packresh2(v10, v11);
    }
}

// ============================================================================
// launch
// ============================================================================
extern "C" void kernel_launch(void* const* d_in, const int* in_sizes, int n_in,
                              void* d_out, int out_size)
{
    const float* query = (const float*)d_in[0];
    const float* key   = (const float*)d_in[1];
    const float* value = (const float*)d_in[2];
    const unsigned char* mask = (const unsigned char*)d_in[3];
    const float* Wq = (const float*)d_in[4];
    const float* bq = (const float*)d_in[5];
    const float* Wk = (const float*)d_in[6];
    const float* bk = (const float*)d_in[7];
    const float* Wv = (const float*)d_in[8];
    const float* bv = (const float*)d_in[9];
    const float* Wo = (const float*)d_in[10];
    const float* bo = (const float*)d_in[11];
    float* out = (float*)d_out;

    __half *aqh, *aql, *akh, *akl, *avh, *avl;
    __half *wqh, *wkh, *wvh, *woh;
    __half *qh, *ql, *kh, *vh;
    cudaGetSymbolAddress((void**)&aqh, g_aq_h); cudaGetSymbolAddress((void**)&aql, g_aq_l);
    cudaGetSymbolAddress((void**)&akh, g_ak_h); cudaGetSymbolAddress((void**)&akl, g_ak_l);
    cudaGetSymbolAddress((void**)&avh, g_av_h); cudaGetSymbolAddress((void**)&avl, g_av_l);
    cudaGetSymbolAddress((void**)&wqh, g_wq_h); cudaGetSymbolAddress((void**)&wkh, g_wk_h);
    cudaGetSymbolAddress((void**)&wvh, g_wv_h); cudaGetSymbolAddress((void**)&woh, g_wo_h);
    cudaGetSymbolAddress((void**)&qh, g_Qh); cudaGetSymbolAddress((void**)&ql, g_Ql);
    cudaGetSymbolAddress((void**)&kh, g_Kh); cudaGetSymbolAddress((void**)&vh, g_Vh);

    cudaFuncSetAttribute(mma_gemm_qkv, cudaFuncAttributeMaxDynamicSharedMemorySize, GEMM_SMEM);
    cudaFuncSetAttribute(mma_gemm_o,   cudaFuncAttributeMaxDynamicSharedMemorySize, GEMM_SMEM);
    cudaFuncSetAttribute(flash_attn_mma, cudaFuncAttributeMaxDynamicSharedMemorySize, FA_SMEM);

    // one fused split launch (activations hi+lo, weights hi)
    dim3 sgrid(1024, 7);
    split_all<<<sgrid, 256>>>(query, key, value, Wq, Wk, Wv, Wo,
                              aqh, aql, akh, akl, avh, avl,
                              wqh, wkh, wvh, woh);

    // batched QKV projections (+RoPE on Q,K)
    dim3 qkv_grid(E_DIM / 128, M_ROWS / 128, 3);   // (8, 32, 3)
    mma_gemm_qkv<<<qkv_grid, 256, GEMM_SMEM>>>(
        aqh, aql, akh, akl, avh, avl,
        wqh, wkh, wvh, bq, bk, bv, qh, ql, kh, vh);

    // attention -> act hi/lo [m][E] (reuse g_aq buffers)
    dim3 agrid(L_DIM / 128, B_DIM * H_DIM);        // (16, 32)
    flash_attn_mma<<<agrid, 256, FA_SMEM>>>(qh, ql, kh, vh, mask, aqh, aql);

    // output projection -> d_out fp32
    dim3 ogrid(E_DIM / 128, M_ROWS / 128);
    mma_gemm_o<<<ogrid, 256, GEMM_SMEM>>>(aqh, aql, woh, bo, out);
}

// round 11
// speedup vs baseline: 4.2770x; 1.0595x over previous
#include <cuda_runtime.h>
#include <cuda_fp16.h>
#include <math.h>
#include <math_constants.h>
#include <cstdint>

#define L_DIM 2048
#define S_DIM 2048
#define B_DIM 2
#define E_DIM 1024
#define H_DIM 16
#define HD    64
#define M_ROWS (L_DIM * B_DIM)   // 4096

// ============================ helpers ============================
__device__ __forceinline__ uint32_t smem_to_u32(const void* p) {
    uint32_t a;
    asm("{ .reg .u64 t; cvta.to.shared.u64 t, %1; cvt.u32.u64 %0, t; }" : "=r"(a) : "l"(p));
    return a;
}
__device__ __forceinline__ void cp_async16(uint32_t dst, const void* src) {
    asm volatile("cp.async.cg.shared.global [%0], [%1], 16;" :: "r"(dst), "l"(src));
}
#define CP_COMMIT() asm volatile("cp.async.commit_group;" ::: "memory")
#define CP_WAIT(n)  asm volatile("cp.async.wait_group %0;" :: "n"(n) : "memory")

__device__ __forceinline__ void ldmatrix_x4(uint32_t& r0, uint32_t& r1,
                                            uint32_t& r2, uint32_t& r3, uint32_t addr) {
    asm volatile("ldmatrix.sync.aligned.m8n8.x4.shared.b16 {%0,%1,%2,%3}, [%4];"
                 : "=r"(r0), "=r"(r1), "=r"(r2), "=r"(r3) : "r"(addr));
}
__device__ __forceinline__ void ldmatrix_x4_trans(uint32_t& r0, uint32_t& r1,
                                                  uint32_t& r2, uint32_t& r3, uint32_t addr) {
    asm volatile("ldmatrix.sync.aligned.m8n8.x4.trans.shared.b16 {%0,%1,%2,%3}, [%4];"
                 : "=r"(r0), "=r"(r1), "=r"(r2), "=r"(r3) : "r"(addr));
}
__device__ __forceinline__ void mma_f16(float* d, const uint32_t* a, const uint32_t* b) {
    asm volatile(
        "mma.sync.aligned.m16n8k16.row.col.f32.f16.f16.f32 "
        "{%0,%1,%2,%3}, {%4,%5,%6,%7}, {%8,%9}, {%0,%1,%2,%3};"
        : "+f"(d[0]), "+f"(d[1]), "+f"(d[2]), "+f"(d[3])
        : "r"(a[0]), "r"(a[1]), "r"(a[2]), "r"(a[3]), "r"(b[0]), "r"(b[1]));
}
__device__ __forceinline__ uint32_t packh2(float lo, float hi) {
    __half2 h = __floats2half2_rn(lo, hi);
    return *(uint32_t*)&h;
}
__device__ __forceinline__ uint32_t packresh2(float lo, float hi) {
    float rl = lo - __half2float(__float2half_rn(lo));
    float rh = hi - __half2float(__float2half_rn(hi));
    return packh2(rl, rh);
}

// ============================ scratch ============================
#define ACT_SZ ((size_t)M_ROWS * E_DIM)
#define W_SZ   ((size_t)E_DIM * E_DIM)
__device__ __half g_aq_h[ACT_SZ], g_aq_l[ACT_SZ];
__device__ __half g_ak_h[ACT_SZ], g_ak_l[ACT_SZ];
__device__ __half g_av_h[ACT_SZ], g_av_l[ACT_SZ];
__device__ __half g_wq_h[W_SZ], g_wk_h[W_SZ], g_wv_h[W_SZ], g_wo_h[W_SZ];
#define BHTD ((size_t)B_DIM * H_DIM * L_DIM * HD)
__device__ __half g_Qh[BHTD], g_Ql[BHTD];
__device__ __half g_Kh[BHTD];
__device__ __half g_Vh[BHTD];

// ==================== fused fp32 -> fp16 hi(/lo) split ====================
__global__ void __launch_bounds__(256)
split_all(const float* __restrict__ q,  const float* __restrict__ k,
          const float* __restrict__ v,  const float* __restrict__ wq,
          const float* __restrict__ wk, const float* __restrict__ wv,
          const float* __restrict__ wo,
          __half* aqh, __half* aql, __half* akh, __half* akl,
          __half* avh, __half* avl,
          __half* wqh, __half* wkh, __half* wvh, __half* woh)
{
    const int j = blockIdx.y;
    const float* src = (j == 0) ? q : (j == 1) ? k : (j == 2) ? v
                     : (j == 3) ? wq : (j == 4) ? wk : (j == 5) ? wv : wo;
    __half* hi = (j == 0) ? aqh : (j == 1) ? akh : (j == 2) ? avh
               : (j == 3) ? wqh : (j == 4) ? wkh : (j == 5) ? wvh : woh;
    __half* lo = (j == 0) ? aql : (j == 1) ? akl : avl;
    const int reps = (j < 3) ? 4 : 1;

    for (int r = 0; r < reps; r++) {
        int i = (r * 1024 + blockIdx.x) * 256 + threadIdx.x;
        float4 vv = ((const float4*)src)[i];
        uint2 uh = {packh2(vv.x, vv.y), packh2(vv.z, vv.w)};
        ((uint2*)hi)[i] = uh;
        if (j < 3) {
            uint2 ul = {packresh2(vv.x, vv.y), packresh2(vv.z, vv.w)};
            ((uint2*)lo)[i] = ul;
        }
    }
}

// ==================== GEMM core (BK=64, fp16 2-pass, double buffer) ==========
#define BK        64
#define ROW_PADB  72                          // fp16 pitch 144 B (128B data + 16 pad)
#define TILE_B    (128 * ROW_PADB * 2)        // 18432
#define STAGE_B   (3 * TILE_B)                // 55296 (Ah, Al, Wh)
#define GEMM_SMEM (2 * STAGE_B)               // 110592; x2 CTA = 221184 <= 228KB
#define NCHUNK    (E_DIM / BK)                // 16

__device__ __forceinline__ void gemm_core(
    const __half* __restrict__ Ah, const __half* __restrict__ Al,
    const __half* __restrict__ Wh,
    uint32_t sb, int m0, int n0, int tid, float acc[2][8][4])
{
    const int wid  = tid >> 5;
    const int lane = tid & 31;
    const int wm = (wid & 3) * 32;
    const int wn = (wid >> 2) * 64;

    const __half* gsrc[3] = {Ah, Al, Wh};

    auto prefetch = [&](int c, int buf) {
        const int k0 = c * BK;
#pragma unroll
        for (int it = 0; it < 12; it++) {
            int idx  = it * 256 + tid;        // 0..3071
            int tile = idx >> 10;             // 0..2
            int i    = idx & 1023;
            int row  = i >> 3;                // 0..127
            int ch   = i & 7;                 // 16B chunk (8 per row)
            int grow = (tile < 2 ? m0 : n0) + row;
            const __half* gp = gsrc[tile] + (size_t)grow * E_DIM + k0 + ch * 8;
            uint32_t dst = sb + buf * STAGE_B + tile * TILE_B + row * (ROW_PADB * 2) + ch * 16;
            cp_async16(dst, gp);
        }
        CP_COMMIT();
    };

    prefetch(0, 0);

    const int arow = lane & 15;
    const int akh  = (lane >> 4) * 8;
    const int bg = lane >> 3;
    const int br = lane & 7;

    for (int c = 0; c < NCHUNK; c++) {
        const int buf = c & 1;
        CP_WAIT(0);
        __syncthreads();
        if (c + 1 < NCHUNK) prefetch(c + 1, buf ^ 1);

        const uint32_t st = sb + buf * STAGE_B;
#pragma unroll
        for (int ks = 0; ks < 4; ks++) {
            const int kb = ks * 16;
            uint32_t ah[2][4], al[2][4];
#pragma unroll
            for (int mi = 0; mi < 2; mi++) {
                uint32_t addr = st +
                    (wm + mi * 16 + arow) * (ROW_PADB * 2) + (kb + akh) * 2;
                ldmatrix_x4(ah[mi][0], ah[mi][1], ah[mi][2], ah[mi][3], addr);
                addr += TILE_B;
                ldmatrix_x4(al[mi][0], al[mi][1], al[mi][2], al[mi][3], addr);
            }
            uint32_t bhv[8][2];
#pragma unroll
            for (int nq = 0; nq < 4; nq++) {
                uint32_t addr = st + 2 * TILE_B +
                    (wn + nq * 16 + (bg >> 1) * 8 + br) * (ROW_PADB * 2) + (kb + (bg & 1) * 8) * 2;
                uint32_t r0, r1, r2, r3;
                ldmatrix_x4(r0, r1, r2, r3, addr);
                bhv[2 * nq][0] = r0; bhv[2 * nq][1] = r1;
                bhv[2 * nq + 1][0] = r2; bhv[2 * nq + 1][1] = r3;
            }
#pragma unroll
            for (int mi = 0; mi < 2; mi++)
#pragma unroll
                for (int ni = 0; ni < 8; ni++)
                    mma_f16(acc[mi][ni], ah[mi], bhv[ni]);   // hi pass
#pragma unroll
            for (int mi = 0; mi < 2; mi++)
#pragma unroll
                for (int ni = 0; ni < 8; ni++)
                    mma_f16(acc[mi][ni], al[mi], bhv[ni]);   // lo pass
        }
    }
}

// ---- batched QKV projection: z=0 Q(+rope, hi+lo out), z=1 K(+rope, hi), z=2 V(hi) ----
__global__ void __launch_bounds__(256, 2)
mma_gemm_qkv(const __half* __restrict__ aqh, const __half* __restrict__ aql,
             const __half* __restrict__ akh, const __half* __restrict__ akl,
             const __half* __restrict__ avh, const __half* __restrict__ avl,
             const __half* __restrict__ wqh, const __half* __restrict__ wkh,
             const __half* __restrict__ wvh,
             const float* __restrict__ bq, const float* __restrict__ bk,
             const float* __restrict__ bv,
             __half* __restrict__ qh, __half* __restrict__ ql,
             __half* __restrict__ kh, __half* __restrict__ vh)
{
    extern __shared__ char smem[];
    const uint32_t sb = smem_to_u32(smem);
    const int tid = threadIdx.x;
    const int z = blockIdx.z;
    const int m0 = blockIdx.y * 128;
    const int n0 = blockIdx.x * 128;

    const __half* Ah = (z == 0) ? aqh : (z == 1) ? akh : avh;
    const __half* Al = (z == 0) ? aql : (z == 1) ? akl : avl;
    const __half* Wh = (z == 0) ? wqh : (z == 1) ? wkh : wvh;
    const float* bias = (z == 0) ? bq : (z == 1) ? bk : bv;
    __half* outh = (z == 0) ? qh : (z == 1) ? kh : vh;
    const bool rope = (z != 2);

    float acc[2][8][4];
#pragma unroll
    for (int mi = 0; mi < 2; mi++)
#pragma unroll
        for (int ni = 0; ni < 8; ni++)
#pragma unroll
            for (int q = 0; q < 4; q++) acc[mi][ni][q] = 0.0f;

    gemm_core(Ah, Al, Wh, sb, m0, n0, tid, acc);

    const int wid  = tid >> 5;
    const int lane = tid & 31;
    const int wm = (wid & 3) * 32;
    const int wn = (wid >> 2) * 64;
    const int cbase = n0 + wn + (lane & 3) * 2;
#pragma unroll
    for (int ni = 0; ni < 8; ni++) {
        const int c = cbase + ni * 8;
        const float b0 = bias[c], b1 = bias[c + 1];
        float freq = 0.0f;
        if (rope) {
            int d = c & (HD - 1);
            freq = powf(10000.0f, -(float)d / (float)HD);
        }
        const int h    = c >> 6;
        const int dcol = c & (HD - 1);
#pragma unroll
        for (int mi = 0; mi < 2; mi++) {
#pragma unroll
            for (int rg = 0; rg < 2; rg++) {
                int m = m0 + wm + mi * 16 + (lane >> 2) + rg * 8;
                float v0 = acc[mi][ni][2 * rg] + b0;
                float v1 = acc[mi][ni][2 * rg + 1] + b1;
                int l  = m >> 1;
                int bb = m & 1;
                if (rope) {
                    float sv, cv;
                    sincosf((float)l * freq, &sv, &cv);
                    float x1 = v0, x2 = v1;
                    v0 = x1 * cv - x2 * sv;
                    v1 = x1 * sv + x2 * cv;
                }
                size_t idx = (((size_t)bb * H_DIM + h) * L_DIM + l) * HD + dcol;
                *(uint32_t*)(outh + idx) = packh2(v0, v1);
                if (z == 0)
                    *(uint32_t*)(ql + idx) = packresh2(v0, v1);
            }
        }
    }
}

// ---- output projection: fp32 out[m*E+n] ----
__global__ void __launch_bounds__(256, 2)
mma_gemm_o(const __half* __restrict__ Ah, const __half* __restrict__ Al,
           const __half* __restrict__ Wh,
           const float* __restrict__ bias, float* __restrict__ outf)
{
    extern __shared__ char smem[];
    const uint32_t sb = smem_to_u32(smem);
    const int tid = threadIdx.x;
    const int m0 = blockIdx.y * 128;
    const int n0 = blockIdx.x * 128;

    float acc[2][8][4];
#pragma unroll
    for (int mi = 0; mi < 2; mi++)
#pragma unroll
        for (int ni = 0; ni < 8; ni++)
#pragma unroll
            for (int q = 0; q < 4; q++) acc[mi][ni][q] = 0.0f;

    gemm_core(Ah, Al, Wh, sb, m0, n0, tid, acc);

    const int wid  = tid >> 5;
    const int lane = tid & 31;
    const int wm = (wid & 3) * 32;
    const int wn = (wid >> 2) * 64;
    const int cbase = n0 + wn + (lane & 3) * 2;
#pragma unroll
    for (int ni = 0; ni < 8; ni++) {
        const int c = cbase + ni * 8;
        const float b0 = bias[c], b1 = bias[c + 1];
#pragma unroll
        for (int mi = 0; mi < 2; mi++) {
#pragma unroll
            for (int rg = 0; rg < 2; rg++) {
                int m = m0 + wm + mi * 16 + (lane >> 2) + rg * 8;
                float2 r = {acc[mi][ni][2 * rg] + b0, acc[mi][ni][2 * rg + 1] + b1};
                *(float2*)(outf + (size_t)m * E_DIM + c) = r;
            }
        }
    }
}

// ==================== flash attention (fp16 2-pass, 3-stage KV ring) ====================
#define FA_ROWB   144
#define FA_QTILE  (128 * FA_ROWB)              // 18432
#define FA_KVTILE (64 * FA_ROWB)               // 9216
#define FA_STAGE  (2 * FA_KVTILE)              // Kh, Vh = 18432
#define FA_SMEM   (2 * FA_QTILE + 3 * FA_STAGE)  // 92160
#define FA_NC     (S_DIM / 64)

__global__ void __launch_bounds__(256, 2)
flash_attn_mma(const __half* __restrict__ Qh_g, const __half* __restrict__ Ql_g,
               const __half* __restrict__ Kh_g, const __half* __restrict__ Vh_g,
               const unsigned char* __restrict__ mask,
               __half* __restrict__ Oh_g, __half* __restrict__ Ol_g)
{
    extern __shared__ char smem[];
    const uint32_t sb = smem_to_u32(smem);
    const int tid = threadIdx.x, lane = tid & 31, wid = tid >> 5;
    const int bh = blockIdx.y, b = bh >> 4, h = bh & 15;
    const int l0 = blockIdx.x * 128;
    const int wm = wid * 16;

    const size_t goff = (size_t)bh * L_DIM * HD;

    const __half* qsrc[2] = {Qh_g + goff, Ql_g + goff};
#pragma unroll
    for (int it = 0; it < 8; it++) {
        int idx = it * 256 + tid;
        int tile = idx >> 10, i = idx & 1023, row = i >> 3, ch = i & 7;
        cp_async16(sb + tile * FA_QTILE + row * FA_ROWB + ch * 16,
                   qsrc[tile] + (size_t)(l0 + row) * HD + ch * 8);
    }

    const __half* kvsrc[2] = {Kh_g + goff, Vh_g + goff};
    const uint32_t kvbase = sb + 2 * FA_QTILE;
    auto prefetch_kv = [&](int c, int buf) {
        int s0 = c * 64;
#pragma unroll
        for (int it = 0; it < 4; it++) {
            int idx = it * 256 + tid;
            int tile = idx >> 9, i = idx & 511, row = i >> 3, ch = i & 7;
            cp_async16(kvbase + buf * FA_STAGE + tile * FA_KVTILE + row * FA_ROWB + ch * 16,
                       kvsrc[tile] + (size_t)(s0 + row) * HD + ch * 8);
        }
        CP_COMMIT();
    };
    prefetch_kv(0, 0);
    prefetch_kv(1, 1);

    float o_acc[8][4];
#pragma unroll
    for (int ni = 0; ni < 8; ni++)
#pragma unroll
        for (int q = 0; q < 4; q++) o_acc[ni][q] = 0.0f;
    float mi0 = -CUDART_INF_F, mi1 = -CUDART_INF_F, li0 = 0.0f, li1 = 0.0f;

    const int arow = lane & 15, akh = (lane >> 4) * 8;
    const int bg = lane >> 3, br = lane & 7;
    const int brow_off = (bg >> 1) * 8 + br;
    const int bk_off   = (bg & 1) * 8;
    const int trow_off = ((lane >> 3) & 1) * 8 + (lane & 7);
    const int tcol_off = (lane >> 4) * 8;
    const float scale2 = 0.125f * 1.4426950408889634f;

    uint32_t qfh[4][4], qfl[4][4];

    for (int c = 0; c < FA_NC; c++) {
        const int buf = c % 3;

        const int s0c = c * 64;
        uchar2 mk[8];
#pragma unroll
        for (int ni = 0; ni < 8; ni++)
            mk[ni] = *(const uchar2*)(mask + (size_t)b * S_DIM + s0c + ni * 8 + (lane & 3) * 2);

        if (c + 1 < FA_NC) CP_WAIT(1); else CP_WAIT(0);
        __syncthreads();
        if (c + 2 < FA_NC) prefetch_kv(c + 2, (c + 2) % 3);

        if (c == 0) {
#pragma unroll
            for (int ks = 0; ks < 4; ks++) {
                uint32_t qaddr = sb + (wm + arow) * FA_ROWB + (ks * 16 + akh) * 2;
                ldmatrix_x4(qfh[ks][0], qfh[ks][1], qfh[ks][2], qfh[ks][3], qaddr);
                ldmatrix_x4(qfl[ks][0], qfl[ks][1], qfl[ks][2], qfl[ks][3], qaddr + FA_QTILE);
            }
        }

        const uint32_t sK = kvbase + buf * FA_STAGE;
        const uint32_t sV = sK + FA_KVTILE;

        float s[8][4];
#pragma unroll
        for (int ni = 0; ni < 8; ni++)
#pragma unroll
            for (int q = 0; q < 4; q++) s[ni][q] = 0.0f;

#pragma unroll
        for (int ks = 0; ks < 4; ks++) {
            const int kb = ks * 16;
#pragma unroll
            for (int nq = 0; nq < 4; nq++) {
                uint32_t kaddr = sK + (nq * 16 + brow_off) * FA_ROWB + (kb + bk_off) * 2;
                uint32_t k0, k1, k2, k3;
                ldmatrix_x4(k0, k1, k2, k3, kaddr);
                uint32_t kh0[2] = {k0, k1}, kh1[2] = {k2, k3};
                mma_f16(s[2 * nq],     qfh[ks], kh0);
                mma_f16(s[2 * nq + 1], qfh[ks], kh1);
                mma_f16(s[2 * nq],     qfl[ks], kh0);
                mma_f16(s[2 * nq + 1], qfl[ks], kh1);
            }
        }

        float mlo = -CUDART_INF_F, mhi = -CUDART_INF_F;
#pragma unroll
        for (int ni = 0; ni < 8; ni++) {
            float v0 = mk[ni].x ? -CUDART_INF_F : s[ni][0] * scale2;
            float v1 = mk[ni].y ? -CUDART_INF_F : s[ni][1] * scale2;
            float v2 = mk[ni].x ? -CUDART_INF_F : s[ni][2] * scale2;
            float v3 = mk[ni].y ? -CUDART_INF_F : s[ni][3] * scale2;
            s[ni][0] = v0; s[ni][1] = v1; s[ni][2] = v2; s[ni][3] = v3;
            mlo = fmaxf(mlo, fmaxf(v0, v1));
            mhi = fmaxf(mhi, fmaxf(v2, v3));
        }
        mlo = fmaxf(mlo, __shfl_xor_sync(0xffffffffu, mlo, 1));
        mlo = fmaxf(mlo, __shfl_xor_sync(0xffffffffu, mlo, 2));
        mhi = fmaxf(mhi, __shfl_xor_sync(0xffffffffu, mhi, 1));
        mhi = fmaxf(mhi, __shfl_xor_sync(0xffffffffu, mhi, 2));

        float mn0 = fmaxf(mi0, mlo), mn1 = fmaxf(mi1, mhi);
        float a0 = exp2f(mi0 - mn0), a1 = exp2f(mi1 - mn1);
        float ps0 = 0.0f, ps1 = 0.0f;
#pragma unroll
        for (int ni = 0; ni < 8; ni++) {
            float p0 = exp2f(s[ni][0] - mn0);
            float p1 = exp2f(s[ni][1] - mn0);
            float p2 = exp2f(s[ni][2] - mn1);
            float p3 = exp2f(s[ni][3] - mn1);
            s[ni][0] = p0; s[ni][1] = p1; s[ni][2] = p2; s[ni][3] = p3;
            ps0 += p0 + p1;
            ps1 += p2 + p3;
        }
        ps0 += __shfl_xor_sync(0xffffffffu, ps0, 1);
        ps0 += __shfl_xor_sync(0xffffffffu, ps0, 2);
        ps1 += __shfl_xor_sync(0xffffffffu, ps1, 1);
        ps1 += __shfl_xor_sync(0xffffffffu, ps1, 2);
        li0 = li0 * a0 + ps0;
        li1 = li1 * a1 + ps1;
        mi0 = mn0; mi1 = mn1;
#pragma unroll
        for (int ni = 0; ni < 8; ni++) {
            o_acc[ni][0] *= a0; o_acc[ni][1] *= a0;
            o_acc[ni][2] *= a1; o_acc[ni][3] *= a1;
        }

#pragma unroll
        for (int ks = 0; ks < 4; ks++) {
            uint32_t pah[4], pal[4];
            pah[0] = packh2(s[2 * ks][0],     s[2 * ks][1]);
            pah[1] = packh2(s[2 * ks][2],     s[2 * ks][3]);
            pah[2] = packh2(s[2 * ks + 1][0], s[2 * ks + 1][1]);
            pah[3] = packh2(s[2 * ks + 1][2], s[2 * ks + 1][3]);
            pal[0] = packresh2(s[2 * ks][0],     s[2 * ks][1]);
            pal[1] = packresh2(s[2 * ks][2],     s[2 * ks][3]);
            pal[2] = packresh2(s[2 * ks + 1][0], s[2 * ks + 1][1]);
            pal[3] = packresh2(s[2 * ks + 1][2], s[2 * ks + 1][3]);
#pragma unroll
            for (int nb = 0; nb < 4; nb++) {
                uint32_t vaddr = sV + (ks * 16 + trow_off) * FA_ROWB + (nb * 16 + tcol_off) * 2;
                uint32_t v0, v1, v2, v3;
                ldmatrix_x4_trans(v0, v1, v2, v3, vaddr);
                uint32_t vh0[2] = {v0, v1}, vh1[2] = {v2, v3};
                mma_f16(o_acc[2 * nb],     pah, vh0);
                mma_f16(o_acc[2 * nb + 1], pah, vh1);
                mma_f16(o_acc[2 * nb],     pal, vh0);
                mma_f16(o_acc[2 * nb + 1], pal, vh1);
            }
        }
    }

    const float inv0 = 1.0f / li0, inv1 = 1.0f / li1;
    const int r0 = lane >> 2;
    const int m0g = ((l0 + wm + r0) << 1) | b;
    const int m1g = ((l0 + wm + r0 + 8) << 1) | b;
#pragma unroll
    for (int ni = 0; ni < 8; ni++) {
        int cg = h * HD + ni * 8 + (lane & 3) * 2;
        float v00 = o_acc[ni][0] * inv0, v01 = o_acc[ni][1] * inv0;
        float v10 = o_acc[ni][2] * inv1, v11 = o_acc[ni][3] * inv1;
        *(uint32_t*)(Oh_g + (size_t)m0g * E_DIM + cg) = packh2(v00, v01);
        *(uint32_t*)(Ol_g + (size_t)m0g * E_DIM + cg) = packresh2(v00, v01);
        *(uint32_t*)(Oh_g + (size_t)m1g * E_DIM + cg) = packh2(v10, v11);
        *(uint32_t*)(Ol_g + (size_t)m1g * E_DIM + cg) = packresh2(v10, v11);
    }
}

// ============================================================================
// launch
// ============================================================================
extern "C" void kernel_launch(void* const* d_in, const int* in_sizes, int n_in,
                              void* d_out, int out_size)
{
    const float* query = (const float*)d_in[0];
    const float* key   = (const float*)d_in[1];
    const float* value = (const float*)d_in[2];
    const unsigned char* mask = (const unsigned char*)d_in[3];
    const float* Wq = (const float*)d_in[4];
    const float* bq = (const float*)d_in[5];
    const float* Wk = (const float*)d_in[6];
    const float* bk = (const float*)d_in[7];
    const float* Wv = (const float*)d_in[8];
    const float* bv = (const float*)d_in[9];
    const float* Wo = (const float*)d_in[10];
    const float* bo = (const float*)d_in[11];
    float* out = (float*)d_out;

    __half *aqh, *aql, *akh, *akl, *avh, *avl;
    __half *wqh, *wkh, *wvh, *woh;
    __half *qh, *ql, *kh, *vh;
    cudaGetSymbolAddress((void**)&aqh, g_aq_h); cudaGetSymbolAddress((void**)&aql, g_aq_l);
    cudaGetSymbolAddress((void**)&akh, g_ak_h); cudaGetSymbolAddress((void**)&akl, g_ak_l);
    cudaGetSymbolAddress((void**)&avh, g_av_h); cudaGetSymbolAddress((void**)&avl, g_av_l);
    cudaGetSymbolAddress((void**)&wqh, g_wq_h); cudaGetSymbolAddress((void**)&wkh, g_wk_h);
    cudaGetSymbolAddress((void**)&wvh, g_wv_h); cudaGetSymbolAddress((void**)&woh, g_wo_h);
    cudaGetSymbolAddress((void**)&qh, g_Qh); cudaGetSymbolAddress((void**)&ql, g_Ql);
    cudaGetSymbolAddress((void**)&kh, g_Kh); cudaGetSymbolAddress((void**)&vh, g_Vh);

    cudaFuncSetAttribute(mma_gemm_qkv, cudaFuncAttributeMaxDynamicSharedMemorySize, GEMM_SMEM);
    cudaFuncSetAttribute(mma_gemm_o,   cudaFuncAttributeMaxDynamicSharedMemorySize, GEMM_SMEM);
    cudaFuncSetAttribute(flash_attn_mma, cudaFuncAttributeMaxDynamicSharedMemorySize, FA_SMEM);

    // one fused split launch (activations hi+lo, weights hi)
    dim3 sgrid(1024, 7);
    split_all<<<sgrid, 256>>>(query, key, value, Wq, Wk, Wv, Wo,
                              aqh, aql, akh, akl, avh, avl,
                              wqh, wkh, wvh, woh);

    // batched QKV projections (+RoPE on Q,K)
    dim3 qkv_grid(E_DIM / 128, M_ROWS / 128, 3);   // (8, 32, 3)
    mma_gemm_qkv<<<qkv_grid, 256, GEMM_SMEM>>>(
        aqh, aql, akh, akl, avh, avl,
        wqh, wkh, wvh, bq, bk, bv, qh, ql, kh, vh);

    // attention -> act hi/lo [m][E] (reuse g_aq buffers)
    dim3 agrid(L_DIM / 128, B_DIM * H_DIM);        // (16, 32)
    flash_attn_mma<<<agrid, 256, FA_SMEM>>>(qh, ql, kh, vh, mask, aqh, aql);

    // output projection -> d_out fp32
    dim3 ogrid(E_DIM / 128, M_ROWS / 128);
    mma_gemm_o<<<ogrid, 256, GEMM_SMEM>>>(aqh, aql, woh, bo, out);
}

// round 12
// speedup vs baseline: 4.6452x; 1.0861x over previous
#include <cuda_runtime.h>
#include <cuda_fp16.h>
#include <math.h>
#include <math_constants.h>
#include <cstdint>

#define L_DIM 2048
#define S_DIM 2048
#define B_DIM 2
#define E_DIM 1024
#define H_DIM 16
#define HD    64
#define M_ROWS (L_DIM * B_DIM)   // 4096

// ============================ helpers ============================
__device__ __forceinline__ uint32_t smem_to_u32(const void* p) {
    uint32_t a;
    asm("{ .reg .u64 t; cvta.to.shared.u64 t, %1; cvt.u32.u64 %0, t; }" : "=r"(a) : "l"(p));
    return a;
}
__device__ __forceinline__ void cp_async16(uint32_t dst, const void* src) {
    asm volatile("cp.async.cg.shared.global [%0], [%1], 16;" :: "r"(dst), "l"(src));
}
#define CP_COMMIT() asm volatile("cp.async.commit_group;" ::: "memory")
#define CP_WAIT(n)  asm volatile("cp.async.wait_group %0;" :: "n"(n) : "memory")

__device__ __forceinline__ void ldmatrix_x4(uint32_t& r0, uint32_t& r1,
                                            uint32_t& r2, uint32_t& r3, uint32_t addr) {
    asm volatile("ldmatrix.sync.aligned.m8n8.x4.shared.b16 {%0,%1,%2,%3}, [%4];"
                 : "=r"(r0), "=r"(r1), "=r"(r2), "=r"(r3) : "r"(addr));
}
__device__ __forceinline__ void ldmatrix_x4_trans(uint32_t& r0, uint32_t& r1,
                                                  uint32_t& r2, uint32_t& r3, uint32_t addr) {
    asm volatile("ldmatrix.sync.aligned.m8n8.x4.trans.shared.b16 {%0,%1,%2,%3}, [%4];"
                 : "=r"(r0), "=r"(r1), "=r"(r2), "=r"(r3) : "r"(addr));
}
__device__ __forceinline__ void mma_f16(float* d, const uint32_t* a, const uint32_t* b) {
    asm volatile(
        "mma.sync.aligned.m16n8k16.row.col.f32.f16.f16.f32 "
        "{%0,%1,%2,%3}, {%4,%5,%6,%7}, {%8,%9}, {%0,%1,%2,%3};"
        : "+f"(d[0]), "+f"(d[1]), "+f"(d[2]), "+f"(d[3])
        : "r"(a[0]), "r"(a[1]), "r"(a[2]), "r"(a[3]), "r"(b[0]), "r"(b[1]));
}
__device__ __forceinline__ uint32_t packh2(float lo, float hi) {
    __half2 h = __floats2half2_rn(lo, hi);
    return *(uint32_t*)&h;
}
__device__ __forceinline__ uint32_t packresh2(float lo, float hi) {
    float rl = lo - __half2float(__float2half_rn(lo));
    float rh = hi - __half2float(__float2half_rn(hi));
    return packh2(rl, rh);
}

// ============================ scratch ============================
#define ACT_SZ ((size_t)M_ROWS * E_DIM)
#define W_SZ   ((size_t)E_DIM * E_DIM)
__device__ __half g_aq_h[ACT_SZ], g_aq_l[ACT_SZ];
__device__ __half g_ak_h[ACT_SZ], g_ak_l[ACT_SZ];
__device__ __half g_av_h[ACT_SZ], g_av_l[ACT_SZ];
__device__ __half g_wq_h[W_SZ], g_wk_h[W_SZ], g_wv_h[W_SZ], g_wo_h[W_SZ];
#define BHTD ((size_t)B_DIM * H_DIM * L_DIM * HD)
__device__ __half g_Qh[BHTD];
__device__ __half g_Kh[BHTD];
__device__ __half g_Vh[BHTD];

// ==================== fused fp32 -> fp16 hi(/lo) split ====================
__global__ void __launch_bounds__(256)
split_all(const float* __restrict__ q,  const float* __restrict__ k,
          const float* __restrict__ v,  const float* __restrict__ wq,
          const float* __restrict__ wk, const float* __restrict__ wv,
          const float* __restrict__ wo,
          __half* aqh, __half* aql, __half* akh, __half* akl,
          __half* avh, __half* avl,
          __half* wqh, __half* wkh, __half* wvh, __half* woh)
{
    const int j = blockIdx.y;
    const float* src = (j == 0) ? q : (j == 1) ? k : (j == 2) ? v
                     : (j == 3) ? wq : (j == 4) ? wk : (j == 5) ? wv : wo;
    __half* hi = (j == 0) ? aqh : (j == 1) ? akh : (j == 2) ? avh
               : (j == 3) ? wqh : (j == 4) ? wkh : (j == 5) ? wvh : woh;
    __half* lo = (j == 0) ? aql : (j == 1) ? akl : avl;
    const int reps = (j < 3) ? 4 : 1;

    for (int r = 0; r < reps; r++) {
        int i = (r * 1024 + blockIdx.x) * 256 + threadIdx.x;
        float4 vv = ((const float4*)src)[i];
        uint2 uh = {packh2(vv.x, vv.y), packh2(vv.z, vv.w)};
        ((uint2*)hi)[i] = uh;
        if (j < 3) {
            uint2 ul = {packresh2(vv.x, vv.y), packresh2(vv.z, vv.w)};
            ((uint2*)lo)[i] = ul;
        }
    }
}

// ==================== GEMM core (BK=64, fp16 2-pass, double buffer) ==========
#define BK        64
#define ROW_PADB  72                          // fp16 pitch 144 B
#define TILE_B    (128 * ROW_PADB * 2)        // 18432
#define STAGE_B   (3 * TILE_B)                // 55296 (Ah, Al, Wh)
#define GEMM_SMEM (2 * STAGE_B)               // 110592; x2 CTA = 221184
#define NCHUNK    (E_DIM / BK)                // 16

__device__ __forceinline__ void gemm_core(
    const __half* __restrict__ Ah, const __half* __restrict__ Al,
    const __half* __restrict__ Wh,
    uint32_t sb, int m0, int n0, int tid, float acc[2][8][4])
{
    const int wid  = tid >> 5;
    const int lane = tid & 31;
    const int wm = (wid & 3) * 32;
    const int wn = (wid >> 2) * 64;

    const __half* gsrc[3] = {Ah, Al, Wh};

    auto prefetch = [&](int c, int buf) {
        const int k0 = c * BK;
#pragma unroll
        for (int it = 0; it < 12; it++) {
            int idx  = it * 256 + tid;
            int tile = idx >> 10;
            int i    = idx & 1023;
            int row  = i >> 3;
            int ch   = i & 7;
            int grow = (tile < 2 ? m0 : n0) + row;
            const __half* gp = gsrc[tile] + (size_t)grow * E_DIM + k0 + ch * 8;
            uint32_t dst = sb + buf * STAGE_B + tile * TILE_B + row * (ROW_PADB * 2) + ch * 16;
            cp_async16(dst, gp);
        }
        CP_COMMIT();
    };

    prefetch(0, 0);

    const int arow = lane & 15;
    const int akh  = (lane >> 4) * 8;
    const int bg = lane >> 3;
    const int br = lane & 7;

    for (int c = 0; c < NCHUNK; c++) {
        const int buf = c & 1;
        CP_WAIT(0);
        __syncthreads();
        if (c + 1 < NCHUNK) prefetch(c + 1, buf ^ 1);

        const uint32_t st = sb + buf * STAGE_B;
#pragma unroll
        for (int ks = 0; ks < 4; ks++) {
            const int kb = ks * 16;
            uint32_t ah[2][4], al[2][4];
#pragma unroll
            for (int mi = 0; mi < 2; mi++) {
                uint32_t addr = st +
                    (wm + mi * 16 + arow) * (ROW_PADB * 2) + (kb + akh) * 2;
                ldmatrix_x4(ah[mi][0], ah[mi][1], ah[mi][2], ah[mi][3], addr);
                addr += TILE_B;
                ldmatrix_x4(al[mi][0], al[mi][1], al[mi][2], al[mi][3], addr);
            }
            uint32_t bhv[8][2];
#pragma unroll
            for (int nq = 0; nq < 4; nq++) {
                uint32_t addr = st + 2 * TILE_B +
                    (wn + nq * 16 + (bg >> 1) * 8 + br) * (ROW_PADB * 2) + (kb + (bg & 1) * 8) * 2;
                uint32_t r0, r1, r2, r3;
                ldmatrix_x4(r0, r1, r2, r3, addr);
                bhv[2 * nq][0] = r0; bhv[2 * nq][1] = r1;
                bhv[2 * nq + 1][0] = r2; bhv[2 * nq + 1][1] = r3;
            }
#pragma unroll
            for (int mi = 0; mi < 2; mi++)
#pragma unroll
                for (int ni = 0; ni < 8; ni++)
                    mma_f16(acc[mi][ni], ah[mi], bhv[ni]);   // hi pass
#pragma unroll
            for (int mi = 0; mi < 2; mi++)
#pragma unroll
                for (int ni = 0; ni < 8; ni++)
                    mma_f16(acc[mi][ni], al[mi], bhv[ni]);   // lo pass
        }
    }
}

// ---- batched QKV projection: z=0 Q(+rope), z=1 K(+rope), z=2 V; all hi-only out ----
__global__ void __launch_bounds__(256, 2)
mma_gemm_qkv(const __half* __restrict__ aqh, const __half* __restrict__ aql,
             const __half* __restrict__ akh, const __half* __restrict__ akl,
             const __half* __restrict__ avh, const __half* __restrict__ avl,
             const __half* __restrict__ wqh, const __half* __restrict__ wkh,
             const __half* __restrict__ wvh,
             const float* __restrict__ bq, const float* __restrict__ bk,
             const float* __restrict__ bv,
             __half* __restrict__ qh, __half* __restrict__ kh, __half* __restrict__ vh)
{
    extern __shared__ char smem[];
    const uint32_t sb = smem_to_u32(smem);
    const int tid = threadIdx.x;
    const int z = blockIdx.z;
    const int m0 = blockIdx.y * 128;
    const int n0 = blockIdx.x * 128;

    const __half* Ah = (z == 0) ? aqh : (z == 1) ? akh : avh;
    const __half* Al = (z == 0) ? aql : (z == 1) ? akl : avl;
    const __half* Wh = (z == 0) ? wqh : (z == 1) ? wkh : wvh;
    const float* bias = (z == 0) ? bq : (z == 1) ? bk : bv;
    __half* outh = (z == 0) ? qh : (z == 1) ? kh : vh;
    const bool rope = (z != 2);

    float acc[2][8][4];
#pragma unroll
    for (int mi = 0; mi < 2; mi++)
#pragma unroll
        for (int ni = 0; ni < 8; ni++)
#pragma unroll
            for (int q = 0; q < 4; q++) acc[mi][ni][q] = 0.0f;

    gemm_core(Ah, Al, Wh, sb, m0, n0, tid, acc);

    const int wid  = tid >> 5;
    const int lane = tid & 31;
    const int wm = (wid & 3) * 32;
    const int wn = (wid >> 2) * 64;
    const int cbase = n0 + wn + (lane & 3) * 2;
#pragma unroll
    for (int ni = 0; ni < 8; ni++) {
        const int c = cbase + ni * 8;
        const float b0 = bias[c], b1 = bias[c + 1];
        float freq = 0.0f;
        if (rope) {
            int d = c & (HD - 1);
            freq = powf(10000.0f, -(float)d / (float)HD);
        }
        const int h    = c >> 6;
        const int dcol = c & (HD - 1);
#pragma unroll
        for (int mi = 0; mi < 2; mi++) {
#pragma unroll
            for (int rg = 0; rg < 2; rg++) {
                int m = m0 + wm + mi * 16 + (lane >> 2) + rg * 8;
                float v0 = acc[mi][ni][2 * rg] + b0;
                float v1 = acc[mi][ni][2 * rg + 1] + b1;
                int l  = m >> 1;
                int bb = m & 1;
                if (rope) {
                    float sv, cv;
                    sincosf((float)l * freq, &sv, &cv);
                    float x1 = v0, x2 = v1;
                    v0 = x1 * cv - x2 * sv;
                    v1 = x1 * sv + x2 * cv;
                }
                size_t idx = (((size_t)bb * H_DIM + h) * L_DIM + l) * HD + dcol;
                *(uint32_t*)(outh + idx) = packh2(v0, v1);
            }
        }
    }
}

// ---- output projection: fp32 out[m*E+n] ----
__global__ void __launch_bounds__(256, 2)
mma_gemm_o(const __half* __restrict__ Ah, const __half* __restrict__ Al,
           const __half* __restrict__ Wh,
           const float* __restrict__ bias, float* __restrict__ outf)
{
    extern __shared__ char smem[];
    const uint32_t sb = smem_to_u32(smem);
    const int tid = threadIdx.x;
    const int m0 = blockIdx.y * 128;
    const int n0 = blockIdx.x * 128;

    float acc[2][8][4];
#pragma unroll
    for (int mi = 0; mi < 2; mi++)
#pragma unroll
        for (int ni = 0; ni < 8; ni++)
#pragma unroll
            for (int q = 0; q < 4; q++) acc[mi][ni][q] = 0.0f;

    gemm_core(Ah, Al, Wh, sb, m0, n0, tid, acc);

    const int wid  = tid >> 5;
    const int lane = tid & 31;
    const int wm = (wid & 3) * 32;
    const int wn = (wid >> 2) * 64;
    const int cbase = n0 + wn + (lane & 3) * 2;
#pragma unroll
    for (int ni = 0; ni < 8; ni++) {
        const int c = cbase + ni * 8;
        const float b0 = bias[c], b1 = bias[c + 1];
#pragma unroll
        for (int mi = 0; mi < 2; mi++) {
#pragma unroll
            for (int rg = 0; rg < 2; rg++) {
                int m = m0 + wm + mi * 16 + (lane >> 2) + rg * 8;
                float2 r = {acc[mi][ni][2 * rg] + b0, acc[mi][ni][2 * rg + 1] + b1};
                *(float2*)(outf + (size_t)m * E_DIM + c) = r;
            }
        }
    }
}

// ==================== flash attention (Qh-only GEMM1, Ph+Pl GEMM2) ====================
#define FA_ROWB   144
#define FA_QTILE  (128 * FA_ROWB)              // 18432 (Qh only)
#define FA_KVTILE (64 * FA_ROWB)               // 9216
#define FA_STAGE  (2 * FA_KVTILE)              // 18432
#define FA_SMEM   (FA_QTILE + 3 * FA_STAGE)    // 73728
#define FA_NC     (S_DIM / 64)

__global__ void __launch_bounds__(256, 2)
flash_attn_mma(const __half* __restrict__ Qh_g,
               const __half* __restrict__ Kh_g, const __half* __restrict__ Vh_g,
               const unsigned char* __restrict__ mask,
               __half* __restrict__ Oh_g, __half* __restrict__ Ol_g)
{
    extern __shared__ char smem[];
    const uint32_t sb = smem_to_u32(smem);
    const int tid = threadIdx.x, lane = tid & 31, wid = tid >> 5;
    const int bh = blockIdx.y, b = bh >> 4, h = bh & 15;
    const int l0 = blockIdx.x * 128;
    const int wm = wid * 16;

    const size_t goff = (size_t)bh * L_DIM * HD;

    // Q hi tile only
#pragma unroll
    for (int it = 0; it < 4; it++) {
        int idx = it * 256 + tid;           // 0..1023
        int row = idx >> 3, ch = idx & 7;
        cp_async16(sb + row * FA_ROWB + ch * 16,
                   Qh_g + goff + (size_t)(l0 + row) * HD + ch * 8);
    }

    const __half* kvsrc[2] = {Kh_g + goff, Vh_g + goff};
    const uint32_t kvbase = sb + FA_QTILE;
    auto prefetch_kv = [&](int c, int buf) {
        int s0 = c * 64;
#pragma unroll
        for (int it = 0; it < 4; it++) {
            int idx = it * 256 + tid;
            int tile = idx >> 9, i = idx & 511, row = i >> 3, ch = i & 7;
            cp_async16(kvbase + buf * FA_STAGE + tile * FA_KVTILE + row * FA_ROWB + ch * 16,
                       kvsrc[tile] + (size_t)(s0 + row) * HD + ch * 8);
        }
        CP_COMMIT();
    };
    prefetch_kv(0, 0);   // commits Q loads too
    prefetch_kv(1, 1);

    float o_acc[8][4];
#pragma unroll
    for (int ni = 0; ni < 8; ni++)
#pragma unroll
        for (int q = 0; q < 4; q++) o_acc[ni][q] = 0.0f;
    float mi0 = -CUDART_INF_F, mi1 = -CUDART_INF_F, li0 = 0.0f, li1 = 0.0f;

    const int arow = lane & 15, akh = (lane >> 4) * 8;
    const int bg = lane >> 3, br = lane & 7;
    const int brow_off = (bg >> 1) * 8 + br;
    const int bk_off   = (bg & 1) * 8;
    const int trow_off = ((lane >> 3) & 1) * 8 + (lane & 7);
    const int tcol_off = (lane >> 4) * 8;
    const float scale2 = 0.125f * 1.4426950408889634f;

    uint32_t qfh[4][4];

    for (int c = 0; c < FA_NC; c++) {
        const int buf = c % 3;

        const int s0c = c * 64;
        uchar2 mk[8];
#pragma unroll
        for (int ni = 0; ni < 8; ni++)
            mk[ni] = *(const uchar2*)(mask + (size_t)b * S_DIM + s0c + ni * 8 + (lane & 3) * 2);

        if (c + 1 < FA_NC) CP_WAIT(1); else CP_WAIT(0);
        __syncthreads();
        if (c + 2 < FA_NC) prefetch_kv(c + 2, (c + 2) % 3);

        if (c == 0) {
#pragma unroll
            for (int ks = 0; ks < 4; ks++) {
                uint32_t qaddr = sb + (wm + arow) * FA_ROWB + (ks * 16 + akh) * 2;
                ldmatrix_x4(qfh[ks][0], qfh[ks][1], qfh[ks][2], qfh[ks][3], qaddr);
            }
        }

        const uint32_t sK = kvbase + buf * FA_STAGE;
        const uint32_t sV = sK + FA_KVTILE;

        float s[8][4];
#pragma unroll
        for (int ni = 0; ni < 8; ni++)
#pragma unroll
            for (int q = 0; q < 4; q++) s[ni][q] = 0.0f;

        // GEMM1: S = Qh * Kh^T (single pass)
#pragma unroll
        for (int ks = 0; ks < 4; ks++) {
            const int kb = ks * 16;
#pragma unroll
            for (int nq = 0; nq < 4; nq++) {
                uint32_t kaddr = sK + (nq * 16 + brow_off) * FA_ROWB + (kb + bk_off) * 2;
                uint32_t k0, k1, k2, k3;
                ldmatrix_x4(k0, k1, k2, k3, kaddr);
                uint32_t kh0[2] = {k0, k1}, kh1[2] = {k2, k3};
                mma_f16(s[2 * nq],     qfh[ks], kh0);
                mma_f16(s[2 * nq + 1], qfh[ks], kh1);
            }
        }

        float mlo = -CUDART_INF_F, mhi = -CUDART_INF_F;
#pragma unroll
        for (int ni = 0; ni < 8; ni++) {
            float v0 = mk[ni].x ? -CUDART_INF_F : s[ni][0] * scale2;
            float v1 = mk[ni].y ? -CUDART_INF_F : s[ni][1] * scale2;
            float v2 = mk[ni].x ? -CUDART_INF_F : s[ni][2] * scale2;
            float v3 = mk[ni].y ? -CUDART_INF_F : s[ni][3] * scale2;
            s[ni][0] = v0; s[ni][1] = v1; s[ni][2] = v2; s[ni][3] = v3;
            mlo = fmaxf(mlo, fmaxf(v0, v1));
            mhi = fmaxf(mhi, fmaxf(v2, v3));
        }
        mlo = fmaxf(mlo, __shfl_xor_sync(0xffffffffu, mlo, 1));
        mlo = fmaxf(mlo, __shfl_xor_sync(0xffffffffu, mlo, 2));
        mhi = fmaxf(mhi, __shfl_xor_sync(0xffffffffu, mhi, 1));
        mhi = fmaxf(mhi, __shfl_xor_sync(0xffffffffu, mhi, 2));

        float mn0 = fmaxf(mi0, mlo), mn1 = fmaxf(mi1, mhi);
        float a0 = exp2f(mi0 - mn0), a1 = exp2f(mi1 - mn1);
        float ps0 = 0.0f, ps1 = 0.0f;
#pragma unroll
        for (int ni = 0; ni < 8; ni++) {
            float p0 = exp2f(s[ni][0] - mn0);
            float p1 = exp2f(s[ni][1] - mn0);
            float p2 = exp2f(s[ni][2] - mn1);
            float p3 = exp2f(s[ni][3] - mn1);
            s[ni][0] = p0; s[ni][1] = p1; s[ni][2] = p2; s[ni][3] = p3;
            ps0 += p0 + p1;
            ps1 += p2 + p3;
        }
        ps0 += __shfl_xor_sync(0xffffffffu, ps0, 1);
        ps0 += __shfl_xor_sync(0xffffffffu, ps0, 2);
        ps1 += __shfl_xor_sync(0xffffffffu, ps1, 1);
        ps1 += __shfl_xor_sync(0xffffffffu, ps1, 2);
        li0 = li0 * a0 + ps0;
        li1 = li1 * a1 + ps1;
        mi0 = mn0; mi1 = mn1;
#pragma unroll
        for (int ni = 0; ni < 8; ni++) {
            o_acc[ni][0] *= a0; o_acc[ni][1] *= a0;
            o_acc[ni][2] *= a1; o_acc[ni][3] *= a1;
        }

        // GEMM2: O += (Ph + Pl) * Vh
#pragma unroll
        for (int ks = 0; ks < 4; ks++) {
            uint32_t pah[4], pal[4];
            pah[0] = packh2(s[2 * ks][0],     s[2 * ks][1]);
            pah[1] = packh2(s[2 * ks][2],     s[2 * ks][3]);
            pah[2] = packh2(s[2 * ks + 1][0], s[2 * ks + 1][1]);
            pah[3] = packh2(s[2 * ks + 1][2], s[2 * ks + 1][3]);
            pal[0] = packresh2(s[2 * ks][0],     s[2 * ks][1]);
            pal[1] = packresh2(s[2 * ks][2],     s[2 * ks][3]);
            pal[2] = packresh2(s[2 * ks + 1][0], s[2 * ks + 1][1]);
            pal[3] = packresh2(s[2 * ks + 1][2], s[2 * ks + 1][3]);
#pragma unroll
            for (int nb = 0; nb < 4; nb++) {
                uint32_t vaddr = sV + (ks * 16 + trow_off) * FA_ROWB + (nb * 16 + tcol_off) * 2;
                uint32_t v0, v1, v2, v3;
                ldmatrix_x4_trans(v0, v1, v2, v3, vaddr);
                uint32_t vh0[2] = {v0, v1}, vh1[2] = {v2, v3};
                mma_f16(o_acc[2 * nb],     pah, vh0);
                mma_f16(o_acc[2 * nb + 1], pah, vh1);
                mma_f16(o_acc[2 * nb],     pal, vh0);
                mma_f16(o_acc[2 * nb + 1], pal, vh1);
            }
        }
    }

    const float inv0 = 1.0f / li0, inv1 = 1.0f / li1;
    const int r0 = lane >> 2;
    const int m0g = ((l0 + wm + r0) << 1) | b;
    const int m1g = ((l0 + wm + r0 + 8) << 1) | b;
#pragma unroll
    for (int ni = 0; ni < 8; ni++) {
        int cg = h * HD + ni * 8 + (lane & 3) * 2;
        float v00 = o_acc[ni][0] * inv0, v01 = o_acc[ni][1] * inv0;
        float v10 = o_acc[ni][2] * inv1, v11 = o_acc[ni][3] * inv1;
        *(uint32_t*)(Oh_g + (size_t)m0g * E_DIM + cg) = packh2(v00, v01);
        *(uint32_t*)(Ol_g + (size_t)m0g * E_DIM + cg) = packresh2(v00, v01);
        *(uint32_t*)(Oh_g + (size_t)m1g * E_DIM + cg) = packh2(v10, v11);
        *(uint32_t*)(Ol_g + (size_t)m1g * E_DIM + cg) = packresh2(v10, v11);
    }
}

// ============================================================================
// launch
// ============================================================================
extern "C" void kernel_launch(void* const* d_in, const int* in_sizes, int n_in,
                              void* d_out, int out_size)
{
    const float* query = (const float*)d_in[0];
    const float* key   = (const float*)d_in[1];
    const float* value = (const float*)d_in[2];
    const unsigned char* mask = (const unsigned char*)d_in[3];
    const float* Wq = (const float*)d_in[4];
    const float* bq = (const float*)d_in[5];
    const float* Wk = (const float*)d_in[6];
    const float* bk = (const float*)d_in[7];
    const float* Wv = (const float*)d_in[8];
    const float* bv = (const float*)d_in[9];
    const float* Wo = (const float*)d_in[10];
    const float* bo = (const float*)d_in[11];
    float* out = (float*)d_out;

    __half *aqh, *aql, *akh, *akl, *avh, *avl;
    __half *wqh, *wkh, *wvh, *woh;
    __half *qh, *kh, *vh;
    cudaGetSymbolAddress((void**)&aqh, g_aq_h); cudaGetSymbolAddress((void**)&aql, g_aq_l);
    cudaGetSymbolAddress((void**)&akh, g_ak_h); cudaGetSymbolAddress((void**)&akl, g_ak_l);
    cudaGetSymbolAddress((void**)&avh, g_av_h); cudaGetSymbolAddress((void**)&avl, g_av_l);
    cudaGetSymbolAddress((void**)&wqh, g_wq_h); cudaGetSymbolAddress((void**)&wkh, g_wk_h);
    cudaGetSymbolAddress((void**)&wvh, g_wv_h); cudaGetSymbolAddress((void**)&woh, g_wo_h);
    cudaGetSymbolAddress((void**)&qh, g_Qh);
    cudaGetSymbolAddress((void**)&kh, g_Kh); cudaGetSymbolAddress((void**)&vh, g_Vh);

    cudaFuncSetAttribute(mma_gemm_qkv, cudaFuncAttributeMaxDynamicSharedMemorySize, GEMM_SMEM);
    cudaFuncSetAttribute(mma_gemm_o,   cudaFuncAttributeMaxDynamicSharedMemorySize, GEMM_SMEM);
    cudaFuncSetAttribute(flash_attn_mma, cudaFuncAttributeMaxDynamicSharedMemorySize, FA_SMEM);

    dim3 sgrid(1024, 7);
    split_all<<<sgrid, 256>>>(query, key, value, Wq, Wk, Wv, Wo,
                              aqh, aql, akh, akl, avh, avl,
                              wqh, wkh, wvh, woh);

    dim3 qkv_grid(E_DIM / 128, M_ROWS / 128, 3);   // (8, 32, 3)
    mma_gemm_qkv<<<qkv_grid, 256, GEMM_SMEM>>>(
        aqh, aql, akh, akl, avh, avl,
        wqh, wkh, wvh, bq, bk, bv, qh, kh, vh);

    dim3 agrid(L_DIM / 128, B_DIM * H_DIM);        // (16, 32)
    flash_attn_mma<<<agrid, 256, FA_SMEM>>>(qh, kh, vh, mask, aqh, aql);

    dim3 ogrid(E_DIM / 128, M_ROWS / 128);
    mma_gemm_o<<<ogrid, 256, GEMM_SMEM>>>(aqh, aql, woh, bo, out);
}

// round 13
// speedup vs baseline: 5.2701x; 1.1345x over previous
#include <cuda_runtime.h>
#include <cuda_fp16.h>
#include <math.h>
#include <math_constants.h>
#include <cstdint>

#define L_DIM 2048
#define S_DIM 2048
#define B_DIM 2
#define E_DIM 1024
#define H_DIM 16
#define HD    64
#define M_ROWS (L_DIM * B_DIM)   // 4096

// ============================ helpers ============================
__device__ __forceinline__ uint32_t smem_to_u32(const void* p) {
    uint32_t a;
    asm("{ .reg .u64 t; cvta.to.shared.u64 t, %1; cvt.u32.u64 %0, t; }" : "=r"(a) : "l"(p));
    return a;
}
__device__ __forceinline__ void cp_async16(uint32_t dst, const void* src) {
    asm volatile("cp.async.cg.shared.global [%0], [%1], 16;" :: "r"(dst), "l"(src));
}
#define CP_COMMIT() asm volatile("cp.async.commit_group;" ::: "memory")
#define CP_WAIT(n)  asm volatile("cp.async.wait_group %0;" :: "n"(n) : "memory")

__device__ __forceinline__ void ldmatrix_x4(uint32_t& r0, uint32_t& r1,
                                            uint32_t& r2, uint32_t& r3, uint32_t addr) {
    asm volatile("ldmatrix.sync.aligned.m8n8.x4.shared.b16 {%0,%1,%2,%3}, [%4];"
                 : "=r"(r0), "=r"(r1), "=r"(r2), "=r"(r3) : "r"(addr));
}
__device__ __forceinline__ void ldmatrix_x4_trans(uint32_t& r0, uint32_t& r1,
                                                  uint32_t& r2, uint32_t& r3, uint32_t addr) {
    asm volatile("ldmatrix.sync.aligned.m8n8.x4.trans.shared.b16 {%0,%1,%2,%3}, [%4];"
                 : "=r"(r0), "=r"(r1), "=r"(r2), "=r"(r3) : "r"(addr));
}
__device__ __forceinline__ void mma_f16(float* d, const uint32_t* a, const uint32_t* b) {
    asm volatile(
        "mma.sync.aligned.m16n8k16.row.col.f32.f16.f16.f32 "
        "{%0,%1,%2,%3}, {%4,%5,%6,%7}, {%8,%9}, {%0,%1,%2,%3};"
        : "+f"(d[0]), "+f"(d[1]), "+f"(d[2]), "+f"(d[3])
        : "r"(a[0]), "r"(a[1]), "r"(a[2]), "r"(a[3]), "r"(b[0]), "r"(b[1]));
}
__device__ __forceinline__ uint32_t packh2(float lo, float hi) {
    __half2 h = __floats2half2_rn(lo, hi);
    return *(uint32_t*)&h;
}
__device__ __forceinline__ uint32_t packresh2(float lo, float hi) {
    float rl = lo - __half2float(__float2half_rn(lo));
    float rh = hi - __half2float(__float2half_rn(hi));
    return packh2(rl, rh);
}

// ============================ scratch ============================
#define ACT_SZ ((size_t)M_ROWS * E_DIM)
#define W_SZ   ((size_t)E_DIM * E_DIM)
__device__ __half g_aq_h[ACT_SZ], g_aq_l[ACT_SZ];
__device__ __half g_ak_h[ACT_SZ], g_ak_l[ACT_SZ];
__device__ __half g_av_h[ACT_SZ], g_av_l[ACT_SZ];
__device__ __half g_wq_h[W_SZ], g_wk_h[W_SZ], g_wv_h[W_SZ], g_wo_h[W_SZ];
#define BHTD ((size_t)B_DIM * H_DIM * L_DIM * HD)
__device__ __half g_Qh[BHTD];
__device__ __half g_Kh[BHTD];
__device__ __half g_Vh[BHTD];

// ==================== fused fp32 -> fp16 hi(/lo) split ====================
__global__ void __launch_bounds__(256)
split_all(const float* __restrict__ q,  const float* __restrict__ k,
          const float* __restrict__ v,  const float* __restrict__ wq,
          const float* __restrict__ wk, const float* __restrict__ wv,
          const float* __restrict__ wo,
          __half* aqh, __half* aql, __half* akh, __half* akl,
          __half* avh, __half* avl,
          __half* wqh, __half* wkh, __half* wvh, __half* woh)
{
    const int j = blockIdx.y;
    const float* src = (j == 0) ? q : (j == 1) ? k : (j == 2) ? v
                     : (j == 3) ? wq : (j == 4) ? wk : (j == 5) ? wv : wo;
    __half* hi = (j == 0) ? aqh : (j == 1) ? akh : (j == 2) ? avh
               : (j == 3) ? wqh : (j == 4) ? wkh : (j == 5) ? wvh : woh;
    __half* lo = (j == 0) ? aql : (j == 1) ? akl : avl;
    const int reps = (j < 3) ? 4 : 1;

    for (int r = 0; r < reps; r++) {
        int i = (r * 1024 + blockIdx.x) * 256 + threadIdx.x;
        float4 vv = ((const float4*)src)[i];
        uint2 uh = {packh2(vv.x, vv.y), packh2(vv.z, vv.w)};
        ((uint2*)hi)[i] = uh;
        if (j < 3) {
            uint2 ul = {packresh2(vv.x, vv.y), packresh2(vv.z, vv.w)};
            ((uint2*)lo)[i] = ul;
        }
    }
}

// ==================== GEMM core (BK=64, fp16 2-pass, double buffer) ==========
#define BK        64
#define ROW_PADB  72                          // fp16 pitch 144 B
#define TILE_B    (128 * ROW_PADB * 2)        // 18432
#define STAGE_B   (3 * TILE_B)                // 55296 (Ah, Al, Wh)
#define GEMM_SMEM (2 * STAGE_B)               // 110592; x2 CTA = 221184
#define NCHUNK    (E_DIM / BK)                // 16

__device__ __forceinline__ void gemm_core(
    const __half* __restrict__ Ah, const __half* __restrict__ Al,
    const __half* __restrict__ Wh,
    uint32_t sb, int m0, int n0, int tid, float acc[2][8][4])
{
    const int wid  = tid >> 5;
    const int lane = tid & 31;
    const int wm = (wid & 3) * 32;
    const int wn = (wid >> 2) * 64;

    const __half* gsrc[3] = {Ah, Al, Wh};

    auto prefetch = [&](int c, int buf) {
        const int k0 = c * BK;
#pragma unroll
        for (int it = 0; it < 12; it++) {
            int idx  = it * 256 + tid;
            int tile = idx >> 10;
            int i    = idx & 1023;
            int row  = i >> 3;
            int ch   = i & 7;
            int grow = (tile < 2 ? m0 : n0) + row;
            const __half* gp = gsrc[tile] + (size_t)grow * E_DIM + k0 + ch * 8;
            uint32_t dst = sb + buf * STAGE_B + tile * TILE_B + row * (ROW_PADB * 2) + ch * 16;
            cp_async16(dst, gp);
        }
        CP_COMMIT();
    };

    prefetch(0, 0);

    const int arow = lane & 15;
    const int akh  = (lane >> 4) * 8;
    const int bg = lane >> 3;
    const int br = lane & 7;

    for (int c = 0; c < NCHUNK; c++) {
        const int buf = c & 1;
        CP_WAIT(0);
        __syncthreads();
        if (c + 1 < NCHUNK) prefetch(c + 1, buf ^ 1);

        const uint32_t st = sb + buf * STAGE_B;
#pragma unroll
        for (int ks = 0; ks < 4; ks++) {
            const int kb = ks * 16;
            uint32_t ah[2][4], al[2][4];
#pragma unroll
            for (int mi = 0; mi < 2; mi++) {
                uint32_t addr = st +
                    (wm + mi * 16 + arow) * (ROW_PADB * 2) + (kb + akh) * 2;
                ldmatrix_x4(ah[mi][0], ah[mi][1], ah[mi][2], ah[mi][3], addr);
                addr += TILE_B;
                ldmatrix_x4(al[mi][0], al[mi][1], al[mi][2], al[mi][3], addr);
            }
            uint32_t bhv[8][2];
#pragma unroll
            for (int nq = 0; nq < 4; nq++) {
                uint32_t addr = st + 2 * TILE_B +
                    (wn + nq * 16 + (bg >> 1) * 8 + br) * (ROW_PADB * 2) + (kb + (bg & 1) * 8) * 2;
                uint32_t r0, r1, r2, r3;
                ldmatrix_x4(r0, r1, r2, r3, addr);
                bhv[2 * nq][0] = r0; bhv[2 * nq][1] = r1;
                bhv[2 * nq + 1][0] = r2; bhv[2 * nq + 1][1] = r3;
            }
#pragma unroll
            for (int mi = 0; mi < 2; mi++)
#pragma unroll
                for (int ni = 0; ni < 8; ni++)
                    mma_f16(acc[mi][ni], ah[mi], bhv[ni]);   // hi pass
#pragma unroll
            for (int mi = 0; mi < 2; mi++)
#pragma unroll
                for (int ni = 0; ni < 8; ni++)
                    mma_f16(acc[mi][ni], al[mi], bhv[ni]);   // lo pass
        }
    }
}

// ---- batched QKV projection: z=0 Q(+rope), z=1 K(+rope), z=2 V; hi-only out ----
__global__ void __launch_bounds__(256, 2)
mma_gemm_qkv(const __half* __restrict__ aqh, const __half* __restrict__ aql,
             const __half* __restrict__ akh, const __half* __restrict__ akl,
             const __half* __restrict__ avh, const __half* __restrict__ avl,
             const __half* __restrict__ wqh, const __half* __restrict__ wkh,
             const __half* __restrict__ wvh,
             const float* __restrict__ bq, const float* __restrict__ bk,
             const float* __restrict__ bv,
             __half* __restrict__ qh, __half* __restrict__ kh, __half* __restrict__ vh)
{
    extern __shared__ char smem[];
    const uint32_t sb = smem_to_u32(smem);
    const int tid = threadIdx.x;
    const int z = blockIdx.z;
    const int m0 = blockIdx.y * 128;
    const int n0 = blockIdx.x * 128;

    const __half* Ah = (z == 0) ? aqh : (z == 1) ? akh : avh;
    const __half* Al = (z == 0) ? aql : (z == 1) ? akl : avl;
    const __half* Wh = (z == 0) ? wqh : (z == 1) ? wkh : wvh;
    const float* bias = (z == 0) ? bq : (z == 1) ? bk : bv;
    __half* outh = (z == 0) ? qh : (z == 1) ? kh : vh;
    const bool rope = (z != 2);

    float acc[2][8][4];
#pragma unroll
    for (int mi = 0; mi < 2; mi++)
#pragma unroll
        for (int ni = 0; ni < 8; ni++)
#pragma unroll
            for (int q = 0; q < 4; q++) acc[mi][ni][q] = 0.0f;

    gemm_core(Ah, Al, Wh, sb, m0, n0, tid, acc);

    const int wid  = tid >> 5;
    const int lane = tid & 31;
    const int wm = (wid & 3) * 32;
    const int wn = (wid >> 2) * 64;
    const int cbase = n0 + wn + (lane & 3) * 2;
#pragma unroll
    for (int ni = 0; ni < 8; ni++) {
        const int c = cbase + ni * 8;
        const float b0 = bias[c], b1 = bias[c + 1];
        float freq = 0.0f;
        if (rope) {
            int d = c & (HD - 1);
            freq = powf(10000.0f, -(float)d / (float)HD);
        }
        const int h    = c >> 6;
        const int dcol = c & (HD - 1);
#pragma unroll
        for (int mi = 0; mi < 2; mi++) {
#pragma unroll
            for (int rg = 0; rg < 2; rg++) {
                int m = m0 + wm + mi * 16 + (lane >> 2) + rg * 8;
                float v0 = acc[mi][ni][2 * rg] + b0;
                float v1 = acc[mi][ni][2 * rg + 1] + b1;
                int l  = m >> 1;
                int bb = m & 1;
                if (rope) {
                    float sv, cv;
                    sincosf((float)l * freq, &sv, &cv);
                    float x1 = v0, x2 = v1;
                    v0 = x1 * cv - x2 * sv;
                    v1 = x1 * sv + x2 * cv;
                }
                size_t idx = (((size_t)bb * H_DIM + h) * L_DIM + l) * HD + dcol;
                *(uint32_t*)(outh + idx) = packh2(v0, v1);
            }
        }
    }
}

// ---- output projection: fp32 out[m*E+n] ----
__global__ void __launch_bounds__(256, 2)
mma_gemm_o(const __half* __restrict__ Ah, const __half* __restrict__ Al,
           const __half* __restrict__ Wh,
           const float* __restrict__ bias, float* __restrict__ outf)
{
    extern __shared__ char smem[];
    const uint32_t sb = smem_to_u32(smem);
    const int tid = threadIdx.x;
    const int m0 = blockIdx.y * 128;
    const int n0 = blockIdx.x * 128;

    float acc[2][8][4];
#pragma unroll
    for (int mi = 0; mi < 2; mi++)
#pragma unroll
        for (int ni = 0; ni < 8; ni++)
#pragma unroll
            for (int q = 0; q < 4; q++) acc[mi][ni][q] = 0.0f;

    gemm_core(Ah, Al, Wh, sb, m0, n0, tid, acc);

    const int wid  = tid >> 5;
    const int lane = tid & 31;
    const int wm = (wid & 3) * 32;
    const int wn = (wid >> 2) * 64;
    const int cbase = n0 + wn + (lane & 3) * 2;
#pragma unroll
    for (int ni = 0; ni < 8; ni++) {
        const int c = cbase + ni * 8;
        const float b0 = bias[c], b1 = bias[c + 1];
#pragma unroll
        for (int mi = 0; mi < 2; mi++) {
#pragma unroll
            for (int rg = 0; rg < 2; rg++) {
                int m = m0 + wm + mi * 16 + (lane >> 2) + rg * 8;
                float2 r = {acc[mi][ni][2 * rg] + b0, acc[mi][ni][2 * rg + 1] + b1};
                *(float2*)(outf + (size_t)m * E_DIM + c) = r;
            }
        }
    }
}

// ==================== flash attention (Qh-only GEMM1, Ph-only GEMM2) ====================
#define FA_ROWB   144
#define FA_QTILE  (128 * FA_ROWB)              // 18432 (Qh only)
#define FA_KVTILE (64 * FA_ROWB)               // 9216
#define FA_STAGE  (2 * FA_KVTILE)              // 18432
#define FA_SMEM   (FA_QTILE + 3 * FA_STAGE)    // 73728
#define FA_NC     (S_DIM / 64)

__global__ void __launch_bounds__(256, 2)
flash_attn_mma(const __half* __restrict__ Qh_g,
               const __half* __restrict__ Kh_g, const __half* __restrict__ Vh_g,
               const unsigned char* __restrict__ mask,
               __half* __restrict__ Oh_g, __half* __restrict__ Ol_g)
{
    extern __shared__ char smem[];
    const uint32_t sb = smem_to_u32(smem);
    const int tid = threadIdx.x, lane = tid & 31, wid = tid >> 5;
    const int bh = blockIdx.y, b = bh >> 4, h = bh & 15;
    const int l0 = blockIdx.x * 128;
    const int wm = wid * 16;

    const size_t goff = (size_t)bh * L_DIM * HD;

    // Q hi tile only
#pragma unroll
    for (int it = 0; it < 4; it++) {
        int idx = it * 256 + tid;
        int row = idx >> 3, ch = idx & 7;
        cp_async16(sb + row * FA_ROWB + ch * 16,
                   Qh_g + goff + (size_t)(l0 + row) * HD + ch * 8);
    }

    const __half* kvsrc[2] = {Kh_g + goff, Vh_g + goff};
    const uint32_t kvbase = sb + FA_QTILE;
    auto prefetch_kv = [&](int c, int buf) {
        int s0 = c * 64;
#pragma unroll
        for (int it = 0; it < 4; it++) {
            int idx = it * 256 + tid;
            int tile = idx >> 9, i = idx & 511, row = i >> 3, ch = i & 7;
            cp_async16(kvbase + buf * FA_STAGE + tile * FA_KVTILE + row * FA_ROWB + ch * 16,
                       kvsrc[tile] + (size_t)(s0 + row) * HD + ch * 8);
        }
        CP_COMMIT();
    };
    prefetch_kv(0, 0);   // commits Q loads too
    prefetch_kv(1, 1);

    float o_acc[8][4];
#pragma unroll
    for (int ni = 0; ni < 8; ni++)
#pragma unroll
        for (int q = 0; q < 4; q++) o_acc[ni][q] = 0.0f;
    float mi0 = -CUDART_INF_F, mi1 = -CUDART_INF_F, li0 = 0.0f, li1 = 0.0f;

    const int arow = lane & 15, akh = (lane >> 4) * 8;
    const int bg = lane >> 3, br = lane & 7;
    const int brow_off = (bg >> 1) * 8 + br;
    const int bk_off   = (bg & 1) * 8;
    const int trow_off = ((lane >> 3) & 1) * 8 + (lane & 7);
    const int tcol_off = (lane >> 4) * 8;
    const float scale2 = 0.125f * 1.4426950408889634f;

    uint32_t qfh[4][4];

    for (int c = 0; c < FA_NC; c++) {
        const int buf = c % 3;

        const int s0c = c * 64;
        uchar2 mk[8];
#pragma unroll
        for (int ni = 0; ni < 8; ni++)
            mk[ni] = *(const uchar2*)(mask + (size_t)b * S_DIM + s0c + ni * 8 + (lane & 3) * 2);

        if (c + 1 < FA_NC) CP_WAIT(1); else CP_WAIT(0);
        __syncthreads();
        if (c + 2 < FA_NC) prefetch_kv(c + 2, (c + 2) % 3);

        if (c == 0) {
#pragma unroll
            for (int ks = 0; ks < 4; ks++) {
                uint32_t qaddr = sb + (wm + arow) * FA_ROWB + (ks * 16 + akh) * 2;
                ldmatrix_x4(qfh[ks][0], qfh[ks][1], qfh[ks][2], qfh[ks][3], qaddr);
            }
        }

        const uint32_t sK = kvbase + buf * FA_STAGE;
        const uint32_t sV = sK + FA_KVTILE;

        float s[8][4];
#pragma unroll
        for (int ni = 0; ni < 8; ni++)
#pragma unroll
            for (int q = 0; q < 4; q++) s[ni][q] = 0.0f;

        // GEMM1: S = Qh * Kh^T (single pass)
#pragma unroll
        for (int ks = 0; ks < 4; ks++) {
            const int kb = ks * 16;
#pragma unroll
            for (int nq = 0; nq < 4; nq++) {
                uint32_t kaddr = sK + (nq * 16 + brow_off) * FA_ROWB + (kb + bk_off) * 2;
                uint32_t k0, k1, k2, k3;
                ldmatrix_x4(k0, k1, k2, k3, kaddr);
                uint32_t kh0[2] = {k0, k1}, kh1[2] = {k2, k3};
                mma_f16(s[2 * nq],     qfh[ks], kh0);
                mma_f16(s[2 * nq + 1], qfh[ks], kh1);
            }
        }

        float mlo = -CUDART_INF_F, mhi = -CUDART_INF_F;
#pragma unroll
        for (int ni = 0; ni < 8; ni++) {
            float v0 = mk[ni].x ? -CUDART_INF_F : s[ni][0] * scale2;
            float v1 = mk[ni].y ? -CUDART_INF_F : s[ni][1] * scale2;
            float v2 = mk[ni].x ? -CUDART_INF_F : s[ni][2] * scale2;
            float v3 = mk[ni].y ? -CUDART_INF_F : s[ni][3] * scale2;
            s[ni][0] = v0; s[ni][1] = v1; s[ni][2] = v2; s[ni][3] = v3;
            mlo = fmaxf(mlo, fmaxf(v0, v1));
            mhi = fmaxf(mhi, fmaxf(v2, v3));
        }
        mlo = fmaxf(mlo, __shfl_xor_sync(0xffffffffu, mlo, 1));
        mlo = fmaxf(mlo, __shfl_xor_sync(0xffffffffu, mlo, 2));
        mhi = fmaxf(mhi, __shfl_xor_sync(0xffffffffu, mhi, 1));
        mhi = fmaxf(mhi, __shfl_xor_sync(0xffffffffu, mhi, 2));

        float mn0 = fmaxf(mi0, mlo), mn1 = fmaxf(mi1, mhi);
        float a0 = exp2f(mi0 - mn0), a1 = exp2f(mi1 - mn1);
        float ps0 = 0.0f, ps1 = 0.0f;
#pragma unroll
        for (int ni = 0; ni < 8; ni++) {
            float p0 = exp2f(s[ni][0] - mn0);
            float p1 = exp2f(s[ni][1] - mn0);
            float p2 = exp2f(s[ni][2] - mn1);
            float p3 = exp2f(s[ni][3] - mn1);
            s[ni][0] = p0; s[ni][1] = p1; s[ni][2] = p2; s[ni][3] = p3;
            ps0 += p0 + p1;
            ps1 += p2 + p3;
        }
        ps0 += __shfl_xor_sync(0xffffffffu, ps0, 1);
        ps0 += __shfl_xor_sync(0xffffffffu, ps0, 2);
        ps1 += __shfl_xor_sync(0xffffffffu, ps1, 1);
        ps1 += __shfl_xor_sync(0xffffffffu, ps1, 2);
        li0 = li0 * a0 + ps0;
        li1 = li1 * a1 + ps1;
        mi0 = mn0; mi1 = mn1;
#pragma unroll
        for (int ni = 0; ni < 8; ni++) {
            o_acc[ni][0] *= a0; o_acc[ni][1] *= a0;
            o_acc[ni][2] *= a1; o_acc[ni][3] *= a1;
        }

        // GEMM2: O += Ph * Vh (single pass; P residual dropped)
#pragma unroll
        for (int ks = 0; ks < 4; ks++) {
            uint32_t pah[4];
            pah[0] = packh2(s[2 * ks][0],     s[2 * ks][1]);
            pah[1] = packh2(s[2 * ks][2],     s[2 * ks][3]);
            pah[2] = packh2(s[2 * ks + 1][0], s[2 * ks + 1][1]);
            pah[3] = packh2(s[2 * ks + 1][2], s[2 * ks + 1][3]);
#pragma unroll
            for (int nb = 0; nb < 4; nb++) {
                uint32_t vaddr = sV + (ks * 16 + trow_off) * FA_ROWB + (nb * 16 + tcol_off) * 2;
                uint32_t v0, v1, v2, v3;
                ldmatrix_x4_trans(v0, v1, v2, v3, vaddr);
                uint32_t vh0[2] = {v0, v1}, vh1[2] = {v2, v3};
                mma_f16(o_acc[2 * nb],     pah, vh0);
                mma_f16(o_acc[2 * nb + 1], pah, vh1);
            }
        }
    }

    const float inv0 = 1.0f / li0, inv1 = 1.0f / li1;
    const int r0 = lane >> 2;
    const int m0g = ((l0 + wm + r0) << 1) | b;
    const int m1g = ((l0 + wm + r0 + 8) << 1) | b;
#pragma unroll
    for (int ni = 0; ni < 8; ni++) {
        int cg = h * HD + ni * 8 + (lane & 3) * 2;
        float v00 = o_acc[ni][0] * inv0, v01 = o_acc[ni][1] * inv0;
        float v10 = o_acc[ni][2] * inv1, v11 = o_acc[ni][3] * inv1;
        *(uint32_t*)(Oh_g + (size_t)m0g * E_DIM + cg) = packh2(v00, v01);
        *(uint32_t*)(Ol_g + (size_t)m0g * E_DIM + cg) = packresh2(v00, v01);
        *(uint32_t*)(Oh_g + (size_t)m1g * E_DIM + cg) = packh2(v10, v11);
        *(uint32_t*)(Ol_g + (size_t)m1g * E_DIM + cg) = packresh2(v10, v11);
    }
}

// ============================================================================
// launch
// ============================================================================
extern "C" void kernel_launch(void* const* d_in, const int* in_sizes, int n_in,
                              void* d_out, int out_size)
{
    const float* query = (const float*)d_in[0];
    const float* key   = (const float*)d_in[1];
    const float* value = (const float*)d_in[2];
    const unsigned char* mask = (const unsigned char*)d_in[3];
    const float* Wq = (const float*)d_in[4];
    const float* bq = (const float*)d_in[5];
    const float* Wk = (const float*)d_in[6];
    const float* bk = (const float*)d_in[7];
    const float* Wv = (const float*)d_in[8];
    const float* bv = (const float*)d_in[9];
    const float* Wo = (const float*)d_in[10];
    const float* bo = (const float*)d_in[11];
    float* out = (float*)d_out;

    __half *aqh, *aql, *akh, *akl, *avh, *avl;
    __half *wqh, *wkh, *wvh, *woh;
    __half *qh, *kh, *vh;
    cudaGetSymbolAddress((void**)&aqh, g_aq_h); cudaGetSymbolAddress((void**)&aql, g_aq_l);
    cudaGetSymbolAddress((void**)&akh, g_ak_h); cudaGetSymbolAddress((void**)&akl, g_ak_l);
    cudaGetSymbolAddress((void**)&avh, g_av_h); cudaGetSymbolAddress((void**)&avl, g_av_l);
    cudaGetSymbolAddress((void**)&wqh, g_wq_h); cudaGetSymbolAddress((void**)&wkh, g_wk_h);
    cudaGetSymbolAddress((void**)&wvh, g_wv_h); cudaGetSymbolAddress((void**)&woh, g_wo_h);
    cudaGetSymbolAddress((void**)&qh, g_Qh);
    cudaGetSymbolAddress((void**)&kh, g_Kh); cudaGetSymbolAddress((void**)&vh, g_Vh);

    cudaFuncSetAttribute(mma_gemm_qkv, cudaFuncAttributeMaxDynamicSharedMemorySize, GEMM_SMEM);
    cudaFuncSetAttribute(mma_gemm_o,   cudaFuncAttributeMaxDynamicSharedMemorySize, GEMM_SMEM);
    cudaFuncSetAttribute(flash_attn_mma, cudaFuncAttributeMaxDynamicSharedMemorySize, FA_SMEM);

    dim3 sgrid(1024, 7);
    split_all<<<sgrid, 256>>>(query, key, value, Wq, Wk, Wv, Wo,
                              aqh, aql, akh, akl, avh, avl,
                              wqh, wkh, wvh, woh);

    dim3 qkv_grid(E_DIM / 128, M_ROWS / 128, 3);   // (8, 32, 3)
    mma_gemm_qkv<<<qkv_grid, 256, GEMM_SMEM>>>(
        aqh, aql, akh, akl, avh, avl,
        wqh, wkh, wvh, bq, bk, bv, qh, kh, vh);

    dim3 agrid(L_DIM / 128, B_DIM * H_DIM);        // (16, 32)
    flash_attn_mma<<<agrid, 256, FA_SMEM>>>(qh, kh, vh, mask, aqh, aql);

    dim3 ogrid(E_DIM / 128, M_ROWS / 128);
    mma_gemm_o<<<ogrid, 256, GEMM_SMEM>>>(aqh, aql, woh, bo, out);
}

// round 14
// speedup vs baseline: 5.4226x; 1.0289x over previous
#include <cuda_runtime.h>
#include <cuda_fp16.h>
#include <math.h>
#include <math_constants.h>
#include <cstdint>

#define L_DIM 2048
#define S_DIM 2048
#define B_DIM 2
#define E_DIM 1024
#define H_DIM 16
#define HD    64
#define M_ROWS (L_DIM * B_DIM)   // 4096

// ============================ helpers ============================
__device__ __forceinline__ uint32_t smem_to_u32(const void* p) {
    uint32_t a;
    asm("{ .reg .u64 t; cvta.to.shared.u64 t, %1; cvt.u32.u64 %0, t; }" : "=r"(a) : "l"(p));
    return a;
}
__device__ __forceinline__ void cp_async16(uint32_t dst, const void* src) {
    asm volatile("cp.async.cg.shared.global [%0], [%1], 16;" :: "r"(dst), "l"(src));
}
#define CP_COMMIT() asm volatile("cp.async.commit_group;" ::: "memory")
#define CP_WAIT(n)  asm volatile("cp.async.wait_group %0;" :: "n"(n) : "memory")

__device__ __forceinline__ void ldmatrix_x4(uint32_t& r0, uint32_t& r1,
                                            uint32_t& r2, uint32_t& r3, uint32_t addr) {
    asm volatile("ldmatrix.sync.aligned.m8n8.x4.shared.b16 {%0,%1,%2,%3}, [%4];"
                 : "=r"(r0), "=r"(r1), "=r"(r2), "=r"(r3) : "r"(addr));
}
__device__ __forceinline__ void ldmatrix_x4_trans(uint32_t& r0, uint32_t& r1,
                                                  uint32_t& r2, uint32_t& r3, uint32_t addr) {
    asm volatile("ldmatrix.sync.aligned.m8n8.x4.trans.shared.b16 {%0,%1,%2,%3}, [%4];"
                 : "=r"(r0), "=r"(r1), "=r"(r2), "=r"(r3) : "r"(addr));
}
__device__ __forceinline__ void mma_f16(float* d, const uint32_t* a, const uint32_t* b) {
    asm volatile(
        "mma.sync.aligned.m16n8k16.row.col.f32.f16.f16.f32 "
        "{%0,%1,%2,%3}, {%4,%5,%6,%7}, {%8,%9}, {%0,%1,%2,%3};"
        : "+f"(d[0]), "+f"(d[1]), "+f"(d[2]), "+f"(d[3])
        : "r"(a[0]), "r"(a[1]), "r"(a[2]), "r"(a[3]), "r"(b[0]), "r"(b[1]));
}
__device__ __forceinline__ uint32_t packh2(float lo, float hi) {
    __half2 h = __floats2half2_rn(lo, hi);
    return *(uint32_t*)&h;
}
__device__ __forceinline__ uint32_t packresh2(float lo, float hi) {
    float rl = lo - __half2float(__float2half_rn(lo));
    float rh = hi - __half2float(__float2half_rn(hi));
    return packh2(rl, rh);
}
// exp2 on a packed half2 (one MUFU op, two values, result MMA-ready)
__device__ __forceinline__ uint32_t h2exp2(uint32_t x) {
    uint32_t r;
    asm("ex2.approx.f16x2 %0, %1;" : "=r"(r) : "r"(x));
    return r;
}

// ============================ scratch ============================
#define ACT_SZ ((size_t)M_ROWS * E_DIM)
#define W_SZ   ((size_t)E_DIM * E_DIM)
__device__ __half g_aq_h[ACT_SZ], g_aq_l[ACT_SZ];
__device__ __half g_ak_h[ACT_SZ], g_ak_l[ACT_SZ];
__device__ __half g_av_h[ACT_SZ], g_av_l[ACT_SZ];
__device__ __half g_wq_h[W_SZ], g_wk_h[W_SZ], g_wv_h[W_SZ], g_wo_h[W_SZ];
#define BHTD ((size_t)B_DIM * H_DIM * L_DIM * HD)
__device__ __half g_Qh[BHTD];
__device__ __half g_Kh[BHTD];
__device__ __half g_Vh[BHTD];

// ==================== fused fp32 -> fp16 hi(/lo) split ====================
__global__ void __launch_bounds__(256)
split_all(const float* __restrict__ q,  const float* __restrict__ k,
          const float* __restrict__ v,  const float* __restrict__ wq,
          const float* __restrict__ wk, const float* __restrict__ wv,
          const float* __restrict__ wo,
          __half* aqh, __half* aql, __half* akh, __half* akl,
          __half* avh, __half* avl,
          __half* wqh, __half* wkh, __half* wvh, __half* woh)
{
    const int j = blockIdx.y;
    const float* src = (j == 0) ? q : (j == 1) ? k : (j == 2) ? v
                     : (j == 3) ? wq : (j == 4) ? wk : (j == 5) ? wv : wo;
    __half* hi = (j == 0) ? aqh : (j == 1) ? akh : (j == 2) ? avh
               : (j == 3) ? wqh : (j == 4) ? wkh : (j == 5) ? wvh : woh;
    __half* lo = (j == 0) ? aql : (j == 1) ? akl : avl;
    const int reps = (j < 3) ? 4 : 1;

    for (int r = 0; r < reps; r++) {
        int i = (r * 1024 + blockIdx.x) * 256 + threadIdx.x;
        float4 vv = ((const float4*)src)[i];
        uint2 uh = {packh2(vv.x, vv.y), packh2(vv.z, vv.w)};
        ((uint2*)hi)[i] = uh;
        if (j < 3) {
            uint2 ul = {packresh2(vv.x, vv.y), packresh2(vv.z, vv.w)};
            ((uint2*)lo)[i] = ul;
        }
    }
}

// ==================== GEMM core (BK=64, fp16 2-pass, double buffer) ==========
#define BK        64
#define ROW_PADB  72
#define TILE_B    (128 * ROW_PADB * 2)        // 18432
#define STAGE_B   (3 * TILE_B)                // 55296 (Ah, Al, Wh)
#define GEMM_SMEM (2 * STAGE_B)               // 110592
#define NCHUNK    (E_DIM / BK)                // 16

__device__ __forceinline__ void gemm_core(
    const __half* __restrict__ Ah, const __half* __restrict__ Al,
    const __half* __restrict__ Wh,
    uint32_t sb, int m0, int n0, int tid, float acc[2][8][4])
{
    const int wid  = tid >> 5;
    const int lane = tid & 31;
    const int wm = (wid & 3) * 32;
    const int wn = (wid >> 2) * 64;

    const __half* gsrc[3] = {Ah, Al, Wh};

    auto prefetch = [&](int c, int buf) {
        const int k0 = c * BK;
#pragma unroll
        for (int it = 0; it < 12; it++) {
            int idx  = it * 256 + tid;
            int tile = idx >> 10;
            int i    = idx & 1023;
            int row  = i >> 3;
            int ch   = i & 7;
            int grow = (tile < 2 ? m0 : n0) + row;
            const __half* gp = gsrc[tile] + (size_t)grow * E_DIM + k0 + ch * 8;
            uint32_t dst = sb + buf * STAGE_B + tile * TILE_B + row * (ROW_PADB * 2) + ch * 16;
            cp_async16(dst, gp);
        }
        CP_COMMIT();
    };

    prefetch(0, 0);

    const int arow = lane & 15;
    const int akh  = (lane >> 4) * 8;
    const int bg = lane >> 3;
    const int br = lane & 7;

    for (int c = 0; c < NCHUNK; c++) {
        const int buf = c & 1;
        CP_WAIT(0);
        __syncthreads();
        if (c + 1 < NCHUNK) prefetch(c + 1, buf ^ 1);

        const uint32_t st = sb + buf * STAGE_B;
#pragma unroll
        for (int ks = 0; ks < 4; ks++) {
            const int kb = ks * 16;
            uint32_t ah[2][4], al[2][4];
#pragma unroll
            for (int mi = 0; mi < 2; mi++) {
                uint32_t addr = st +
                    (wm + mi * 16 + arow) * (ROW_PADB * 2) + (kb + akh) * 2;
                ldmatrix_x4(ah[mi][0], ah[mi][1], ah[mi][2], ah[mi][3], addr);
                addr += TILE_B;
                ldmatrix_x4(al[mi][0], al[mi][1], al[mi][2], al[mi][3], addr);
            }
            uint32_t bhv[8][2];
#pragma unroll
            for (int nq = 0; nq < 4; nq++) {
                uint32_t addr = st + 2 * TILE_B +
                    (wn + nq * 16 + (bg >> 1) * 8 + br) * (ROW_PADB * 2) + (kb + (bg & 1) * 8) * 2;
                uint32_t r0, r1, r2, r3;
                ldmatrix_x4(r0, r1, r2, r3, addr);
                bhv[2 * nq][0] = r0; bhv[2 * nq][1] = r1;
                bhv[2 * nq + 1][0] = r2; bhv[2 * nq + 1][1] = r3;
            }
#pragma unroll
            for (int mi = 0; mi < 2; mi++)
#pragma unroll
                for (int ni = 0; ni < 8; ni++)
                    mma_f16(acc[mi][ni], ah[mi], bhv[ni]);   // hi pass
#pragma unroll
            for (int mi = 0; mi < 2; mi++)
#pragma unroll
                for (int ni = 0; ni < 8; ni++)
                    mma_f16(acc[mi][ni], al[mi], bhv[ni]);   // lo pass
        }
    }
}

// ---- batched QKV projection: z=0 Q(+rope, pre-scaled), z=1 K(+rope), z=2 V ----
#define SCALE2F (0.125f * 1.4426950408889634f)   // (1/sqrt(64)) / ln2, folded into Q

__global__ void __launch_bounds__(256, 2)
mma_gemm_qkv(const __half* __restrict__ aqh, const __half* __restrict__ aql,
             const __half* __restrict__ akh, const __half* __restrict__ akl,
             const __half* __restrict__ avh, const __half* __restrict__ avl,
             const __half* __restrict__ wqh, const __half* __restrict__ wkh,
             const __half* __restrict__ wvh,
             const float* __restrict__ bq, const float* __restrict__ bk,
             const float* __restrict__ bv,
             __half* __restrict__ qh, __half* __restrict__ kh, __half* __restrict__ vh)
{
    extern __shared__ char smem[];
    const uint32_t sb = smem_to_u32(smem);
    const int tid = threadIdx.x;
    const int z = blockIdx.z;
    const int m0 = blockIdx.y * 128;
    const int n0 = blockIdx.x * 128;

    const __half* Ah = (z == 0) ? aqh : (z == 1) ? akh : avh;
    const __half* Al = (z == 0) ? aql : (z == 1) ? akl : avl;
    const __half* Wh = (z == 0) ? wqh : (z == 1) ? wkh : wvh;
    const float* bias = (z == 0) ? bq : (z == 1) ? bk : bv;
    __half* outh = (z == 0) ? qh : (z == 1) ? kh : vh;
    const bool rope = (z != 2);
    const float oscale = (z == 0) ? SCALE2F : 1.0f;

    float acc[2][8][4];
#pragma unroll
    for (int mi = 0; mi < 2; mi++)
#pragma unroll
        for (int ni = 0; ni < 8; ni++)
#pragma unroll
            for (int q = 0; q < 4; q++) acc[mi][ni][q] = 0.0f;

    gemm_core(Ah, Al, Wh, sb, m0, n0, tid, acc);

    const int wid  = tid >> 5;
    const int lane = tid & 31;
    const int wm = (wid & 3) * 32;
    const int wn = (wid >> 2) * 64;
    const int cbase = n0 + wn + (lane & 3) * 2;
#pragma unroll
    for (int ni = 0; ni < 8; ni++) {
        const int c = cbase + ni * 8;
        const float b0 = bias[c], b1 = bias[c + 1];
        float freq = 0.0f;
        if (rope) {
            int d = c & (HD - 1);
            freq = powf(10000.0f, -(float)d / (float)HD);
        }
        const int h    = c >> 6;
        const int dcol = c & (HD - 1);
#pragma unroll
        for (int mi = 0; mi < 2; mi++) {
#pragma unroll
            for (int rg = 0; rg < 2; rg++) {
                int m = m0 + wm + mi * 16 + (lane >> 2) + rg * 8;
                float v0 = acc[mi][ni][2 * rg] + b0;
                float v1 = acc[mi][ni][2 * rg + 1] + b1;
                int l  = m >> 1;
                int bb = m & 1;
                if (rope) {
                    float sv, cv;
                    sincosf((float)l * freq, &sv, &cv);
                    float x1 = v0, x2 = v1;
                    v0 = x1 * cv - x2 * sv;
                    v1 = x1 * sv + x2 * cv;
                }
                v0 *= oscale;
                v1 *= oscale;
                size_t idx = (((size_t)bb * H_DIM + h) * L_DIM + l) * HD + dcol;
                *(uint32_t*)(outh + idx) = packh2(v0, v1);
            }
        }
    }
}

// ---- output projection: fp32 out[m*E+n] ----
__global__ void __launch_bounds__(256, 2)
mma_gemm_o(const __half* __restrict__ Ah, const __half* __restrict__ Al,
           const __half* __restrict__ Wh,
           const float* __restrict__ bias, float* __restrict__ outf)
{
    extern __shared__ char smem[];
    const uint32_t sb = smem_to_u32(smem);
    const int tid = threadIdx.x;
    const int m0 = blockIdx.y * 128;
    const int n0 = blockIdx.x * 128;

    float acc[2][8][4];
#pragma unroll
    for (int mi = 0; mi < 2; mi++)
#pragma unroll
        for (int ni = 0; ni < 8; ni++)
#pragma unroll
            for (int q = 0; q < 4; q++) acc[mi][ni][q] = 0.0f;

    gemm_core(Ah, Al, Wh, sb, m0, n0, tid, acc);

    const int wid  = tid >> 5;
    const int lane = tid & 31;
    const int wm = (wid & 3) * 32;
    const int wn = (wid >> 2) * 64;
    const int cbase = n0 + wn + (lane & 3) * 2;
#pragma unroll
    for (int ni = 0; ni < 8; ni++) {
        const int c = cbase + ni * 8;
        const float b0 = bias[c], b1 = bias[c + 1];
#pragma unroll
        for (int mi = 0; mi < 2; mi++) {
#pragma unroll
            for (int rg = 0; rg < 2; rg++) {
                int m = m0 + wm + mi * 16 + (lane >> 2) + rg * 8;
                float2 r = {acc[mi][ni][2 * rg] + b0, acc[mi][ni][2 * rg + 1] + b1};
                *(float2*)(outf + (size_t)m * E_DIM + c) = r;
            }
        }
    }
}

// ==================== flash attention (f16x2 exp, ones-MMA row sums) ====================
#define FA_ROWB   144
#define FA_QTILE  (128 * FA_ROWB)
#define FA_KVTILE (64 * FA_ROWB)
#define FA_STAGE  (2 * FA_KVTILE)
#define FA_SMEM   (FA_QTILE + 3 * FA_STAGE)    // 73728
#define FA_NC     (S_DIM / 64)

__global__ void __launch_bounds__(256, 2)
flash_attn_mma(const __half* __restrict__ Qh_g,
               const __half* __restrict__ Kh_g, const __half* __restrict__ Vh_g,
               const unsigned char* __restrict__ mask,
               __half* __restrict__ Oh_g, __half* __restrict__ Ol_g)
{
    extern __shared__ char smem[];
    const uint32_t sb = smem_to_u32(smem);
    const int tid = threadIdx.x, lane = tid & 31, wid = tid >> 5;
    const int bh = blockIdx.y, b = bh >> 4, h = bh & 15;
    const int l0 = blockIdx.x * 128;
    const int wm = wid * 16;

    const size_t goff = (size_t)bh * L_DIM * HD;

#pragma unroll
    for (int it = 0; it < 4; it++) {
        int idx = it * 256 + tid;
        int row = idx >> 3, ch = idx & 7;
        cp_async16(sb + row * FA_ROWB + ch * 16,
                   Qh_g + goff + (size_t)(l0 + row) * HD + ch * 8);
    }

    const __half* kvsrc[2] = {Kh_g + goff, Vh_g + goff};
    const uint32_t kvbase = sb + FA_QTILE;
    auto prefetch_kv = [&](int c, int buf) {
        int s0 = c * 64;
#pragma unroll
        for (int it = 0; it < 4; it++) {
            int idx = it * 256 + tid;
            int tile = idx >> 9, i = idx & 511, row = i >> 3, ch = i & 7;
            cp_async16(kvbase + buf * FA_STAGE + tile * FA_KVTILE + row * FA_ROWB + ch * 16,
                       kvsrc[tile] + (size_t)(s0 + row) * HD + ch * 8);
        }
        CP_COMMIT();
    };
    prefetch_kv(0, 0);
    prefetch_kv(1, 1);

    float o_acc[8][4];
#pragma unroll
    for (int ni = 0; ni < 8; ni++)
#pragma unroll
        for (int q = 0; q < 4; q++) o_acc[ni][q] = 0.0f;
    float mi0 = -CUDART_INF_F, mi1 = -CUDART_INF_F, li0 = 0.0f, li1 = 0.0f;

    const int arow = lane & 15, akh = (lane >> 4) * 8;
    const int bg = lane >> 3, br = lane & 7;
    const int brow_off = (bg >> 1) * 8 + br;
    const int bk_off   = (bg & 1) * 8;
    const int trow_off = ((lane >> 3) & 1) * 8 + (lane & 7);
    const int tcol_off = (lane >> 4) * 8;
    const uint32_t ones2 = packh2(1.0f, 1.0f);
    const uint32_t bones[2] = {ones2, ones2};

    uint32_t qfh[4][4];

    for (int c = 0; c < FA_NC; c++) {
        const int buf = c % 3;

        const int s0c = c * 64;
        uchar2 mk[8];
#pragma unroll
        for (int ni = 0; ni < 8; ni++)
            mk[ni] = *(const uchar2*)(mask + (size_t)b * S_DIM + s0c + ni * 8 + (lane & 3) * 2);

        if (c + 1 < FA_NC) CP_WAIT(1); else CP_WAIT(0);
        __syncthreads();
        if (c + 2 < FA_NC) prefetch_kv(c + 2, (c + 2) % 3);

        if (c == 0) {
#pragma unroll
            for (int ks = 0; ks < 4; ks++) {
                uint32_t qaddr = sb + (wm + arow) * FA_ROWB + (ks * 16 + akh) * 2;
                ldmatrix_x4(qfh[ks][0], qfh[ks][1], qfh[ks][2], qfh[ks][3], qaddr);
            }
        }

        const uint32_t sK = kvbase + buf * FA_STAGE;
        const uint32_t sV = sK + FA_KVTILE;

        float s[8][4];
#pragma unroll
        for (int ni = 0; ni < 8; ni++)
#pragma unroll
            for (int q = 0; q < 4; q++) s[ni][q] = 0.0f;

        // GEMM1: S = Qh * Kh^T (Q pre-scaled by 1/(sqrt(hd)*ln2))
#pragma unroll
        for (int ks = 0; ks < 4; ks++) {
            const int kb = ks * 16;
#pragma unroll
            for (int nq = 0; nq < 4; nq++) {
                uint32_t kaddr = sK + (nq * 16 + brow_off) * FA_ROWB + (kb + bk_off) * 2;
                uint32_t k0, k1, k2, k3;
                ldmatrix_x4(k0, k1, k2, k3, kaddr);
                uint32_t kh0[2] = {k0, k1}, kh1[2] = {k2, k3};
                mma_f16(s[2 * nq],     qfh[ks], kh0);
                mma_f16(s[2 * nq + 1], qfh[ks], kh1);
            }
        }

        // mask + running max (scores already exp2-domain)
        float mlo = -CUDART_INF_F, mhi = -CUDART_INF_F;
#pragma unroll
        for (int ni = 0; ni < 8; ni++) {
            float v0 = mk[ni].x ? -CUDART_INF_F : s[ni][0];
            float v1 = mk[ni].y ? -CUDART_INF_F : s[ni][1];
            float v2 = mk[ni].x ? -CUDART_INF_F : s[ni][2];
            float v3 = mk[ni].y ? -CUDART_INF_F : s[ni][3];
            s[ni][0] = v0; s[ni][1] = v1; s[ni][2] = v2; s[ni][3] = v3;
            mlo = fmaxf(mlo, fmaxf(v0, v1));
            mhi = fmaxf(mhi, fmaxf(v2, v3));
        }
        mlo = fmaxf(mlo, __shfl_xor_sync(0xffffffffu, mlo, 1));
        mlo = fmaxf(mlo, __shfl_xor_sync(0xffffffffu, mlo, 2));
        mhi = fmaxf(mhi, __shfl_xor_sync(0xffffffffu, mhi, 1));
        mhi = fmaxf(mhi, __shfl_xor_sync(0xffffffffu, mhi, 2));

        float mn0 = fmaxf(mi0, mlo), mn1 = fmaxf(mi1, mhi);
        float a0 = exp2f(mi0 - mn0), a1 = exp2f(mi1 - mn1);
        mi0 = mn0; mi1 = mn1;
#pragma unroll
        for (int ni = 0; ni < 8; ni++) {
            o_acc[ni][0] *= a0; o_acc[ni][1] *= a0;
            o_acc[ni][2] *= a1; o_acc[ni][3] *= a1;
        }

        // per-ks: build P fragments with f16x2 exp, row-sum via ones MMA, GEMM2
        float sum_acc[4] = {0.0f, 0.0f, 0.0f, 0.0f};
#pragma unroll
        for (int ks = 0; ks < 4; ks++) {
            uint32_t pah[4];
            pah[0] = h2exp2(packh2(s[2 * ks][0] - mn0,     s[2 * ks][1] - mn0));
            pah[1] = h2exp2(packh2(s[2 * ks][2] - mn1,     s[2 * ks][3] - mn1));
            pah[2] = h2exp2(packh2(s[2 * ks + 1][0] - mn0, s[2 * ks + 1][1] - mn0));
            pah[3] = h2exp2(packh2(s[2 * ks + 1][2] - mn1, s[2 * ks + 1][3] - mn1));
            // row sums: P @ ones (result replicated across row quad, fp32 exact)
            mma_f16(sum_acc, pah, bones);
#pragma unroll
            for (int nb = 0; nb < 4; nb++) {
                uint32_t vaddr = sV + (ks * 16 + trow_off) * FA_ROWB + (nb * 16 + tcol_off) * 2;
                uint32_t v0, v1, v2, v3;
                ldmatrix_x4_trans(v0, v1, v2, v3, vaddr);
                uint32_t vh0[2] = {v0, v1}, vh1[2] = {v2, v3};
                mma_f16(o_acc[2 * nb],     pah, vh0);
                mma_f16(o_acc[2 * nb + 1], pah, vh1);
            }
        }
        li0 = li0 * a0 + sum_acc[0];
        li1 = li1 * a1 + sum_acc[2];
    }

    const float inv0 = 1.0f / li0, inv1 = 1.0f / li1;
    const int r0 = lane >> 2;
    const int m0g = ((l0 + wm + r0) << 1) | b;
    const int m1g = ((l0 + wm + r0 + 8) << 1) | b;
#pragma unroll
    for (int ni = 0; ni < 8; ni++) {
        int cg = h * HD + ni * 8 + (lane & 3) * 2;
        float v00 = o_acc[ni][0] * inv0, v01 = o_acc[ni][1] * inv0;
        float v10 = o_acc[ni][2] * inv1, v11 = o_acc[ni][3] * inv1;
        *(uint32_t*)(Oh_g + (size_t)m0g * E_DIM + cg) = packh2(v00, v01);
        *(uint32_t*)(Ol_g + (size_t)m0g * E_DIM + cg) = packresh2(v00, v01);
        *(uint32_t*)(Oh_g + (size_t)m1g * E_DIM + cg) = packh2(v10, v11);
        *(uint32_t*)(Ol_g + (size_t)m1g * E_DIM + cg) = packresh2(v10, v11);
    }
}

// ============================================================================
// launch
// ============================================================================
extern "C" void kernel_launch(void* const* d_in, const int* in_sizes, int n_in,
                              void* d_out, int out_size)
{
    const float* query = (const float*)d_in[0];
    const float* key   = (const float*)d_in[1];
    const float* value = (const float*)d_in[2];
    const unsigned char* mask = (const unsigned char*)d_in[3];
    const float* Wq = (const float*)d_in[4];
    const float* bq = (const float*)d_in[5];
    const float* Wk = (const float*)d_in[6];
    const float* bk = (const float*)d_in[7];
    const float* Wv = (const float*)d_in[8];
    const float* bv = (const float*)d_in[9];
    const float* Wo = (const float*)d_in[10];
    const float* bo = (const float*)d_in[11];
    float* out = (float*)d_out;

    __half *aqh, *aql, *akh, *akl, *avh, *avl;
    __half *wqh, *wkh, *wvh, *woh;
    __half *qh, *kh, *vh;
    cudaGetSymbolAddress((void**)&aqh, g_aq_h); cudaGetSymbolAddress((void**)&aql, g_aq_l);
    cudaGetSymbolAddress((void**)&akh, g_ak_h); cudaGetSymbolAddress((void**)&akl, g_ak_l);
    cudaGetSymbolAddress((void**)&avh, g_av_h); cudaGetSymbolAddress((void**)&avl, g_av_l);
    cudaGetSymbolAddress((void**)&wqh, g_wq_h); cudaGetSymbolAddress((void**)&wkh, g_wk_h);
    cudaGetSymbolAddress((void**)&wvh, g_wv_h); cudaGetSymbolAddress((void**)&woh, g_wo_h);
    cudaGetSymbolAddress((void**)&qh, g_Qh);
    cudaGetSymbolAddress((void**)&kh, g_Kh); cudaGetSymbolAddress((void**)&vh, g_Vh);

    cudaFuncSetAttribute(mma_gemm_qkv, cudaFuncAttributeMaxDynamicSharedMemorySize, GEMM_SMEM);
    cudaFuncSetAttribute(mma_gemm_o,   cudaFuncAttributeMaxDynamicSharedMemorySize, GEMM_SMEM);
    cudaFuncSetAttribute(flash_attn_mma, cudaFuncAttributeMaxDynamicSharedMemorySize, FA_SMEM);

    dim3 sgrid(1024, 7);
    split_all<<<sgrid, 256>>>(query, key, value, Wq, Wk, Wv, Wo,
                              aqh, aql, akh, akl, avh, avl,
                              wqh, wkh, wvh, woh);

    dim3 qkv_grid(E_DIM / 128, M_ROWS / 128, 3);   // (8, 32, 3)
    mma_gemm_qkv<<<qkv_grid, 256, GEMM_SMEM>>>(
        aqh, aql, akh, akl, avh, avl,
        wqh, wkh, wvh, bq, bk, bv, qh, kh, vh);

    dim3 agrid(L_DIM / 128, B_DIM * H_DIM);        // (16, 32)
    flash_attn_mma<<<agrid, 256, FA_SMEM>>>(qh, kh, vh, mask, aqh, aql);

    dim3 ogrid(E_DIM / 128, M_ROWS / 128);
    mma_gemm_o<<<ogrid, 256, GEMM_SMEM>>>(aqh, aql, woh, bo, out);
}

// round 15
// speedup vs baseline: 6.6253x; 1.2218x over previous
#include <cuda_runtime.h>
#include <cuda_fp16.h>
#include <math.h>
#include <math_constants.h>
#include <cstdint>

#define L_DIM 2048
#define S_DIM 2048
#define B_DIM 2
#define E_DIM 1024
#define H_DIM 16
#define HD    64
#define M_ROWS (L_DIM * B_DIM)   // 4096

// ============================ helpers ============================
__device__ __forceinline__ uint32_t smem_to_u32(const void* p) {
    uint32_t a;
    asm("{ .reg .u64 t; cvta.to.shared.u64 t, %1; cvt.u32.u64 %0, t; }" : "=r"(a) : "l"(p));
    return a;
}
__device__ __forceinline__ void cp_async16(uint32_t dst, const void* src) {
    asm volatile("cp.async.cg.shared.global [%0], [%1], 16;" :: "r"(dst), "l"(src));
}
#define CP_COMMIT() asm volatile("cp.async.commit_group;" ::: "memory")
#define CP_WAIT(n)  asm volatile("cp.async.wait_group %0;" :: "n"(n) : "memory")

__device__ __forceinline__ void ldmatrix_x4(uint32_t& r0, uint32_t& r1,
                                            uint32_t& r2, uint32_t& r3, uint32_t addr) {
    asm volatile("ldmatrix.sync.aligned.m8n8.x4.shared.b16 {%0,%1,%2,%3}, [%4];"
                 : "=r"(r0), "=r"(r1), "=r"(r2), "=r"(r3) : "r"(addr));
}
__device__ __forceinline__ void ldmatrix_x4_trans(uint32_t& r0, uint32_t& r1,
                                                  uint32_t& r2, uint32_t& r3, uint32_t addr) {
    asm volatile("ldmatrix.sync.aligned.m8n8.x4.trans.shared.b16 {%0,%1,%2,%3}, [%4];"
                 : "=r"(r0), "=r"(r1), "=r"(r2), "=r"(r3) : "r"(addr));
}
__device__ __forceinline__ void mma_f16(float* d, const uint32_t* a, const uint32_t* b) {
    asm volatile(
        "mma.sync.aligned.m16n8k16.row.col.f32.f16.f16.f32 "
        "{%0,%1,%2,%3}, {%4,%5,%6,%7}, {%8,%9}, {%0,%1,%2,%3};"
        : "+f"(d[0]), "+f"(d[1]), "+f"(d[2]), "+f"(d[3])
        : "r"(a[0]), "r"(a[1]), "r"(a[2]), "r"(a[3]), "r"(b[0]), "r"(b[1]));
}
__device__ __forceinline__ uint32_t packh2(float lo, float hi) {
    __half2 h = __floats2half2_rn(lo, hi);
    return *(uint32_t*)&h;
}
__device__ __forceinline__ uint32_t packresh2(float lo, float hi) {
    float rl = lo - __half2float(__float2half_rn(lo));
    float rh = hi - __half2float(__float2half_rn(hi));
    return packh2(rl, rh);
}
__device__ __forceinline__ uint32_t h2exp2(uint32_t x) {
    uint32_t r;
    asm("ex2.approx.f16x2 %0, %1;" : "=r"(r) : "r"(x));
    return r;
}

// ============================ scratch ============================
#define ACT_SZ ((size_t)M_ROWS * E_DIM)
#define W_SZ   ((size_t)E_DIM * E_DIM)
__device__ __half g_aq_h[ACT_SZ], g_aq_l[ACT_SZ];   // also reused: flash O hi/lo
__device__ __half g_ak_h[ACT_SZ];
__device__ __half g_av_h[ACT_SZ];
__device__ __half g_wq_h[W_SZ], g_wk_h[W_SZ], g_wv_h[W_SZ], g_wo_h[W_SZ];
#define BHTD ((size_t)B_DIM * H_DIM * L_DIM * HD)
__device__ __half g_Qh[BHTD];
__device__ __half g_Kh[BHTD];
__device__ __half g_Vh[BHTD];

// ==================== fused fp32 -> fp16 split (hi only) ====================
__global__ void __launch_bounds__(256)
split_all(const float* __restrict__ q,  const float* __restrict__ k,
          const float* __restrict__ v,  const float* __restrict__ wq,
          const float* __restrict__ wk, const float* __restrict__ wv,
          const float* __restrict__ wo,
          __half* aqh, __half* akh, __half* avh,
          __half* wqh, __half* wkh, __half* wvh, __half* woh)
{
    const int j = blockIdx.y;
    const float* src = (j == 0) ? q : (j == 1) ? k : (j == 2) ? v
                     : (j == 3) ? wq : (j == 4) ? wk : (j == 5) ? wv : wo;
    __half* hi = (j == 0) ? aqh : (j == 1) ? akh : (j == 2) ? avh
               : (j == 3) ? wqh : (j == 4) ? wkh : (j == 5) ? wvh : woh;
    const int reps = (j < 3) ? 4 : 1;

    for (int r = 0; r < reps; r++) {
        int i = (r * 1024 + blockIdx.x) * 256 + threadIdx.x;
        float4 vv = ((const float4*)src)[i];
        uint2 uh = {packh2(vv.x, vv.y), packh2(vv.z, vv.w)};
        ((uint2*)hi)[i] = uh;
    }
}

// ==================== GEMM core (BK=64, templated pass count) ==========
// NT = tiles per stage: 2 -> single pass (Ah, Wh); 3 -> two pass (Ah, Al, Wh)
#define BK        64
#define ROW_PADB  72
#define TILE_B    (128 * ROW_PADB * 2)        // 18432
#define NCHUNK    (E_DIM / BK)                // 16
#define GEMM_SMEM1 (2 * 2 * TILE_B)           // 73728  (qkv, single pass)
#define GEMM_SMEM2 (2 * 3 * TILE_B)           // 110592 (o, two pass)

template<int NT>
__device__ __forceinline__ void gemm_core(
    const __half* __restrict__ Ah, const __half* __restrict__ Al,
    const __half* __restrict__ Wh,
    uint32_t sb, int m0, int n0, int tid, float acc[2][8][4])
{
    const int STAGE = NT * TILE_B;
    const int wid  = tid >> 5;
    const int lane = tid & 31;
    const int wm = (wid & 3) * 32;
    const int wn = (wid >> 2) * 64;

    auto prefetch = [&](int c, int buf) {
        const int k0 = c * BK;
#pragma unroll
        for (int it = 0; it < NT * 4; it++) {
            int idx  = it * 256 + tid;
            int tile = idx >> 10;             // 0..NT-1
            int i    = idx & 1023;
            int row  = i >> 3;
            int ch   = i & 7;
            const __half* base =
                (tile == 0) ? Ah : (NT == 3 && tile == 1) ? Al : Wh;
            int grow = (tile < NT - 1 ? m0 : n0) + row;
            const __half* gp = base + (size_t)grow * E_DIM + k0 + ch * 8;
            uint32_t dst = sb + buf * STAGE + tile * TILE_B + row * (ROW_PADB * 2) + ch * 16;
            cp_async16(dst, gp);
        }
        CP_COMMIT();
    };

    prefetch(0, 0);

    const int arow = lane & 15;
    const int akh  = (lane >> 4) * 8;
    const int bg = lane >> 3;
    const int br = lane & 7;

    for (int c = 0; c < NCHUNK; c++) {
        const int buf = c & 1;
        CP_WAIT(0);
        __syncthreads();
        if (c + 1 < NCHUNK) prefetch(c + 1, buf ^ 1);

        const uint32_t st = sb + buf * STAGE;
        const uint32_t stB = st + (NT - 1) * TILE_B;
#pragma unroll
        for (int ks = 0; ks < 4; ks++) {
            const int kb = ks * 16;
            uint32_t ah[2][4], al[2][4];
#pragma unroll
            for (int mi = 0; mi < 2; mi++) {
                uint32_t addr = st +
                    (wm + mi * 16 + arow) * (ROW_PADB * 2) + (kb + akh) * 2;
                ldmatrix_x4(ah[mi][0], ah[mi][1], ah[mi][2], ah[mi][3], addr);
                if (NT == 3) {
                    addr += TILE_B;
                    ldmatrix_x4(al[mi][0], al[mi][1], al[mi][2], al[mi][3], addr);
                }
            }
            uint32_t bhv[8][2];
#pragma unroll
            for (int nq = 0; nq < 4; nq++) {
                uint32_t addr = stB +
                    (wn + nq * 16 + (bg >> 1) * 8 + br) * (ROW_PADB * 2) + (kb + (bg & 1) * 8) * 2;
                uint32_t r0, r1, r2, r3;
                ldmatrix_x4(r0, r1, r2, r3, addr);
                bhv[2 * nq][0] = r0; bhv[2 * nq][1] = r1;
                bhv[2 * nq + 1][0] = r2; bhv[2 * nq + 1][1] = r3;
            }
#pragma unroll
            for (int mi = 0; mi < 2; mi++)
#pragma unroll
                for (int ni = 0; ni < 8; ni++)
                    mma_f16(acc[mi][ni], ah[mi], bhv[ni]);   // hi pass
            if (NT == 3) {
#pragma unroll
                for (int mi = 0; mi < 2; mi++)
#pragma unroll
                    for (int ni = 0; ni < 8; ni++)
                        mma_f16(acc[mi][ni], al[mi], bhv[ni]);   // lo pass
            }
        }
    }
}

// ---- batched QKV projection (single-pass): z=0 Q(+rope, pre-scaled), z=1 K(+rope), z=2 V ----
#define SCALE2F (0.125f * 1.4426950408889634f)

__global__ void __launch_bounds__(256, 2)
mma_gemm_qkv(const __half* __restrict__ aqh, const __half* __restrict__ akh,
             const __half* __restrict__ avh,
             const __half* __restrict__ wqh, const __half* __restrict__ wkh,
             const __half* __restrict__ wvh,
             const float* __restrict__ bq, const float* __restrict__ bk,
             const float* __restrict__ bv,
             __half* __restrict__ qh, __half* __restrict__ kh, __half* __restrict__ vh)
{
    extern __shared__ char smem[];
    const uint32_t sb = smem_to_u32(smem);
    const int tid = threadIdx.x;
    const int z = blockIdx.z;
    const int m0 = blockIdx.y * 128;
    const int n0 = blockIdx.x * 128;

    const __half* Ah = (z == 0) ? aqh : (z == 1) ? akh : avh;
    const __half* Wh = (z == 0) ? wqh : (z == 1) ? wkh : wvh;
    const float* bias = (z == 0) ? bq : (z == 1) ? bk : bv;
    __half* outh = (z == 0) ? qh : (z == 1) ? kh : vh;
    const bool rope = (z != 2);
    const float oscale = (z == 0) ? SCALE2F : 1.0f;

    float acc[2][8][4];
#pragma unroll
    for (int mi = 0; mi < 2; mi++)
#pragma unroll
        for (int ni = 0; ni < 8; ni++)
#pragma unroll
            for (int q = 0; q < 4; q++) acc[mi][ni][q] = 0.0f;

    gemm_core<2>(Ah, nullptr, Wh, sb, m0, n0, tid, acc);

    const int wid  = tid >> 5;
    const int lane = tid & 31;
    const int wm = (wid & 3) * 32;
    const int wn = (wid >> 2) * 64;
    const int cbase = n0 + wn + (lane & 3) * 2;
#pragma unroll
    for (int ni = 0; ni < 8; ni++) {
        const int c = cbase + ni * 8;
        const float b0 = bias[c], b1 = bias[c + 1];
        float freq = 0.0f;
        if (rope) {
            int d = c & (HD - 1);
            freq = powf(10000.0f, -(float)d / (float)HD);
        }
        const int h    = c >> 6;
        const int dcol = c & (HD - 1);
#pragma unroll
        for (int mi = 0; mi < 2; mi++) {
#pragma unroll
            for (int rg = 0; rg < 2; rg++) {
                int m = m0 + wm + mi * 16 + (lane >> 2) + rg * 8;
                float v0 = acc[mi][ni][2 * rg] + b0;
                float v1 = acc[mi][ni][2 * rg + 1] + b1;
                int l  = m >> 1;
                int bb = m & 1;
                if (rope) {
                    float sv, cv;
                    sincosf((float)l * freq, &sv, &cv);
                    float x1 = v0, x2 = v1;
                    v0 = x1 * cv - x2 * sv;
                    v1 = x1 * sv + x2 * cv;
                }
                v0 *= oscale;
                v1 *= oscale;
                size_t idx = (((size_t)bb * H_DIM + h) * L_DIM + l) * HD + dcol;
                *(uint32_t*)(outh + idx) = packh2(v0, v1);
            }
        }
    }
}

// ---- output projection (two-pass A hi/lo): fp32 out[m*E+n] ----
__global__ void __launch_bounds__(256, 2)
mma_gemm_o(const __half* __restrict__ Ah, const __half* __restrict__ Al,
           const __half* __restrict__ Wh,
           const float* __restrict__ bias, float* __restrict__ outf)
{
    extern __shared__ char smem[];
    const uint32_t sb = smem_to_u32(smem);
    const int tid = threadIdx.x;
    const int m0 = blockIdx.y * 128;
    const int n0 = blockIdx.x * 128;

    float acc[2][8][4];
#pragma unroll
    for (int mi = 0; mi < 2; mi++)
#pragma unroll
        for (int ni = 0; ni < 8; ni++)
#pragma unroll
            for (int q = 0; q < 4; q++) acc[mi][ni][q] = 0.0f;

    gemm_core<3>(Ah, Al, Wh, sb, m0, n0, tid, acc);

    const int wid  = tid >> 5;
    const int lane = tid & 31;
    const int wm = (wid & 3) * 32;
    const int wn = (wid >> 2) * 64;
    const int cbase = n0 + wn + (lane & 3) * 2;
#pragma unroll
    for (int ni = 0; ni < 8; ni++) {
        const int c = cbase + ni * 8;
        const float b0 = bias[c], b1 = bias[c + 1];
#pragma unroll
        for (int mi = 0; mi < 2; mi++) {
#pragma unroll
            for (int rg = 0; rg < 2; rg++) {
                int m = m0 + wm + mi * 16 + (lane >> 2) + rg * 8;
                float2 r = {acc[mi][ni][2 * rg] + b0, acc[mi][ni][2 * rg + 1] + b1};
                *(float2*)(outf + (size_t)m * E_DIM + c) = r;
            }
        }
    }
}

// ==================== flash attention (f16x2 exp, ones-MMA row sums) ====================
#define FA_ROWB   144
#define FA_QTILE  (128 * FA_ROWB)
#define FA_KVTILE (64 * FA_ROWB)
#define FA_STAGE  (2 * FA_KVTILE)
#define FA_SMEM   (FA_QTILE + 3 * FA_STAGE)    // 73728
#define FA_NC     (S_DIM / 64)

__global__ void __launch_bounds__(256, 2)
flash_attn_mma(const __half* __restrict__ Qh_g,
               const __half* __restrict__ Kh_g, const __half* __restrict__ Vh_g,
               const unsigned char* __restrict__ mask,
               __half* __restrict__ Oh_g, __half* __restrict__ Ol_g)
{
    extern __shared__ char smem[];
    const uint32_t sb = smem_to_u32(smem);
    const int tid = threadIdx.x, lane = tid & 31, wid = tid >> 5;
    const int bh = blockIdx.y, b = bh >> 4, h = bh & 15;
    const int l0 = blockIdx.x * 128;
    const int wm = wid * 16;

    const size_t goff = (size_t)bh * L_DIM * HD;

#pragma unroll
    for (int it = 0; it < 4; it++) {
        int idx = it * 256 + tid;
        int row = idx >> 3, ch = idx & 7;
        cp_async16(sb + row * FA_ROWB + ch * 16,
                   Qh_g + goff + (size_t)(l0 + row) * HD + ch * 8);
    }

    const __half* kvsrc[2] = {Kh_g + goff, Vh_g + goff};
    const uint32_t kvbase = sb + FA_QTILE;
    auto prefetch_kv = [&](int c, int buf) {
        int s0 = c * 64;
#pragma unroll
        for (int it = 0; it < 4; it++) {
            int idx = it * 256 + tid;
            int tile = idx >> 9, i = idx & 511, row = i >> 3, ch = i & 7;
            cp_async16(kvbase + buf * FA_STAGE + tile * FA_KVTILE + row * FA_ROWB + ch * 16,
                       kvsrc[tile] + (size_t)(s0 + row) * HD + ch * 8);
        }
        CP_COMMIT();
    };
    prefetch_kv(0, 0);
    prefetch_kv(1, 1);

    float o_acc[8][4];
#pragma unroll
    for (int ni = 0; ni < 8; ni++)
#pragma unroll
        for (int q = 0; q < 4; q++) o_acc[ni][q] = 0.0f;
    float mi0 = -CUDART_INF_F, mi1 = -CUDART_INF_F, li0 = 0.0f, li1 = 0.0f;

    const int arow = lane & 15, akh = (lane >> 4) * 8;
    const int bg = lane >> 3, br = lane & 7;
    const int brow_off = (bg >> 1) * 8 + br;
    const int bk_off   = (bg & 1) * 8;
    const int trow_off = ((lane >> 3) & 1) * 8 + (lane & 7);
    const int tcol_off = (lane >> 4) * 8;
    const uint32_t ones2 = packh2(1.0f, 1.0f);
    const uint32_t bones[2] = {ones2, ones2};

    uint32_t qfh[4][4];

    for (int c = 0; c < FA_NC; c++) {
        const int buf = c % 3;

        const int s0c = c * 64;
        uchar2 mk[8];
#pragma unroll
        for (int ni = 0; ni < 8; ni++)
            mk[ni] = *(const uchar2*)(mask + (size_t)b * S_DIM + s0c + ni * 8 + (lane & 3) * 2);

        if (c + 1 < FA_NC) CP_WAIT(1); else CP_WAIT(0);
        __syncthreads();
        if (c + 2 < FA_NC) prefetch_kv(c + 2, (c + 2) % 3);

        if (c == 0) {
#pragma unroll
            for (int ks = 0; ks < 4; ks++) {
                uint32_t qaddr = sb + (wm + arow) * FA_ROWB + (ks * 16 + akh) * 2;
                ldmatrix_x4(qfh[ks][0], qfh[ks][1], qfh[ks][2], qfh[ks][3], qaddr);
            }
        }

        const uint32_t sK = kvbase + buf * FA_STAGE;
        const uint32_t sV = sK + FA_KVTILE;

        float s[8][4];
#pragma unroll
        for (int ni = 0; ni < 8; ni++)
#pragma unroll
            for (int q = 0; q < 4; q++) s[ni][q] = 0.0f;

#pragma unroll
        for (int ks = 0; ks < 4; ks++) {
            const int kb = ks * 16;
#pragma unroll
            for (int nq = 0; nq < 4; nq++) {
                uint32_t kaddr = sK + (nq * 16 + brow_off) * FA_ROWB + (kb + bk_off) * 2;
                uint32_t k0, k1, k2, k3;
                ldmatrix_x4(k0, k1, k2, k3, kaddr);
                uint32_t kh0[2] = {k0, k1}, kh1[2] = {k2, k3};
                mma_f16(s[2 * nq],     qfh[ks], kh0);
                mma_f16(s[2 * nq + 1], qfh[ks], kh1);
            }
        }

        float mlo = -CUDART_INF_F, mhi = -CUDART_INF_F;
#pragma unroll
        for (int ni = 0; ni < 8; ni++) {
            float v0 = mk[ni].x ? -CUDART_INF_F : s[ni][0];
            float v1 = mk[ni].y ? -CUDART_INF_F : s[ni][1];
            float v2 = mk[ni].x ? -CUDART_INF_F : s[ni][2];
            float v3 = mk[ni].y ? -CUDART_INF_F : s[ni][3];
            s[ni][0] = v0; s[ni][1] = v1; s[ni][2] = v2; s[ni][3] = v3;
            mlo = fmaxf(mlo, fmaxf(v0, v1));
            mhi = fmaxf(mhi, fmaxf(v2, v3));
        }
        mlo = fmaxf(mlo, __shfl_xor_sync(0xffffffffu, mlo, 1));
        mlo = fmaxf(mlo, __shfl_xor_sync(0xffffffffu, mlo, 2));
        mhi = fmaxf(mhi, __shfl_xor_sync(0xffffffffu, mhi, 1));
        mhi = fmaxf(mhi, __shfl_xor_sync(0xffffffffu, mhi, 2));

        float mn0 = fmaxf(mi0, mlo), mn1 = fmaxf(mi1, mhi);
        float a0 = exp2f(mi0 - mn0), a1 = exp2f(mi1 - mn1);
        mi0 = mn0; mi1 = mn1;
#pragma unroll
        for (int ni = 0; ni < 8; ni++) {
            o_acc[ni][0] *= a0; o_acc[ni][1] *= a0;
            o_acc[ni][2] *= a1; o_acc[ni][3] *= a1;
        }

        float sum_acc[4] = {0.0f, 0.0f, 0.0f, 0.0f};
#pragma unroll
        for (int ks = 0; ks < 4; ks++) {
            uint32_t pah[4];
            pah[0] = h2exp2(packh2(s[2 * ks][0] - mn0,     s[2 * ks][1] - mn0));
            pah[1] = h2exp2(packh2(s[2 * ks][2] - mn1,     s[2 * ks][3] - mn1));
            pah[2] = h2exp2(packh2(s[2 * ks + 1][0] - mn0, s[2 * ks + 1][1] - mn0));
            pah[3] = h2exp2(packh2(s[2 * ks + 1][2] - mn1, s[2 * ks + 1][3] - mn1));
            mma_f16(sum_acc, pah, bones);
#pragma unroll
            for (int nb = 0; nb < 4; nb++) {
                uint32_t vaddr = sV + (ks * 16 + trow_off) * FA_ROWB + (nb * 16 + tcol_off) * 2;
                uint32_t v0, v1, v2, v3;
                ldmatrix_x4_trans(v0, v1, v2, v3, vaddr);
                uint32_t vh0[2] = {v0, v1}, vh1[2] = {v2, v3};
                mma_f16(o_acc[2 * nb],     pah, vh0);
                mma_f16(o_acc[2 * nb + 1], pah, vh1);
            }
        }
        li0 = li0 * a0 + sum_acc[0];
        li1 = li1 * a1 + sum_acc[2];
    }

    const float inv0 = 1.0f / li0, inv1 = 1.0f / li1;
    const int r0 = lane >> 2;
    const int m0g = ((l0 + wm + r0) << 1) | b;
    const int m1g = ((l0 + wm + r0 + 8) << 1) | b;
#pragma unroll
    for (int ni = 0; ni < 8; ni++) {
        int cg = h * HD + ni * 8 + (lane & 3) * 2;
        float v00 = o_acc[ni][0] * inv0, v01 = o_acc[ni][1] * inv0;
        float v10 = o_acc[ni][2] * inv1, v11 = o_acc[ni][3] * inv1;
        *(uint32_t*)(Oh_g + (size_t)m0g * E_DIM + cg) = packh2(v00, v01);
        *(uint32_t*)(Ol_g + (size_t)m0g * E_DIM + cg) = packresh2(v00, v01);
        *(uint32_t*)(Oh_g + (size_t)m1g * E_DIM + cg) = packh2(v10, v11);
        *(uint32_t*)(Ol_g + (size_t)m1g * E_DIM + cg) = packresh2(v10, v11);
    }
}

// ============================================================================
// launch
// ============================================================================
extern "C" void kernel_launch(void* const* d_in, const int* in_sizes, int n_in,
                              void* d_out, int out_size)
{
    const float* query = (const float*)d_in[0];
    const float* key   = (const float*)d_in[1];
    const float* value = (const float*)d_in[2];
    const unsigned char* mask = (const unsigned char*)d_in[3];
    const float* Wq = (const float*)d_in[4];
    const float* bq = (const float*)d_in[5];
    const float* Wk = (const float*)d_in[6];
    const float* bk = (const float*)d_in[7];
    const float* Wv = (const float*)d_in[8];
    const float* bv = (const float*)d_in[9];
    const float* Wo = (const float*)d_in[10];
    const float* bo = (const float*)d_in[11];
    float* out = (float*)d_out;

    __half *aqh, *aql, *akh, *avh;
    __half *wqh, *wkh, *wvh, *woh;
    __half *qh, *kh, *vh;
    cudaGetSymbolAddress((void**)&aqh, g_aq_h); cudaGetSymbolAddress((void**)&aql, g_aq_l);
    cudaGetSymbolAddress((void**)&akh, g_ak_h);
    cudaGetSymbolAddress((void**)&avh, g_av_h);
    cudaGetSymbolAddress((void**)&wqh, g_wq_h); cudaGetSymbolAddress((void**)&wkh, g_wk_h);
    cudaGetSymbolAddress((void**)&wvh, g_wv_h); cudaGetSymbolAddress((void**)&woh, g_wo_h);
    cudaGetSymbolAddress((void**)&qh, g_Qh);
    cudaGetSymbolAddress((void**)&kh, g_Kh); cudaGetSymbolAddress((void**)&vh, g_Vh);

    cudaFuncSetAttribute(mma_gemm_qkv, cudaFuncAttributeMaxDynamicSharedMemorySize, GEMM_SMEM1);
    cudaFuncSetAttribute(mma_gemm_o,   cudaFuncAttributeMaxDynamicSharedMemorySize, GEMM_SMEM2);
    cudaFuncSetAttribute(flash_attn_mma, cudaFuncAttributeMaxDynamicSharedMemorySize, FA_SMEM);

    // hi-only splits (3 activations + 4 weights)
    dim3 sgrid(1024, 7);
    split_all<<<sgrid, 256>>>(query, key, value, Wq, Wk, Wv, Wo,
                              aqh, akh, avh, wqh, wkh, wvh, woh);

    // batched QKV projections, single-pass (+RoPE on Q,K; Q pre-scaled)
    dim3 qkv_grid(E_DIM / 128, M_ROWS / 128, 3);   // (8, 32, 3)
    mma_gemm_qkv<<<qkv_grid, 256, GEMM_SMEM1>>>(
        aqh, akh, avh, wqh, wkh, wvh, bq, bk, bv, qh, kh, vh);

    // attention -> O hi/lo into g_aq_h / g_aq_l
    dim3 agrid(L_DIM / 128, B_DIM * H_DIM);        // (16, 32)
    flash_attn_mma<<<agrid, 256, FA_SMEM>>>(qh, kh, vh, mask, aqh, aql);

    // output projection (two-pass) -> d_out fp32
    dim3 ogrid(E_DIM / 128, M_ROWS / 128);
    mma_gemm_o<<<ogrid, 256, GEMM_SMEM2>>>(aqh, aql, woh, bo, out);
}